// round 13
// baseline (speedup 1.0000x reference)
#include <cuda_runtime.h>
#include <float.h>
#include <stdint.h>

#define BH 16
#define HH 8
#define NN 4096
#define DD 64
#define MM 256

// ---------------- scratch (__device__ globals; no allocation) ----------------
__device__ float g_nc [BH*MM*DD];
__device__ float g_nr [BH*MM*DD];
__device__ int   g_idxk[BH*MM];
__device__ int   g_idxq[BH*MM];
__device__ float g_u  [BH*MM*MM];
__device__ float g_v0 [BH*MM*MM];
__device__ float g_v1 [BH*MM*MM];
__device__ float g_kv [BH*MM*MM];
__device__ float g_t1 [BH*MM*MM];
__device__ float g_t2 [BH*MM*MM];
__device__ float g_rvp[8*BH*MM*DD];          // flash split partials
__device__ float g_ml [8*BH*MM*2];           // flash split (max, sumexp)
__device__ float g_rv [BH*MM*DD];
__device__ float g_y  [BH*MM*DD];

// ---------------- tf32 mma helpers ----------------
__device__ __forceinline__ uint32_t f2tf(float v) {
    uint32_t r; asm("cvt.rna.tf32.f32 %0, %1;" : "=r"(r) : "f"(v)); return r;
}
__device__ __forceinline__ void mma_tf32(float4& d, const uint32_t* a, const uint32_t* b) {
    asm volatile("mma.sync.aligned.m16n8k8.row.col.f32.tf32.tf32.f32 "
        "{%0,%1,%2,%3}, {%4,%5,%6,%7}, {%8,%9}, {%0,%1,%2,%3};"
        : "+f"(d.x), "+f"(d.y), "+f"(d.z), "+f"(d.w)
        : "r"(a[0]), "r"(a[1]), "r"(a[2]), "r"(a[3]), "r"(b[0]), "r"(b[1]));
}
__device__ __forceinline__ uint2 split_tf32(float x) {
    uint32_t hi = f2tf(x);
    float lo = x - __uint_as_float(hi);
    return make_uint2(hi, f2tf(lo));
}
// 3xTF32: d += a_hi*b_hi + a_lo*b_hi + a_hi*b_lo (fp32-grade)
__device__ __forceinline__ void mma_tf32x3(float4& d, const uint2* a, const uint2* b) {
    uint32_t ah[4] = {a[0].x, a[1].x, a[2].x, a[3].x};
    uint32_t al[4] = {a[0].y, a[1].y, a[2].y, a[3].y};
    uint32_t bh_[2] = {b[0].x, b[1].x};
    uint32_t bl_[2] = {b[0].y, b[1].y};
    mma_tf32(d, ah, bh_);
    mma_tf32(d, al, bh_);
    mma_tf32(d, ah, bl_);
}

// ---------------- top-k: exact bitonic sort of (sum,row) keys ----------------
__global__ void __launch_bounds__(1024) topk_kernel(
    const float* __restrict__ Q, const float* __restrict__ K,
    int* __restrict__ idxk, int* __restrict__ idxq)
{
    __shared__ unsigned long long keys[NN];
    int bh  = blockIdx.x >> 1;
    int isQ = blockIdx.x & 1;
    const float* src = isQ ? Q : K;
    int tid = threadIdx.x;

    for (int r = tid; r < NN; r += 1024) {
        const float4* p = reinterpret_cast<const float4*>(src + ((size_t)bh*NN + r)*DD);
        float s = 0.f;
#pragma unroll
        for (int t = 0; t < DD/4; t++) { float4 v = p[t]; s += v.x + v.y + v.z + v.w; }
        unsigned int u = __float_as_uint(s);
        unsigned int m = (u & 0x80000000u) ? ~u : (u | 0x80000000u);
        keys[r] = ((unsigned long long)(~m) << 32) | (unsigned int)r;
    }
    __syncthreads();

    for (int k = 2; k <= NN; k <<= 1) {
        for (int j = k >> 1; j > 0; j >>= 1) {
            for (int i = tid; i < NN; i += 1024) {
                int ixj = i ^ j;
                if (ixj > i) {
                    bool up = ((i & k) == 0);
                    unsigned long long a = keys[i], c = keys[ixj];
                    if ((a > c) == up) { keys[i] = c; keys[ixj] = a; }
                }
            }
            __syncthreads();
        }
    }
    int* dst = isQ ? idxq : idxk;
    if (tid < MM) dst[bh*MM + tid] = (int)(keys[tid] & 0xFFFFFFFFu);
}

// ---------------- gather nc = K[idx_k], nr = Q[idx_q]/8 ----------------
__global__ void gather_kernel(const float* __restrict__ Q, const float* __restrict__ K,
                              const int* __restrict__ idxk, const int* __restrict__ idxq,
                              float* __restrict__ nc, float* __restrict__ nr)
{
    int bh = blockIdx.x;
    int tx = threadIdx.x;
    int ty = threadIdx.y;
    for (int i = ty; i < MM; i += 4) {
        int ik = idxk[bh*MM + i];
        int iq = idxq[bh*MM + i];
        nc[((size_t)bh*MM + i)*DD + tx] = K[((size_t)bh*NN + ik)*DD + tx];
        nr[((size_t)bh*MM + i)*DD + tx] = Q[((size_t)bh*NN + iq)*DD + tx] * 0.125f;
    }
}

// ---------------- NT GEMM (K=64): 128x128 tile, 8x8 micro (fp32) -------------
__global__ void __launch_bounds__(256) gemm_nt128_kernel(
    const float* __restrict__ A, const float* __restrict__ B, float* __restrict__ C,
    int Ma, int Nb)
{
    extern __shared__ float sm[];
    float (*As)[132] = reinterpret_cast<float(*)[132]>(sm);
    float (*Bs)[132] = reinterpret_cast<float(*)[132]>(sm + 64*132);
    int bh = blockIdx.z;
    int m0 = blockIdx.y * 128;
    int n0 = blockIdx.x * 128;
    const float* Ab = A + (size_t)bh*Ma*64;
    const float* Bb = B + (size_t)bh*Nb*64;
    float*       Cb = C + (size_t)bh*Ma*Nb;
    int tid = threadIdx.x;
#pragma unroll
    for (int i = 0; i < 8; i++) {
        int idx = tid + i*256;
        int row = idx & 127;
        int c4  = (idx >> 7) * 4;
        float4 v = *reinterpret_cast<const float4*>(Ab + (size_t)(m0+row)*64 + c4);
        As[c4+0][row]=v.x; As[c4+1][row]=v.y; As[c4+2][row]=v.z; As[c4+3][row]=v.w;
        float4 w = *reinterpret_cast<const float4*>(Bb + (size_t)(n0+row)*64 + c4);
        Bs[c4+0][row]=w.x; Bs[c4+1][row]=w.y; Bs[c4+2][row]=w.z; Bs[c4+3][row]=w.w;
    }
    __syncthreads();
    int tx8 = (tid & 15) * 8, ty8 = (tid >> 4) * 8;
    float acc[8][8] = {};
#pragma unroll 8
    for (int kk = 0; kk < 64; kk++) {
        float a[8], b[8];
        *reinterpret_cast<float4*>(&a[0]) = *reinterpret_cast<float4*>(&As[kk][ty8]);
        *reinterpret_cast<float4*>(&a[4]) = *reinterpret_cast<float4*>(&As[kk][ty8+4]);
        *reinterpret_cast<float4*>(&b[0]) = *reinterpret_cast<float4*>(&Bs[kk][tx8]);
        *reinterpret_cast<float4*>(&b[4]) = *reinterpret_cast<float4*>(&Bs[kk][tx8+4]);
#pragma unroll
        for (int i = 0; i < 8; i++)
#pragma unroll
            for (int j = 0; j < 8; j++) acc[i][j] += a[i]*b[j];
    }
#pragma unroll
    for (int i = 0; i < 8; i++) {
        *reinterpret_cast<float4*>(Cb + (size_t)(m0+ty8+i)*Nb + n0+tx8) =
            make_float4(acc[i][0],acc[i][1],acc[i][2],acc[i][3]);
        *reinterpret_cast<float4*>(Cb + (size_t)(m0+ty8+i)*Nb + n0+tx8+4) =
            make_float4(acc[i][4],acc[i][5],acc[i][6],acc[i][7]);
    }
}

// ---------------- NS GEMM, full K, 128x128 tile (single tf32; iters 1-3) -----
// Out = alpha*(A@B) + beta*Cadd. Fragment layout identical to proven ns_tf32.
// grid (2, 2, 16) = 64 blocks; static smem 34.8 KB -> multi-block co-residency.
__global__ void __launch_bounds__(256) ns_full1_kernel(
    const float* __restrict__ A, const float* __restrict__ B,
    const float* __restrict__ Cadd, float* __restrict__ Out,
    float alpha, float beta)
{
    __shared__ __align__(16) uint32_t As[32][136];
    __shared__ __align__(16) uint32_t Bs[32][136];
    int bh = blockIdx.z;
    int n0 = blockIdx.x * 128;
    int m0 = blockIdx.y * 128;
    const float* Ab = A + (size_t)bh*MM*MM;
    const float* Bb = B + (size_t)bh*MM*MM;
    float*       Ob = Out + (size_t)bh*MM*MM;
    int tid = threadIdx.x, lane = tid & 31, wid = tid >> 5;
    int wm = (wid & 1) * 64;
    int wn = (wid >> 1) * 32;
    int r4 = lane >> 2, c4 = lane & 3;
    float4 acc[4][4];
#pragma unroll
    for (int i = 0; i < 4; i++)
#pragma unroll
        for (int j = 0; j < 4; j++) acc[i][j] = make_float4(0.f,0.f,0.f,0.f);

    for (int kc = 0; kc < 8; kc++) {
        int k0g = kc*32;
        if (kc) __syncthreads();
#pragma unroll
        for (int i = 0; i < 4; i++) {            // A: 128m x 32k -> k-major
            int idx = tid + i*256;
            int row = idx & 127;
            int kq  = (idx >> 7) * 4;
            float4 v = *reinterpret_cast<const float4*>(Ab + (size_t)(m0+row)*MM + k0g + kq);
            As[kq+0][row]=f2tf(v.x); As[kq+1][row]=f2tf(v.y);
            As[kq+2][row]=f2tf(v.z); As[kq+3][row]=f2tf(v.w);
        }
#pragma unroll
        for (int i = 0; i < 4; i++) {            // B: 32k x 128n
            int idx = tid + i*256;
            int row = idx >> 5;
            int cq  = (idx & 31) * 4;
            float4 v = *reinterpret_cast<const float4*>(Bb + (size_t)(k0g+row)*MM + n0 + cq);
            uint4 t; t.x=f2tf(v.x); t.y=f2tf(v.y); t.z=f2tf(v.z); t.w=f2tf(v.w);
            *reinterpret_cast<uint4*>(&Bs[row][cq]) = t;
        }
        __syncthreads();
#pragma unroll
        for (int ks = 0; ks < 4; ks++) {
            int k0 = ks*8;
            uint32_t af[4][4], bf[4][2];
#pragma unroll
            for (int i = 0; i < 4; i++) {
                int mb = wm + i*16;
                af[i][0] = As[k0+c4  ][mb+r4];
                af[i][1] = As[k0+c4  ][mb+8+r4];
                af[i][2] = As[k0+4+c4][mb+r4];
                af[i][3] = As[k0+4+c4][mb+8+r4];
            }
#pragma unroll
            for (int j = 0; j < 4; j++) {
                int nb = wn + j*8;
                bf[j][0] = Bs[k0+c4  ][nb+r4];
                bf[j][1] = Bs[k0+4+c4][nb+r4];
            }
#pragma unroll
            for (int i = 0; i < 4; i++)
#pragma unroll
                for (int j = 0; j < 4; j++) mma_tf32(acc[i][j], af[i], bf[j]);
        }
    }
    const float* Cb = Cadd ? (Cadd + (size_t)bh*MM*MM) : nullptr;
#pragma unroll
    for (int i = 0; i < 4; i++) {
        int row0 = m0 + wm + i*16 + r4;
#pragma unroll
        for (int j = 0; j < 4; j++) {
            int col = n0 + wn + j*8 + 2*c4;
            float2 v0 = make_float2(alpha*acc[i][j].x, alpha*acc[i][j].y);
            float2 v1 = make_float2(alpha*acc[i][j].z, alpha*acc[i][j].w);
            if (Cb) {
                float2 c0 = *reinterpret_cast<const float2*>(Cb + (size_t)row0*MM + col);
                float2 c1 = *reinterpret_cast<const float2*>(Cb + (size_t)(row0+8)*MM + col);
                v0.x += beta*c0.x; v0.y += beta*c0.y;
                v1.x += beta*c1.x; v1.y += beta*c1.y;
            }
            *reinterpret_cast<float2*>(Ob + (size_t)row0*MM + col) = v0;
            *reinterpret_cast<float2*>(Ob + (size_t)(row0+8)*MM + col) = v1;
        }
    }
}

// ---------------- NS GEMM, full K, 128x128 tile (3xTF32; iteration 4) --------
// Fragment layout identical to proven ns_tf32x3. grid (2, 2, 16).
__global__ void __launch_bounds__(256) ns_full3_kernel(
    const float* __restrict__ A, const float* __restrict__ B,
    const float* __restrict__ Cadd, float* __restrict__ Out,
    float alpha, float beta)
{
    extern __shared__ uint2 smu[];
    uint2 (*As2)[132] = reinterpret_cast<uint2(*)[132]>(smu);
    uint2 (*Bs2)[132] = reinterpret_cast<uint2(*)[132]>(smu + 32*132);
    int bh = blockIdx.z;
    int n0 = blockIdx.x * 128;
    int m0 = blockIdx.y * 128;
    const float* Ab = A + (size_t)bh*MM*MM;
    const float* Bb = B + (size_t)bh*MM*MM;
    float*       Ob = Out + (size_t)bh*MM*MM;
    int tid = threadIdx.x, lane = tid & 31, wid = tid >> 5;
    int wm = (wid & 1) * 64;
    int wn = (wid >> 1) * 32;
    int r4 = lane >> 2, c4 = lane & 3;
    float4 acc[4][4];
#pragma unroll
    for (int i = 0; i < 4; i++)
#pragma unroll
        for (int j = 0; j < 4; j++) acc[i][j] = make_float4(0.f,0.f,0.f,0.f);

    for (int kc = 0; kc < 8; kc++) {
        int k0g = kc*32;
        if (kc) __syncthreads();
#pragma unroll
        for (int i = 0; i < 4; i++) {
            int idx = tid + i*256;
            int row = idx & 127;
            int kq  = (idx >> 7) * 4;
            float4 v = *reinterpret_cast<const float4*>(Ab + (size_t)(m0+row)*MM + k0g + kq);
            As2[kq+0][row]=split_tf32(v.x); As2[kq+1][row]=split_tf32(v.y);
            As2[kq+2][row]=split_tf32(v.z); As2[kq+3][row]=split_tf32(v.w);
        }
#pragma unroll
        for (int i = 0; i < 4; i++) {
            int idx = tid + i*256;
            int row = idx >> 5;
            int cq  = (idx & 31) * 4;
            float4 v = *reinterpret_cast<const float4*>(Bb + (size_t)(k0g+row)*MM + n0 + cq);
            Bs2[row][cq+0]=split_tf32(v.x); Bs2[row][cq+1]=split_tf32(v.y);
            Bs2[row][cq+2]=split_tf32(v.z); Bs2[row][cq+3]=split_tf32(v.w);
        }
        __syncthreads();
#pragma unroll
        for (int ks = 0; ks < 4; ks++) {
            int k0 = ks*8;
            uint2 a2[4][4], b2[4][2];
#pragma unroll
            for (int i = 0; i < 4; i++) {
                int mb = wm + i*16;
                a2[i][0] = As2[k0+c4  ][mb+r4];
                a2[i][1] = As2[k0+c4  ][mb+8+r4];
                a2[i][2] = As2[k0+4+c4][mb+r4];
                a2[i][3] = As2[k0+4+c4][mb+8+r4];
            }
#pragma unroll
            for (int j = 0; j < 4; j++) {
                int nb = wn + j*8;
                b2[j][0] = Bs2[k0+c4  ][nb+r4];
                b2[j][1] = Bs2[k0+4+c4][nb+r4];
            }
#pragma unroll
            for (int i = 0; i < 4; i++)
#pragma unroll
                for (int j = 0; j < 4; j++) mma_tf32x3(acc[i][j], a2[i], b2[j]);
        }
    }
    const float* Cb = Cadd ? (Cadd + (size_t)bh*MM*MM) : nullptr;
#pragma unroll
    for (int i = 0; i < 4; i++) {
        int row0 = m0 + wm + i*16 + r4;
#pragma unroll
        for (int j = 0; j < 4; j++) {
            int col = n0 + wn + j*8 + 2*c4;
            float2 v0 = make_float2(alpha*acc[i][j].x, alpha*acc[i][j].y);
            float2 v1 = make_float2(alpha*acc[i][j].z, alpha*acc[i][j].w);
            if (Cb) {
                float2 c0 = *reinterpret_cast<const float2*>(Cb + (size_t)row0*MM + col);
                float2 c1 = *reinterpret_cast<const float2*>(Cb + (size_t)(row0+8)*MM + col);
                v0.x += beta*c0.x; v0.y += beta*c0.y;
                v1.x += beta*c1.x; v1.y += beta*c1.y;
            }
            *reinterpret_cast<float2*>(Ob + (size_t)row0*MM + col) = v0;
            *reinterpret_cast<float2*>(Ob + (size_t)(row0+8)*MM + col) = v1;
        }
    }
}

// ---------------- NN GEMM (small, for Y = inv @ RV) --------------------------
__global__ void __launch_bounds__(256) gemm_nn_kernel(
    const float* __restrict__ A, const float* __restrict__ B,
    float* __restrict__ Out, int Ma, int Nb, int Kd)
{
    __shared__ float As[64][65];
    __shared__ float Bs[64][65];
    int bh = blockIdx.z;
    int n0 = blockIdx.x * 64;
    int m0 = blockIdx.y * 64;
    const float* Ab = A + (size_t)bh*Ma*Kd;
    const float* Bb = B + (size_t)bh*Kd*Nb;
    float*       Ob = Out + (size_t)bh*Ma*Nb;
    int tid = threadIdx.x;
    int tx4 = (tid & 15) * 4, ty4 = (tid >> 4) * 4;
    float acc[4][4] = {};
    for (int k0 = 0; k0 < Kd; k0 += 64) {
        for (int l = tid; l < 64*16; l += 256) {
            int row = l >> 4, c4 = (l & 15) * 4;
            float4 va = *reinterpret_cast<const float4*>(Ab + (size_t)(m0+row)*Kd + k0 + c4);
            As[row][c4+0]=va.x; As[row][c4+1]=va.y; As[row][c4+2]=va.z; As[row][c4+3]=va.w;
            float4 vb = *reinterpret_cast<const float4*>(Bb + (size_t)(k0+row)*Nb + n0 + c4);
            Bs[row][c4+0]=vb.x; Bs[row][c4+1]=vb.y; Bs[row][c4+2]=vb.z; Bs[row][c4+3]=vb.w;
        }
        __syncthreads();
#pragma unroll 16
        for (int kk = 0; kk < 64; kk++) {
            float a0=As[ty4+0][kk], a1=As[ty4+1][kk], a2=As[ty4+2][kk], a3=As[ty4+3][kk];
            float b0=Bs[kk][tx4+0], b1=Bs[kk][tx4+1], b2=Bs[kk][tx4+2], b3=Bs[kk][tx4+3];
            acc[0][0]+=a0*b0; acc[0][1]+=a0*b1; acc[0][2]+=a0*b2; acc[0][3]+=a0*b3;
            acc[1][0]+=a1*b0; acc[1][1]+=a1*b1; acc[1][2]+=a1*b2; acc[1][3]+=a1*b3;
            acc[2][0]+=a2*b0; acc[2][1]+=a2*b1; acc[2][2]+=a2*b2; acc[2][3]+=a2*b3;
            acc[3][0]+=a3*b0; acc[3][1]+=a3*b1; acc[3][2]+=a3*b2; acc[3][3]+=a3*b3;
        }
        __syncthreads();
    }
#pragma unroll
    for (int i = 0; i < 4; i++) {
        size_t off = (size_t)(m0+ty4+i)*Nb + n0 + tx4;
        *reinterpret_cast<float4*>(Ob + off) =
            make_float4(acc[i][0], acc[i][1], acc[i][2], acc[i][3]);
    }
}

// ---------------- row softmax (in place), one block per row ------------------
__global__ void softmax_rows_kernel(float* __restrict__ data, int cols)
{
    extern __shared__ float buf[];
    __shared__ float red[256];
    size_t row = blockIdx.x;
    float* d = data + row * (size_t)cols;
    int tid = threadIdx.x;
    float mx = -FLT_MAX;
    for (int c = tid; c < cols; c += 256) { float v = d[c]; buf[c] = v; mx = fmaxf(mx, v); }
    red[tid] = mx; __syncthreads();
    for (int st = 128; st > 0; st >>= 1) { if (tid < st) red[tid] = fmaxf(red[tid], red[tid+st]); __syncthreads(); }
    mx = red[0];
    __syncthreads();
    float s = 0.f;
    for (int c = tid; c < cols; c += 256) { float e = __expf(buf[c] - mx); buf[c] = e; s += e; }
    red[tid] = s; __syncthreads();
    for (int st = 128; st > 0; st >>= 1) { if (tid < st) red[tid] += red[tid+st]; __syncthreads(); }
    float inv = 1.0f / red[0];
    for (int c = tid; c < cols; c += 256) d[c] = buf[c] * inv;
}

// ---------------- V0 = u^T / max_j(colsum_j(u)) ------------------------------
__global__ void __launch_bounds__(256) v0init_kernel(const float* __restrict__ U, float* __restrict__ V0)
{
    __shared__ float red[256];
    int bh = blockIdx.x;
    const float* u = U  + (size_t)bh*MM*MM;
    float*       v = V0 + (size_t)bh*MM*MM;
    int j = threadIdx.x;
    float s = 0.f;
    for (int i = 0; i < MM; i++) s += u[(size_t)i*MM + j];
    red[j] = s; __syncthreads();
    for (int st = 128; st > 0; st >>= 1) { if (j < st) red[j] = fmaxf(red[j], red[j+st]); __syncthreads(); }
    float scale = 1.0f / red[0];
    for (int q = 0; q < MM; q++) v[(size_t)j*MM + q] = scale * u[(size_t)q*MM + j];
}

// ---------------- flash RV: partial softmax(nr @ K^T) @ V over KV splits -----
__global__ void __launch_bounds__(256) rv_flash_kernel(
    const float* __restrict__ NR, const float* __restrict__ K,
    const float* __restrict__ V, float* __restrict__ P, float* __restrict__ ML)
{
    extern __shared__ float sm[];
    float (*Nrs)[68] = reinterpret_cast<float(*)[68]>(sm);
    float (*Ksk)[68] = reinterpret_cast<float(*)[68]>(sm + 128*68);
    float (*Vs)[68]  = reinterpret_cast<float(*)[68]>(sm + 128*68 + 64*68);
    float (*Ps)[68]  = reinterpret_cast<float(*)[68]>(sm + 128*68 + 2*64*68);
    int s  = blockIdx.x;
    int m0 = blockIdx.y * 128;
    int bh = blockIdx.z;
    const float* Nb = NR + (size_t)bh*MM*DD;
    const float* Kb = K  + (size_t)bh*NN*DD;
    const float* Vb = V  + (size_t)bh*NN*DD;
    int tid = threadIdx.x;
    int ry = (tid >> 4) * 8;
    int cx = (tid & 15) * 4;

#pragma unroll
    for (int i = 0; i < 8; i++) {
        int idx = tid + i*256;
        int row = idx >> 4, q4 = (idx & 15) * 4;
        *reinterpret_cast<float4*>(&Nrs[row][q4]) =
            *reinterpret_cast<const float4*>(Nb + (size_t)(m0+row)*DD + q4);
    }

    float m_i[8], l_i[8];
    float O[8][4] = {};
#pragma unroll
    for (int i = 0; i < 8; i++) { m_i[i] = -FLT_MAX; l_i[i] = 0.f; }

    for (int kc = 0; kc < 8; kc++) {
        int k0 = s*512 + kc*64;
        __syncthreads();
#pragma unroll
        for (int i = 0; i < 4; i++) {
            int idx = tid + i*256;
            int c  = idx & 63;
            int kq = (idx >> 6) * 4;
            float4 v = *reinterpret_cast<const float4*>(Kb + (size_t)(k0+c)*DD + kq);
            Ksk[kq+0][c]=v.x; Ksk[kq+1][c]=v.y; Ksk[kq+2][c]=v.z; Ksk[kq+3][c]=v.w;
        }
#pragma unroll
        for (int i = 0; i < 4; i++) {
            int idx = tid + i*256;
            int row = idx >> 4, q4 = (idx & 15) * 4;
            *reinterpret_cast<float4*>(&Vs[row][q4]) =
                *reinterpret_cast<const float4*>(Vb + (size_t)(k0+row)*DD + q4);
        }
        __syncthreads();

        float sv[8][4] = {};
#pragma unroll 8
        for (int kk = 0; kk < 64; kk++) {
            float b[4];
            *reinterpret_cast<float4*>(&b[0]) = *reinterpret_cast<float4*>(&Ksk[kk][cx]);
            float a[8];
#pragma unroll
            for (int i = 0; i < 8; i++) a[i] = Nrs[ry+i][kk];
#pragma unroll
            for (int i = 0; i < 8; i++)
#pragma unroll
                for (int j = 0; j < 4; j++) sv[i][j] += a[i]*b[j];
        }

#pragma unroll
        for (int i = 0; i < 8; i++) {
            float mc = fmaxf(fmaxf(sv[i][0], sv[i][1]), fmaxf(sv[i][2], sv[i][3]));
#pragma unroll
            for (int o = 8; o > 0; o >>= 1) mc = fmaxf(mc, __shfl_xor_sync(0xffffffffu, mc, o));
            float mn = fmaxf(m_i[i], mc);
            float corr = __expf(m_i[i] - mn);
            l_i[i] *= corr;
#pragma unroll
            for (int j = 0; j < 4; j++) O[i][j] *= corr;
            float ls = 0.f;
#pragma unroll
            for (int j = 0; j < 4; j++) {
                float p = __expf(sv[i][j] - mn);
                Ps[ry+i][cx+j] = p;
                ls += p;
            }
#pragma unroll
            for (int o = 8; o > 0; o >>= 1) ls += __shfl_xor_sync(0xffffffffu, ls, o);
            l_i[i] += ls;
            m_i[i] = mn;
        }
        __syncthreads();

#pragma unroll 8
        for (int kk = 0; kk < 64; kk++) {
            float b[4];
            *reinterpret_cast<float4*>(&b[0]) = *reinterpret_cast<float4*>(&Vs[kk][cx]);
            float a[8];
#pragma unroll
            for (int i = 0; i < 8; i++) a[i] = Ps[ry+i][kk];
#pragma unroll
            for (int i = 0; i < 8; i++)
#pragma unroll
                for (int j = 0; j < 4; j++) O[i][j] += a[i]*b[j];
        }
    }

    float* Pb = P + ((size_t)s*BH + bh)*MM*DD;
#pragma unroll
    for (int i = 0; i < 8; i++)
        *reinterpret_cast<float4*>(Pb + (size_t)(m0+ry+i)*DD + cx) =
            make_float4(O[i][0], O[i][1], O[i][2], O[i][3]);
    if ((tid & 15) == 0) {
        float* mlb = ML + (((size_t)s*BH + bh)*MM + m0)*2;
#pragma unroll
        for (int i = 0; i < 8; i++) {
            mlb[(ry+i)*2 + 0] = m_i[i];
            mlb[(ry+i)*2 + 1] = l_i[i];
        }
    }
}

__global__ void rv_combine_kernel(const float* __restrict__ P, const float* __restrict__ ML,
                                  float* __restrict__ RV)
{
    int gt = blockIdx.x * 256 + threadIdx.x;
    int row = gt >> 4;
    int c4  = (gt & 15) * 4;
    float m_s[8], l_s[8];
    float gm = -FLT_MAX;
#pragma unroll
    for (int s = 0; s < 8; s++) {
        m_s[s] = ML[(((size_t)s*BH*MM) + row)*2 + 0];
        l_s[s] = ML[(((size_t)s*BH*MM) + row)*2 + 1];
        gm = fmaxf(gm, m_s[s]);
    }
    float L = 0.f;
    float4 acc = make_float4(0.f,0.f,0.f,0.f);
#pragma unroll
    for (int s = 0; s < 8; s++) {
        float w = __expf(m_s[s] - gm);
        L += w * l_s[s];
        float4 o = *reinterpret_cast<const float4*>(P + ((size_t)s*BH*MM + row)*DD + c4);
        acc.x += w*o.x; acc.y += w*o.y; acc.z += w*o.z; acc.w += w*o.w;
    }
    float inv = 1.0f / L;
    *reinterpret_cast<float4*>(RV + (size_t)row*DD + c4) =
        make_float4(acc.x*inv, acc.y*inv, acc.z*inv, acc.w*inv);
}

// ---------------- fused final: X_chunk = softmax(Qs_chunk @ nc^T) @ Y --------
#define FX_LPAD 260
__global__ void __launch_bounds__(256) fusedx_kernel(
    const float* __restrict__ Q, const float* __restrict__ nc,
    const float* __restrict__ Y, float* __restrict__ X)
{
    extern __shared__ float sm[];
    float (*As)[132] = reinterpret_cast<float(*)[132]>(sm);
    float (*Bs)[132] = reinterpret_cast<float(*)[132]>(sm + 64*132);
    float (*Ys)[68]  = reinterpret_cast<float(*)[68]> (sm + 64*132);
    float (*L)[FX_LPAD] = reinterpret_cast<float(*)[FX_LPAD]>(sm + 2*64*132);
    int bh = blockIdx.y;
    int q0 = blockIdx.x * 128;
    int tid = threadIdx.x;
    const float* Qb  = Q  + (size_t)bh*NN*DD;
    const float* ncb = nc + (size_t)bh*MM*DD;
    const float* Yb  = Y  + (size_t)bh*MM*DD;

#pragma unroll
    for (int i = 0; i < 8; i++) {
        int idx = tid + i*256;
        int row = idx & 127;
        int c4  = (idx >> 7) * 4;
        float4 v = *reinterpret_cast<const float4*>(Qb + (size_t)(q0+row)*DD + c4);
        As[c4+0][row]=v.x*0.125f; As[c4+1][row]=v.y*0.125f;
        As[c4+2][row]=v.z*0.125f; As[c4+3][row]=v.w*0.125f;
    }

    int tx8 = (tid & 15) * 8, ty8 = (tid >> 4) * 8;
    for (int cc = 0; cc < 2; cc++) {
        __syncthreads();
#pragma unroll
        for (int i = 0; i < 8; i++) {
            int idx = tid + i*256;
            int row = idx & 127;
            int c4  = (idx >> 7) * 4;
            float4 v = *reinterpret_cast<const float4*>(ncb + (size_t)(cc*128+row)*DD + c4);
            Bs[c4+0][row]=v.x; Bs[c4+1][row]=v.y; Bs[c4+2][row]=v.z; Bs[c4+3][row]=v.w;
        }
        __syncthreads();
        float acc[8][8] = {};
#pragma unroll 8
        for (int kk = 0; kk < 64; kk++) {
            float a[8], b[8];
            *reinterpret_cast<float4*>(&a[0]) = *reinterpret_cast<float4*>(&As[kk][ty8]);
            *reinterpret_cast<float4*>(&a[4]) = *reinterpret_cast<float4*>(&As[kk][ty8+4]);
            *reinterpret_cast<float4*>(&b[0]) = *reinterpret_cast<float4*>(&Bs[kk][tx8]);
            *reinterpret_cast<float4*>(&b[4]) = *reinterpret_cast<float4*>(&Bs[kk][tx8+4]);
#pragma unroll
            for (int i = 0; i < 8; i++)
#pragma unroll
                for (int j = 0; j < 8; j++) acc[i][j] += a[i]*b[j];
        }
#pragma unroll
        for (int i = 0; i < 8; i++) {
            *reinterpret_cast<float4*>(&L[ty8+i][cc*128+tx8]) =
                make_float4(acc[i][0],acc[i][1],acc[i][2],acc[i][3]);
            *reinterpret_cast<float4*>(&L[ty8+i][cc*128+tx8+4]) =
                make_float4(acc[i][4],acc[i][5],acc[i][6],acc[i][7]);
        }
    }
    __syncthreads();

    int wid = tid >> 5, lane = tid & 31;
    for (int r = wid; r < 128; r += 8) {
        float v[8]; float mx = -FLT_MAX;
#pragma unroll
        for (int t = 0; t < 8; t++) { v[t] = L[r][lane + 32*t]; mx = fmaxf(mx, v[t]); }
#pragma unroll
        for (int o = 16; o > 0; o >>= 1) mx = fmaxf(mx, __shfl_xor_sync(0xffffffffu, mx, o));
        float s = 0.f;
#pragma unroll
        for (int t = 0; t < 8; t++) { v[t] = __expf(v[t] - mx); s += v[t]; }
#pragma unroll
        for (int o = 16; o > 0; o >>= 1) s += __shfl_xor_sync(0xffffffffu, s, o);
        float inv = 1.0f / s;
#pragma unroll
        for (int t = 0; t < 8; t++) L[r][lane + 32*t] = v[t] * inv;
    }

    int ry = (tid >> 4) * 8;
    int cx = (tid & 15) * 4;
    float acc3[8][4] = {};
    for (int kc = 0; kc < 4; kc++) {
        __syncthreads();
#pragma unroll
        for (int i = 0; i < 4; i++) {
            int idx = tid + i*256;
            int row = idx >> 4, c4 = (idx & 15) * 4;
            *reinterpret_cast<float4*>(&Ys[row][c4]) =
                *reinterpret_cast<const float4*>(Yb + (size_t)(kc*64+row)*DD + c4);
        }
        __syncthreads();
#pragma unroll 8
        for (int kk = 0; kk < 64; kk++) {
            float b[4];
            *reinterpret_cast<float4*>(&b[0]) = *reinterpret_cast<float4*>(&Ys[kk][cx]);
            float a[8];
#pragma unroll
            for (int i = 0; i < 8; i++) a[i] = L[ry+i][kc*64+kk];
#pragma unroll
            for (int i = 0; i < 8; i++)
#pragma unroll
                for (int j = 0; j < 4; j++) acc3[i][j] += a[i]*b[j];
        }
    }
#pragma unroll
    for (int i = 0; i < 8; i++)
        *reinterpret_cast<float4*>(X + ((size_t)bh*NN + q0 + ry + i)*DD + cx) =
            make_float4(acc3[i][0], acc3[i][1], acc3[i][2], acc3[i][3]);
}

// ---------------- host launch ----------------
extern "C" void kernel_launch(void* const* d_in, const int* in_sizes, int n_in,
                              void* d_out, int out_size)
{
    (void)in_sizes; (void)n_in; (void)out_size;
    const float* Q = (const float*)d_in[0];
    const float* K = (const float*)d_in[1];
    const float* V = (const float*)d_in[2];
    float* X = (float*)d_out;

    static cudaStream_t s2 = nullptr;
    static cudaEvent_t evFork = nullptr, evJoin = nullptr;
    static bool attrs_done = false;
    if (!s2) {
        cudaStreamCreateWithFlags(&s2, cudaStreamNonBlocking);
        cudaEventCreateWithFlags(&evFork, cudaEventDisableTiming);
        cudaEventCreateWithFlags(&evJoin, cudaEventDisableTiming);
    }
    const int NT_SMEM  = 2*64*132*sizeof(float);                 // 67.5 KB
    const int NS3_SMEM = 2*32*132*sizeof(uint2);                 // 67.6 KB
    const int FL_SMEM  = (128*68 + 64*68 + 64*68 + 128*68)*4;    // 104.4 KB
    const int FX_SMEM  = (2*64*132 + 128*FX_LPAD)*sizeof(float); // 200.7 KB
    if (!attrs_done) {
        cudaFuncSetAttribute(gemm_nt128_kernel, cudaFuncAttributeMaxDynamicSharedMemorySize, NT_SMEM);
        cudaFuncSetAttribute(ns_full3_kernel,   cudaFuncAttributeMaxDynamicSharedMemorySize, NS3_SMEM);
        cudaFuncSetAttribute(rv_flash_kernel,   cudaFuncAttributeMaxDynamicSharedMemorySize, FL_SMEM);
        cudaFuncSetAttribute(fusedx_kernel,     cudaFuncAttributeMaxDynamicSharedMemorySize, FX_SMEM);
        attrs_done = true;
    }

    float *nc, *nr, *u, *v0, *v1, *kv, *t1, *t2, *rvp, *ml, *rv, *y;
    int *ik, *iq;
    cudaGetSymbolAddress((void**)&nc, g_nc);
    cudaGetSymbolAddress((void**)&nr, g_nr);
    cudaGetSymbolAddress((void**)&ik, g_idxk);
    cudaGetSymbolAddress((void**)&iq, g_idxq);
    cudaGetSymbolAddress((void**)&u,  g_u);
    cudaGetSymbolAddress((void**)&v0, g_v0);
    cudaGetSymbolAddress((void**)&v1, g_v1);
    cudaGetSymbolAddress((void**)&kv, g_kv);
    cudaGetSymbolAddress((void**)&t1, g_t1);
    cudaGetSymbolAddress((void**)&t2, g_t2);
    cudaGetSymbolAddress((void**)&rvp, g_rvp);
    cudaGetSymbolAddress((void**)&ml, g_ml);
    cudaGetSymbolAddress((void**)&rv, g_rv);
    cudaGetSymbolAddress((void**)&y,  g_y);

    // 1) selection + gather
    topk_kernel<<<32, 1024>>>(Q, K, ik, iq);
    gather_kernel<<<16, dim3(64,4)>>>(Q, K, ik, iq, nc, nr);

    // fork: flash RV pipeline (fp32, FMA pipe) overlaps main-stream tensor work
    cudaEventRecord(evFork, 0);
    cudaStreamWaitEvent(s2, evFork, 0);

    rv_flash_kernel<<<dim3(8, 2, 16), 256, FL_SMEM, s2>>>(nr, K, V, rvp, ml);
    rv_combine_kernel<<<BH*MM*DD/(256*4), 256, 0, s2>>>(rvp, ml, rv);
    cudaEventRecord(evJoin, s2);

    // main: u = softmax(nr @ nc^T); Newton-Schulz inverse
    gemm_nt128_kernel<<<dim3(2, 2, 16), 256, NT_SMEM>>>(nr, nc, u, MM, MM);
    softmax_rows_kernel<<<BH*MM, 256, MM*sizeof(float)>>>(u, MM);
    v0init_kernel<<<16, 256>>>(u, v0);

    const dim3 NSG(2, 2, 16);   // 128x128 tiles, full K, 64 blocks
    float* vin = v0; float* vout = v1;
    for (int it = 0; it < 4; it++) {
        if (it < 3) {
            // single tf32, fused epilogue: Newton-Schulz self-corrects the noise
            ns_full1_kernel<<<NSG, 256>>>(u,   vin, nullptr, kv,   1.0f,  0.0f);
            ns_full1_kernel<<<NSG, 256>>>(kv,  kv,  kv,      t1,  -1.0f,  7.0f);
            ns_full1_kernel<<<NSG, 256>>>(kv,  t1,  kv,      t2,  -1.0f, 15.0f);
            ns_full1_kernel<<<NSG, 256>>>(vin, t2,  vin,     vout, -0.25f, 3.25f);
        } else {
            // final iteration fp32-grade (3xTF32, fused epilogue)
            ns_full3_kernel<<<NSG, 256, NS3_SMEM>>>(u,   vin, nullptr, kv,   1.0f,  0.0f);
            ns_full3_kernel<<<NSG, 256, NS3_SMEM>>>(kv,  kv,  kv,      t1,  -1.0f,  7.0f);
            ns_full3_kernel<<<NSG, 256, NS3_SMEM>>>(kv,  t1,  kv,      t2,  -1.0f, 15.0f);
            ns_full3_kernel<<<NSG, 256, NS3_SMEM>>>(vin, t2,  vin,     vout, -0.25f, 3.25f);
        }
        float* tmp = vin; vin = vout; vout = tmp;
    }

    // join: need rv before Y
    cudaStreamWaitEvent(0, evJoin, 0);

    // 7) Y = V_inv @ RV
    gemm_nn_kernel<<<dim3(1,4,16), 256>>>(vin, rv, y, MM, DD, MM);
    // 8) X = softmax(Qs @ nc^T) @ Y, fused per 128-row chunk
    fusedx_kernel<<<dim3(NN/128, BH), 256, FX_SMEM>>>(Q, nc, y, X);
}

// round 14
// speedup vs baseline: 1.1330x; 1.1330x over previous
#include <cuda_runtime.h>
#include <float.h>
#include <stdint.h>

#define BH 16
#define HH 8
#define NN 4096
#define DD 64
#define MM 256

// ---------------- scratch (__device__ globals; no allocation) ----------------
__device__ float g_nc [BH*MM*DD];
__device__ float g_nr [BH*MM*DD];
__device__ int   g_idxk[BH*MM];
__device__ int   g_idxq[BH*MM];
__device__ float g_u  [BH*MM*MM];
__device__ float g_v0 [BH*MM*MM];
__device__ float g_v1 [BH*MM*MM];
__device__ float g_kv [BH*MM*MM];
__device__ float g_t1 [BH*MM*MM];
__device__ float g_t2 [BH*MM*MM];
__device__ float g_rvp[8*BH*MM*DD];          // flash split partials
__device__ float g_ml [8*BH*MM*2];           // flash split (max, sumexp)
__device__ float g_rv [BH*MM*DD];
__device__ float g_y  [BH*MM*DD];

// ---------------- tf32 mma helpers ----------------
__device__ __forceinline__ uint32_t f2tf(float v) {
    uint32_t r; asm("cvt.rna.tf32.f32 %0, %1;" : "=r"(r) : "f"(v)); return r;
}
__device__ __forceinline__ void mma_tf32(float4& d, const uint32_t* a, const uint32_t* b) {
    asm volatile("mma.sync.aligned.m16n8k8.row.col.f32.tf32.tf32.f32 "
        "{%0,%1,%2,%3}, {%4,%5,%6,%7}, {%8,%9}, {%0,%1,%2,%3};"
        : "+f"(d.x), "+f"(d.y), "+f"(d.z), "+f"(d.w)
        : "r"(a[0]), "r"(a[1]), "r"(a[2]), "r"(a[3]), "r"(b[0]), "r"(b[1]));
}
__device__ __forceinline__ uint2 split_tf32(float x) {
    uint32_t hi = f2tf(x);
    float lo = x - __uint_as_float(hi);
    return make_uint2(hi, f2tf(lo));
}
// 3xTF32: d += a_hi*b_hi + a_lo*b_hi + a_hi*b_lo (fp32-grade)
__device__ __forceinline__ void mma_tf32x3(float4& d, const uint2* a, const uint2* b) {
    uint32_t ah[4] = {a[0].x, a[1].x, a[2].x, a[3].x};
    uint32_t al[4] = {a[0].y, a[1].y, a[2].y, a[3].y};
    uint32_t bh_[2] = {b[0].x, b[1].x};
    uint32_t bl_[2] = {b[0].y, b[1].y};
    mma_tf32(d, ah, bh_);
    mma_tf32(d, al, bh_);
    mma_tf32(d, ah, bl_);
}

// ---------------- top-k: exact bitonic sort of (sum,row) keys ----------------
__global__ void __launch_bounds__(1024) topk_kernel(
    const float* __restrict__ Q, const float* __restrict__ K,
    int* __restrict__ idxk, int* __restrict__ idxq)
{
    __shared__ unsigned long long keys[NN];
    int bh  = blockIdx.x >> 1;
    int isQ = blockIdx.x & 1;
    const float* src = isQ ? Q : K;
    int tid = threadIdx.x;

    for (int r = tid; r < NN; r += 1024) {
        const float4* p = reinterpret_cast<const float4*>(src + ((size_t)bh*NN + r)*DD);
        float s = 0.f;
#pragma unroll
        for (int t = 0; t < DD/4; t++) { float4 v = p[t]; s += v.x + v.y + v.z + v.w; }
        unsigned int u = __float_as_uint(s);
        unsigned int m = (u & 0x80000000u) ? ~u : (u | 0x80000000u);
        keys[r] = ((unsigned long long)(~m) << 32) | (unsigned int)r;
    }
    __syncthreads();

    for (int k = 2; k <= NN; k <<= 1) {
        for (int j = k >> 1; j > 0; j >>= 1) {
            for (int i = tid; i < NN; i += 1024) {
                int ixj = i ^ j;
                if (ixj > i) {
                    bool up = ((i & k) == 0);
                    unsigned long long a = keys[i], c = keys[ixj];
                    if ((a > c) == up) { keys[i] = c; keys[ixj] = a; }
                }
            }
            __syncthreads();
        }
    }
    int* dst = isQ ? idxq : idxk;
    if (tid < MM) dst[bh*MM + tid] = (int)(keys[tid] & 0xFFFFFFFFu);
}

// ---------------- gather nc = K[idx_k], nr = Q[idx_q]/8 ----------------
__global__ void gather_kernel(const float* __restrict__ Q, const float* __restrict__ K,
                              const int* __restrict__ idxk, const int* __restrict__ idxq,
                              float* __restrict__ nc, float* __restrict__ nr)
{
    int bh = blockIdx.x;
    int tx = threadIdx.x;
    int ty = threadIdx.y;
    for (int i = ty; i < MM; i += 4) {
        int ik = idxk[bh*MM + i];
        int iq = idxq[bh*MM + i];
        nc[((size_t)bh*MM + i)*DD + tx] = K[((size_t)bh*NN + ik)*DD + tx];
        nr[((size_t)bh*MM + i)*DD + tx] = Q[((size_t)bh*NN + iq)*DD + tx] * 0.125f;
    }
}

// ---------------- NT GEMM (K=64): 128x128 tile, 8x8 micro (fp32) -------------
__global__ void __launch_bounds__(256) gemm_nt128_kernel(
    const float* __restrict__ A, const float* __restrict__ B, float* __restrict__ C,
    int Ma, int Nb)
{
    extern __shared__ float sm[];
    float (*As)[132] = reinterpret_cast<float(*)[132]>(sm);
    float (*Bs)[132] = reinterpret_cast<float(*)[132]>(sm + 64*132);
    int bh = blockIdx.z;
    int m0 = blockIdx.y * 128;
    int n0 = blockIdx.x * 128;
    const float* Ab = A + (size_t)bh*Ma*64;
    const float* Bb = B + (size_t)bh*Nb*64;
    float*       Cb = C + (size_t)bh*Ma*Nb;
    int tid = threadIdx.x;
#pragma unroll
    for (int i = 0; i < 8; i++) {
        int idx = tid + i*256;
        int row = idx & 127;
        int c4  = (idx >> 7) * 4;
        float4 v = *reinterpret_cast<const float4*>(Ab + (size_t)(m0+row)*64 + c4);
        As[c4+0][row]=v.x; As[c4+1][row]=v.y; As[c4+2][row]=v.z; As[c4+3][row]=v.w;
        float4 w = *reinterpret_cast<const float4*>(Bb + (size_t)(n0+row)*64 + c4);
        Bs[c4+0][row]=w.x; Bs[c4+1][row]=w.y; Bs[c4+2][row]=w.z; Bs[c4+3][row]=w.w;
    }
    __syncthreads();
    int tx8 = (tid & 15) * 8, ty8 = (tid >> 4) * 8;
    float acc[8][8] = {};
#pragma unroll 8
    for (int kk = 0; kk < 64; kk++) {
        float a[8], b[8];
        *reinterpret_cast<float4*>(&a[0]) = *reinterpret_cast<float4*>(&As[kk][ty8]);
        *reinterpret_cast<float4*>(&a[4]) = *reinterpret_cast<float4*>(&As[kk][ty8+4]);
        *reinterpret_cast<float4*>(&b[0]) = *reinterpret_cast<float4*>(&Bs[kk][tx8]);
        *reinterpret_cast<float4*>(&b[4]) = *reinterpret_cast<float4*>(&Bs[kk][tx8+4]);
#pragma unroll
        for (int i = 0; i < 8; i++)
#pragma unroll
            for (int j = 0; j < 8; j++) acc[i][j] += a[i]*b[j];
    }
#pragma unroll
    for (int i = 0; i < 8; i++) {
        *reinterpret_cast<float4*>(Cb + (size_t)(m0+ty8+i)*Nb + n0+tx8) =
            make_float4(acc[i][0],acc[i][1],acc[i][2],acc[i][3]);
        *reinterpret_cast<float4*>(Cb + (size_t)(m0+ty8+i)*Nb + n0+tx8+4) =
            make_float4(acc[i][4],acc[i][5],acc[i][6],acc[i][7]);
    }
}

// ---------------- NS fused GEMM (single tf32, full K, fused epilogue) --------
// Out = alpha*(A@B) + beta*Cadd. Proven R8/R10/R11/R12. grid (4, 2, 16).
__global__ void __launch_bounds__(256) ns_fused1_kernel(
    const float* __restrict__ A, const float* __restrict__ B,
    const float* __restrict__ Cadd, float* __restrict__ Out,
    float alpha, float beta)
{
    extern __shared__ char smc[];
    uint32_t (*As)[136] = reinterpret_cast<uint32_t(*)[136]>(smc);
    uint32_t (*Bs)[72]  = reinterpret_cast<uint32_t(*)[72]> (smc + 64*136*4);
    int bh = blockIdx.z;
    int n0 = blockIdx.x * 64;
    int m0 = blockIdx.y * 128;
    const float* Ab = A + (size_t)bh*MM*MM;
    const float* Bb = B + (size_t)bh*MM*MM;
    float*       Ob = Out + (size_t)bh*MM*MM;
    int tid = threadIdx.x, lane = tid & 31, wid = tid >> 5;
    int r4 = lane >> 2, c4 = lane & 3;
    int wm = (wid & 1) * 64;
    int wn = ((wid >> 1) & 1) * 32;
    int kg = wid >> 2;
    int kb = kg * 32;

    float4 acc[4][4];
#pragma unroll
    for (int i = 0; i < 4; i++)
#pragma unroll
        for (int j = 0; j < 4; j++) acc[i][j] = make_float4(0.f,0.f,0.f,0.f);

    for (int sc = 0; sc < 4; sc++) {
        int k0g = sc * 64;
        if (sc) __syncthreads();
#pragma unroll
        for (int i = 0; i < 8; i++) {
            int idx = tid + i*256;
            int row = idx & 127;
            int kq  = (idx >> 7) * 4;
            float4 v = *reinterpret_cast<const float4*>(Ab + (size_t)(m0+row)*MM + k0g + kq);
            As[kq+0][row]=f2tf(v.x); As[kq+1][row]=f2tf(v.y);
            As[kq+2][row]=f2tf(v.z); As[kq+3][row]=f2tf(v.w);
        }
#pragma unroll
        for (int i = 0; i < 4; i++) {
            int idx = tid + i*256;
            int row = idx >> 4;
            int cq  = (idx & 15) * 4;
            float4 v = *reinterpret_cast<const float4*>(Bb + (size_t)(k0g+row)*MM + n0 + cq);
            Bs[row][cq+0]=f2tf(v.x); Bs[row][cq+1]=f2tf(v.y);
            Bs[row][cq+2]=f2tf(v.z); Bs[row][cq+3]=f2tf(v.w);
        }
        __syncthreads();
#pragma unroll
        for (int ks = 0; ks < 4; ks++) {
            int k0 = kb + ks*8;
            uint32_t af[4][4], bf[4][2];
#pragma unroll
            for (int i = 0; i < 4; i++) {
                int mb = wm + i*16;
                af[i][0] = As[k0+c4  ][mb+r4];
                af[i][1] = As[k0+c4  ][mb+8+r4];
                af[i][2] = As[k0+4+c4][mb+r4];
                af[i][3] = As[k0+4+c4][mb+8+r4];
            }
#pragma unroll
            for (int j = 0; j < 4; j++) {
                int nb = wn + j*8;
                bf[j][0] = Bs[k0+c4  ][nb+r4];
                bf[j][1] = Bs[k0+4+c4][nb+r4];
            }
#pragma unroll
            for (int i = 0; i < 4; i++)
#pragma unroll
                for (int j = 0; j < 4; j++) mma_tf32(acc[i][j], af[i], bf[j]);
        }
    }

    __syncthreads();
    float4* red = reinterpret_cast<float4*>(smc);
    if (kg == 1) {
        int slot = wid - 4;
#pragma unroll
        for (int f = 0; f < 16; f++)
            red[((size_t)f*4 + slot)*32 + lane] = acc[f>>2][f&3];
    }
    __syncthreads();
    if (kg == 0) {
        const float* Cb = Cadd ? (Cadd + (size_t)bh*MM*MM) : nullptr;
#pragma unroll
        for (int f = 0; f < 16; f++) {
            float4 o = red[((size_t)f*4 + wid)*32 + lane];
            acc[f>>2][f&3].x += o.x; acc[f>>2][f&3].y += o.y;
            acc[f>>2][f&3].z += o.z; acc[f>>2][f&3].w += o.w;
        }
#pragma unroll
        for (int i = 0; i < 4; i++) {
            int row0 = m0 + wm + i*16 + r4;
#pragma unroll
            for (int j = 0; j < 4; j++) {
                int col = n0 + wn + j*8 + 2*c4;
                float2 v0 = make_float2(alpha*acc[i][j].x, alpha*acc[i][j].y);
                float2 v1 = make_float2(alpha*acc[i][j].z, alpha*acc[i][j].w);
                if (Cb) {
                    float2 c0 = *reinterpret_cast<const float2*>(Cb + (size_t)row0*MM + col);
                    float2 c1 = *reinterpret_cast<const float2*>(Cb + (size_t)(row0+8)*MM + col);
                    v0.x += beta*c0.x; v0.y += beta*c0.y;
                    v1.x += beta*c1.x; v1.y += beta*c1.y;
                }
                *reinterpret_cast<float2*>(Ob + (size_t)row0*MM + col) = v0;
                *reinterpret_cast<float2*>(Ob + (size_t)(row0+8)*MM + col) = v1;
            }
        }
    }
}

// ---------------- NS fused GEMM (3xTF32, fp32-grade; iteration 4) ------------
// Proven R12. grid (4, 2, 16).
__global__ void __launch_bounds__(256) ns_fused3_kernel(
    const float* __restrict__ A, const float* __restrict__ B,
    const float* __restrict__ Cadd, float* __restrict__ Out,
    float alpha, float beta)
{
    extern __shared__ char smc[];
    uint2 (*As2)[132] = reinterpret_cast<uint2(*)[132]>(smc);
    uint2 (*Bs2)[72]  = reinterpret_cast<uint2(*)[72]> (smc + 64*132*8);
    int bh = blockIdx.z;
    int n0 = blockIdx.x * 64;
    int m0 = blockIdx.y * 128;
    const float* Ab = A + (size_t)bh*MM*MM;
    const float* Bb = B + (size_t)bh*MM*MM;
    float*       Ob = Out + (size_t)bh*MM*MM;
    int tid = threadIdx.x, lane = tid & 31, wid = tid >> 5;
    int r4 = lane >> 2, c4 = lane & 3;
    int wm = (wid & 1) * 64;
    int wn = ((wid >> 1) & 1) * 32;
    int kg = wid >> 2;
    int kb = kg * 32;

    float4 acc[4][4];
#pragma unroll
    for (int i = 0; i < 4; i++)
#pragma unroll
        for (int j = 0; j < 4; j++) acc[i][j] = make_float4(0.f,0.f,0.f,0.f);

    for (int sc = 0; sc < 4; sc++) {
        int k0g = sc * 64;
        if (sc) __syncthreads();
#pragma unroll
        for (int i = 0; i < 8; i++) {
            int idx = tid + i*256;
            int row = idx & 127;
            int kq  = (idx >> 7) * 4;
            float4 v = *reinterpret_cast<const float4*>(Ab + (size_t)(m0+row)*MM + k0g + kq);
            As2[kq+0][row]=split_tf32(v.x); As2[kq+1][row]=split_tf32(v.y);
            As2[kq+2][row]=split_tf32(v.z); As2[kq+3][row]=split_tf32(v.w);
        }
#pragma unroll
        for (int i = 0; i < 4; i++) {
            int idx = tid + i*256;
            int row = idx >> 4;
            int cq  = (idx & 15) * 4;
            float4 v = *reinterpret_cast<const float4*>(Bb + (size_t)(k0g+row)*MM + n0 + cq);
            Bs2[row][cq+0]=split_tf32(v.x); Bs2[row][cq+1]=split_tf32(v.y);
            Bs2[row][cq+2]=split_tf32(v.z); Bs2[row][cq+3]=split_tf32(v.w);
        }
        __syncthreads();
#pragma unroll
        for (int ks = 0; ks < 4; ks++) {
            int k0 = kb + ks*8;
            uint2 a2[4][4], b2[4][2];
#pragma unroll
            for (int i = 0; i < 4; i++) {
                int mb = wm + i*16;
                a2[i][0] = As2[k0+c4  ][mb+r4];
                a2[i][1] = As2[k0+c4  ][mb+8+r4];
                a2[i][2] = As2[k0+4+c4][mb+r4];
                a2[i][3] = As2[k0+4+c4][mb+8+r4];
            }
#pragma unroll
            for (int j = 0; j < 4; j++) {
                int nb = wn + j*8;
                b2[j][0] = Bs2[k0+c4  ][nb+r4];
                b2[j][1] = Bs2[k0+4+c4][nb+r4];
            }
#pragma unroll
            for (int i = 0; i < 4; i++)
#pragma unroll
                for (int j = 0; j < 4; j++) mma_tf32x3(acc[i][j], a2[i], b2[j]);
        }
    }

    __syncthreads();
    float4* red = reinterpret_cast<float4*>(smc);
    if (kg == 1) {
        int slot = wid - 4;
#pragma unroll
        for (int f = 0; f < 16; f++)
            red[((size_t)f*4 + slot)*32 + lane] = acc[f>>2][f&3];
    }
    __syncthreads();
    if (kg == 0) {
        const float* Cb = Cadd ? (Cadd + (size_t)bh*MM*MM) : nullptr;
#pragma unroll
        for (int f = 0; f < 16; f++) {
            float4 o = red[((size_t)f*4 + wid)*32 + lane];
            acc[f>>2][f&3].x += o.x; acc[f>>2][f&3].y += o.y;
            acc[f>>2][f&3].z += o.z; acc[f>>2][f&3].w += o.w;
        }
#pragma unroll
        for (int i = 0; i < 4; i++) {
            int row0 = m0 + wm + i*16 + r4;
#pragma unroll
            for (int j = 0; j < 4; j++) {
                int col = n0 + wn + j*8 + 2*c4;
                float2 v0 = make_float2(alpha*acc[i][j].x, alpha*acc[i][j].y);
                float2 v1 = make_float2(alpha*acc[i][j].z, alpha*acc[i][j].w);
                if (Cb) {
                    float2 c0 = *reinterpret_cast<const float2*>(Cb + (size_t)row0*MM + col);
                    float2 c1 = *reinterpret_cast<const float2*>(Cb + (size_t)(row0+8)*MM + col);
                    v0.x += beta*c0.x; v0.y += beta*c0.y;
                    v1.x += beta*c1.x; v1.y += beta*c1.y;
                }
                *reinterpret_cast<float2*>(Ob + (size_t)row0*MM + col) = v0;
                *reinterpret_cast<float2*>(Ob + (size_t)(row0+8)*MM + col) = v1;
            }
        }
    }
}

// ---------------- NN GEMM (small, for Y = inv @ RV) --------------------------
__global__ void __launch_bounds__(256) gemm_nn_kernel(
    const float* __restrict__ A, const float* __restrict__ B,
    float* __restrict__ Out, int Ma, int Nb, int Kd)
{
    __shared__ float As[64][65];
    __shared__ float Bs[64][65];
    int bh = blockIdx.z;
    int n0 = blockIdx.x * 64;
    int m0 = blockIdx.y * 64;
    const float* Ab = A + (size_t)bh*Ma*Kd;
    const float* Bb = B + (size_t)bh*Kd*Nb;
    float*       Ob = Out + (size_t)bh*Ma*Nb;
    int tid = threadIdx.x;
    int tx4 = (tid & 15) * 4, ty4 = (tid >> 4) * 4;
    float acc[4][4] = {};
    for (int k0 = 0; k0 < Kd; k0 += 64) {
        for (int l = tid; l < 64*16; l += 256) {
            int row = l >> 4, c4 = (l & 15) * 4;
            float4 va = *reinterpret_cast<const float4*>(Ab + (size_t)(m0+row)*Kd + k0 + c4);
            As[row][c4+0]=va.x; As[row][c4+1]=va.y; As[row][c4+2]=va.z; As[row][c4+3]=va.w;
            float4 vb = *reinterpret_cast<const float4*>(Bb + (size_t)(k0+row)*Nb + n0 + c4);
            Bs[row][c4+0]=vb.x; Bs[row][c4+1]=vb.y; Bs[row][c4+2]=vb.z; Bs[row][c4+3]=vb.w;
        }
        __syncthreads();
#pragma unroll 16
        for (int kk = 0; kk < 64; kk++) {
            float a0=As[ty4+0][kk], a1=As[ty4+1][kk], a2=As[ty4+2][kk], a3=As[ty4+3][kk];
            float b0=Bs[kk][tx4+0], b1=Bs[kk][tx4+1], b2=Bs[kk][tx4+2], b3=Bs[kk][tx4+3];
            acc[0][0]+=a0*b0; acc[0][1]+=a0*b1; acc[0][2]+=a0*b2; acc[0][3]+=a0*b3;
            acc[1][0]+=a1*b0; acc[1][1]+=a1*b1; acc[1][2]+=a1*b2; acc[1][3]+=a1*b3;
            acc[2][0]+=a2*b0; acc[2][1]+=a2*b1; acc[2][2]+=a2*b2; acc[2][3]+=a2*b3;
            acc[3][0]+=a3*b0; acc[3][1]+=a3*b1; acc[3][2]+=a3*b2; acc[3][3]+=a3*b3;
        }
        __syncthreads();
    }
#pragma unroll
    for (int i = 0; i < 4; i++) {
        size_t off = (size_t)(m0+ty4+i)*Nb + n0 + tx4;
        *reinterpret_cast<float4*>(Ob + off) =
            make_float4(acc[i][0], acc[i][1], acc[i][2], acc[i][3]);
    }
}

// ---------------- row softmax (in place), one block per row ------------------
__global__ void softmax_rows_kernel(float* __restrict__ data, int cols)
{
    extern __shared__ float buf[];
    __shared__ float red[256];
    size_t row = blockIdx.x;
    float* d = data + row * (size_t)cols;
    int tid = threadIdx.x;
    float mx = -FLT_MAX;
    for (int c = tid; c < cols; c += 256) { float v = d[c]; buf[c] = v; mx = fmaxf(mx, v); }
    red[tid] = mx; __syncthreads();
    for (int st = 128; st > 0; st >>= 1) { if (tid < st) red[tid] = fmaxf(red[tid], red[tid+st]); __syncthreads(); }
    mx = red[0];
    __syncthreads();
    float s = 0.f;
    for (int c = tid; c < cols; c += 256) { float e = __expf(buf[c] - mx); buf[c] = e; s += e; }
    red[tid] = s; __syncthreads();
    for (int st = 128; st > 0; st >>= 1) { if (tid < st) red[tid] += red[tid+st]; __syncthreads(); }
    float inv = 1.0f / red[0];
    for (int c = tid; c < cols; c += 256) d[c] = buf[c] * inv;
}

// ---------------- V0 = u^T / max_j(colsum_j(u)) ------------------------------
__global__ void __launch_bounds__(256) v0init_kernel(const float* __restrict__ U, float* __restrict__ V0)
{
    __shared__ float red[256];
    int bh = blockIdx.x;
    const float* u = U  + (size_t)bh*MM*MM;
    float*       v = V0 + (size_t)bh*MM*MM;
    int j = threadIdx.x;
    float s = 0.f;
    for (int i = 0; i < MM; i++) s += u[(size_t)i*MM + j];
    red[j] = s; __syncthreads();
    for (int st = 128; st > 0; st >>= 1) { if (j < st) red[j] = fmaxf(red[j], red[j+st]); __syncthreads(); }
    float scale = 1.0f / red[0];
    for (int q = 0; q < MM; q++) v[(size_t)j*MM + q] = scale * u[(size_t)q*MM + j];
}

// ---------------- flash RV: partial softmax(nr @ K^T) @ V over KV splits -----
__global__ void __launch_bounds__(256) rv_flash_kernel(
    const float* __restrict__ NR, const float* __restrict__ K,
    const float* __restrict__ V, float* __restrict__ P, float* __restrict__ ML)
{
    extern __shared__ float sm[];
    float (*Nrs)[68] = reinterpret_cast<float(*)[68]>(sm);
    float (*Ksk)[68] = reinterpret_cast<float(*)[68]>(sm + 128*68);
    float (*Vs)[68]  = reinterpret_cast<float(*)[68]>(sm + 128*68 + 64*68);
    float (*Ps)[68]  = reinterpret_cast<float(*)[68]>(sm + 128*68 + 2*64*68);
    int s  = blockIdx.x;
    int m0 = blockIdx.y * 128;
    int bh = blockIdx.z;
    const float* Nb = NR + (size_t)bh*MM*DD;
    const float* Kb = K  + (size_t)bh*NN*DD;
    const float* Vb = V  + (size_t)bh*NN*DD;
    int tid = threadIdx.x;
    int ry = (tid >> 4) * 8;
    int cx = (tid & 15) * 4;

#pragma unroll
    for (int i = 0; i < 8; i++) {
        int idx = tid + i*256;
        int row = idx >> 4, q4 = (idx & 15) * 4;
        *reinterpret_cast<float4*>(&Nrs[row][q4]) =
            *reinterpret_cast<const float4*>(Nb + (size_t)(m0+row)*DD + q4);
    }

    float m_i[8], l_i[8];
    float O[8][4] = {};
#pragma unroll
    for (int i = 0; i < 8; i++) { m_i[i] = -FLT_MAX; l_i[i] = 0.f; }

    for (int kc = 0; kc < 8; kc++) {
        int k0 = s*512 + kc*64;
        __syncthreads();
#pragma unroll
        for (int i = 0; i < 4; i++) {
            int idx = tid + i*256;
            int c  = idx & 63;
            int kq = (idx >> 6) * 4;
            float4 v = *reinterpret_cast<const float4*>(Kb + (size_t)(k0+c)*DD + kq);
            Ksk[kq+0][c]=v.x; Ksk[kq+1][c]=v.y; Ksk[kq+2][c]=v.z; Ksk[kq+3][c]=v.w;
        }
#pragma unroll
        for (int i = 0; i < 4; i++) {
            int idx = tid + i*256;
            int row = idx >> 4, q4 = (idx & 15) * 4;
            *reinterpret_cast<float4*>(&Vs[row][q4]) =
                *reinterpret_cast<const float4*>(Vb + (size_t)(k0+row)*DD + q4);
        }
        __syncthreads();

        float sv[8][4] = {};
#pragma unroll 8
        for (int kk = 0; kk < 64; kk++) {
            float b[4];
            *reinterpret_cast<float4*>(&b[0]) = *reinterpret_cast<float4*>(&Ksk[kk][cx]);
            float a[8];
#pragma unroll
            for (int i = 0; i < 8; i++) a[i] = Nrs[ry+i][kk];
#pragma unroll
            for (int i = 0; i < 8; i++)
#pragma unroll
                for (int j = 0; j < 4; j++) sv[i][j] += a[i]*b[j];
        }

#pragma unroll
        for (int i = 0; i < 8; i++) {
            float mc = fmaxf(fmaxf(sv[i][0], sv[i][1]), fmaxf(sv[i][2], sv[i][3]));
#pragma unroll
            for (int o = 8; o > 0; o >>= 1) mc = fmaxf(mc, __shfl_xor_sync(0xffffffffu, mc, o));
            float mn = fmaxf(m_i[i], mc);
            float corr = __expf(m_i[i] - mn);
            l_i[i] *= corr;
#pragma unroll
            for (int j = 0; j < 4; j++) O[i][j] *= corr;
            float ls = 0.f;
#pragma unroll
            for (int j = 0; j < 4; j++) {
                float p = __expf(sv[i][j] - mn);
                Ps[ry+i][cx+j] = p;
                ls += p;
            }
#pragma unroll
            for (int o = 8; o > 0; o >>= 1) ls += __shfl_xor_sync(0xffffffffu, ls, o);
            l_i[i] += ls;
            m_i[i] = mn;
        }
        __syncthreads();

#pragma unroll 8
        for (int kk = 0; kk < 64; kk++) {
            float b[4];
            *reinterpret_cast<float4*>(&b[0]) = *reinterpret_cast<float4*>(&Vs[kk][cx]);
            float a[8];
#pragma unroll
            for (int i = 0; i < 8; i++) a[i] = Ps[ry+i][kk];
#pragma unroll
            for (int i = 0; i < 8; i++)
#pragma unroll
                for (int j = 0; j < 4; j++) O[i][j] += a[i]*b[j];
        }
    }

    float* Pb = P + ((size_t)s*BH + bh)*MM*DD;
#pragma unroll
    for (int i = 0; i < 8; i++)
        *reinterpret_cast<float4*>(Pb + (size_t)(m0+ry+i)*DD + cx) =
            make_float4(O[i][0], O[i][1], O[i][2], O[i][3]);
    if ((tid & 15) == 0) {
        float* mlb = ML + (((size_t)s*BH + bh)*MM + m0)*2;
#pragma unroll
        for (int i = 0; i < 8; i++) {
            mlb[(ry+i)*2 + 0] = m_i[i];
            mlb[(ry+i)*2 + 1] = l_i[i];
        }
    }
}

__global__ void rv_combine_kernel(const float* __restrict__ P, const float* __restrict__ ML,
                                  float* __restrict__ RV)
{
    int gt = blockIdx.x * 256 + threadIdx.x;
    int row = gt >> 4;
    int c4  = (gt & 15) * 4;
    float m_s[8], l_s[8];
    float gm = -FLT_MAX;
#pragma unroll
    for (int s = 0; s < 8; s++) {
        m_s[s] = ML[(((size_t)s*BH*MM) + row)*2 + 0];
        l_s[s] = ML[(((size_t)s*BH*MM) + row)*2 + 1];
        gm = fmaxf(gm, m_s[s]);
    }
    float L = 0.f;
    float4 acc = make_float4(0.f,0.f,0.f,0.f);
#pragma unroll
    for (int s = 0; s < 8; s++) {
        float w = __expf(m_s[s] - gm);
        L += w * l_s[s];
        float4 o = *reinterpret_cast<const float4*>(P + ((size_t)s*BH*MM + row)*DD + c4);
        acc.x += w*o.x; acc.y += w*o.y; acc.z += w*o.z; acc.w += w*o.w;
    }
    float inv = 1.0f / L;
    *reinterpret_cast<float4*>(RV + (size_t)row*DD + c4) =
        make_float4(acc.x*inv, acc.y*inv, acc.z*inv, acc.w*inv);
}

// ---------------- fused final (fp32): X = softmax(Qs@nc^T) @ Y ---------------
// 128-row chunks starting at qbase. Proven R12 body.
#define FX_LPAD 260
__global__ void __launch_bounds__(256) fusedx_kernel(
    const float* __restrict__ Q, const float* __restrict__ nc,
    const float* __restrict__ Y, float* __restrict__ X, int qbase)
{
    extern __shared__ float sm[];
    float (*As)[132] = reinterpret_cast<float(*)[132]>(sm);
    float (*Bs)[132] = reinterpret_cast<float(*)[132]>(sm + 64*132);
    float (*Ys)[68]  = reinterpret_cast<float(*)[68]> (sm + 64*132);
    float (*L)[FX_LPAD] = reinterpret_cast<float(*)[FX_LPAD]>(sm + 2*64*132);
    int bh = blockIdx.y;
    int q0 = qbase + blockIdx.x * 128;
    int tid = threadIdx.x;
    const float* Qb  = Q  + (size_t)bh*NN*DD;
    const float* ncb = nc + (size_t)bh*MM*DD;
    const float* Yb  = Y  + (size_t)bh*MM*DD;

#pragma unroll
    for (int i = 0; i < 8; i++) {
        int idx = tid + i*256;
        int row = idx & 127;
        int c4  = (idx >> 7) * 4;
        float4 v = *reinterpret_cast<const float4*>(Qb + (size_t)(q0+row)*DD + c4);
        As[c4+0][row]=v.x*0.125f; As[c4+1][row]=v.y*0.125f;
        As[c4+2][row]=v.z*0.125f; As[c4+3][row]=v.w*0.125f;
    }

    int tx8 = (tid & 15) * 8, ty8 = (tid >> 4) * 8;
    for (int cc = 0; cc < 2; cc++) {
        __syncthreads();
#pragma unroll
        for (int i = 0; i < 8; i++) {
            int idx = tid + i*256;
            int row = idx & 127;
            int c4  = (idx >> 7) * 4;
            float4 v = *reinterpret_cast<const float4*>(ncb + (size_t)(cc*128+row)*DD + c4);
            Bs[c4+0][row]=v.x; Bs[c4+1][row]=v.y; Bs[c4+2][row]=v.z; Bs[c4+3][row]=v.w;
        }
        __syncthreads();
        float acc[8][8] = {};
#pragma unroll 8
        for (int kk = 0; kk < 64; kk++) {
            float a[8], b[8];
            *reinterpret_cast<float4*>(&a[0]) = *reinterpret_cast<float4*>(&As[kk][ty8]);
            *reinterpret_cast<float4*>(&a[4]) = *reinterpret_cast<float4*>(&As[kk][ty8+4]);
            *reinterpret_cast<float4*>(&b[0]) = *reinterpret_cast<float4*>(&Bs[kk][tx8]);
            *reinterpret_cast<float4*>(&b[4]) = *reinterpret_cast<float4*>(&Bs[kk][tx8+4]);
#pragma unroll
            for (int i = 0; i < 8; i++)
#pragma unroll
                for (int j = 0; j < 8; j++) acc[i][j] += a[i]*b[j];
        }
#pragma unroll
        for (int i = 0; i < 8; i++) {
            *reinterpret_cast<float4*>(&L[ty8+i][cc*128+tx8]) =
                make_float4(acc[i][0],acc[i][1],acc[i][2],acc[i][3]);
            *reinterpret_cast<float4*>(&L[ty8+i][cc*128+tx8+4]) =
                make_float4(acc[i][4],acc[i][5],acc[i][6],acc[i][7]);
        }
    }
    __syncthreads();

    int wid = tid >> 5, lane = tid & 31;
    for (int r = wid; r < 128; r += 8) {
        float v[8]; float mx = -FLT_MAX;
#pragma unroll
        for (int t = 0; t < 8; t++) { v[t] = L[r][lane + 32*t]; mx = fmaxf(mx, v[t]); }
#pragma unroll
        for (int o = 16; o > 0; o >>= 1) mx = fmaxf(mx, __shfl_xor_sync(0xffffffffu, mx, o));
        float s = 0.f;
#pragma unroll
        for (int t = 0; t < 8; t++) { v[t] = __expf(v[t] - mx); s += v[t]; }
#pragma unroll
        for (int o = 16; o > 0; o >>= 1) s += __shfl_xor_sync(0xffffffffu, s, o);
        float inv = 1.0f / s;
#pragma unroll
        for (int t = 0; t < 8; t++) L[r][lane + 32*t] = v[t] * inv;
    }

    int ry = (tid >> 4) * 8;
    int cx = (tid & 15) * 4;
    float acc3[8][4] = {};
    for (int kc = 0; kc < 4; kc++) {
        __syncthreads();
#pragma unroll
        for (int i = 0; i < 4; i++) {
            int idx = tid + i*256;
            int row = idx >> 4, c4 = (idx & 15) * 4;
            *reinterpret_cast<float4*>(&Ys[row][c4]) =
                *reinterpret_cast<const float4*>(Yb + (size_t)(kc*64+row)*DD + c4);
        }
        __syncthreads();
#pragma unroll 8
        for (int kk = 0; kk < 64; kk++) {
            float b[4];
            *reinterpret_cast<float4*>(&b[0]) = *reinterpret_cast<float4*>(&Ys[kk][cx]);
            float a[8];
#pragma unroll
            for (int i = 0; i < 8; i++) a[i] = L[ry+i][kc*64+kk];
#pragma unroll
            for (int i = 0; i < 8; i++)
#pragma unroll
                for (int j = 0; j < 4; j++) acc3[i][j] += a[i]*b[j];
        }
    }
#pragma unroll
    for (int i = 0; i < 8; i++)
        *reinterpret_cast<float4*>(X + ((size_t)bh*NN + q0 + ry + i)*DD + cx) =
            make_float4(acc3[i][0], acc3[i][1], acc3[i][2], acc3[i][3]);
}

// ---------------- fused final (3xTF32): X = softmax(Qs@nc^T) @ Y -------------
// 64-row chunks starting at qbase. Proven R6 body (tensor pipe).
#define FXL 260
#define FX_QH_BYTES (64*68*8)
#define FX_BH_BYTES (64*132*8)
#define FX_L_BYTES  (64*FXL*4)
__global__ void __launch_bounds__(256) fusedx3_kernel(
    const float* __restrict__ Q, const float* __restrict__ nc,
    const float* __restrict__ Y, float* __restrict__ X, int qbase)
{
    extern __shared__ char smc[];
    uint2 (*Qh)[68]  = reinterpret_cast<uint2(*)[68]> (smc);
    uint2 (*Bh)[132] = reinterpret_cast<uint2(*)[132]>(smc + FX_QH_BYTES);
    uint2 (*Ys)[68]  = reinterpret_cast<uint2(*)[68]> (smc + FX_QH_BYTES);
    float (*L)[FXL]  = reinterpret_cast<float(*)[FXL]>(smc + FX_QH_BYTES + FX_BH_BYTES);
    int bh = blockIdx.y;
    int q0 = qbase + blockIdx.x * 64;
    int tid = threadIdx.x, lane = tid & 31, wid = tid >> 5;
    int r4 = lane >> 2, c4 = lane & 3;
    const float* Qb  = Q  + (size_t)bh*NN*DD;
    const float* ncb = nc + (size_t)bh*MM*DD;
    const float* Yb  = Y  + (size_t)bh*MM*DD;

#pragma unroll
    for (int i = 0; i < 4; i++) {
        int idx = tid + i*256;
        int m  = idx & 63;
        int kq = (idx >> 6) * 4;
        float4 v = *reinterpret_cast<const float4*>(Qb + (size_t)(q0+m)*DD + kq);
        Qh[kq+0][m] = split_tf32(v.x*0.125f);
        Qh[kq+1][m] = split_tf32(v.y*0.125f);
        Qh[kq+2][m] = split_tf32(v.z*0.125f);
        Qh[kq+3][m] = split_tf32(v.w*0.125f);
    }

    int wm = (wid & 1) * 32;
    int wn = (wid >> 1) * 32;
    for (int cc = 0; cc < 2; cc++) {
        __syncthreads();
#pragma unroll
        for (int i = 0; i < 8; i++) {
            int idx = tid + i*256;
            int n  = idx & 127;
            int kq = (idx >> 7) * 4;
            float4 v = *reinterpret_cast<const float4*>(ncb + (size_t)(cc*128+n)*DD + kq);
            Bh[kq+0][n] = split_tf32(v.x);
            Bh[kq+1][n] = split_tf32(v.y);
            Bh[kq+2][n] = split_tf32(v.z);
            Bh[kq+3][n] = split_tf32(v.w);
        }
        __syncthreads();
        float4 acc[2][4];
#pragma unroll
        for (int i = 0; i < 2; i++)
#pragma unroll
            for (int j = 0; j < 4; j++) acc[i][j] = make_float4(0.f,0.f,0.f,0.f);
#pragma unroll
        for (int ks = 0; ks < 8; ks++) {
            int k0 = ks*8;
            uint2 a2[2][4], b2[4][2];
#pragma unroll
            for (int i = 0; i < 2; i++) {
                int mb = wm + i*16;
                a2[i][0] = Qh[k0+c4  ][mb+r4];
                a2[i][1] = Qh[k0+c4  ][mb+8+r4];
                a2[i][2] = Qh[k0+4+c4][mb+r4];
                a2[i][3] = Qh[k0+4+c4][mb+8+r4];
            }
#pragma unroll
            for (int j = 0; j < 4; j++) {
                int nb = wn + j*8;
                b2[j][0] = Bh[k0+c4  ][nb+r4];
                b2[j][1] = Bh[k0+4+c4][nb+r4];
            }
#pragma unroll
            for (int i = 0; i < 2; i++)
#pragma unroll
                for (int j = 0; j < 4; j++) mma_tf32x3(acc[i][j], a2[i], b2[j]);
        }
#pragma unroll
        for (int i = 0; i < 2; i++) {
            int row = wm + i*16 + r4;
#pragma unroll
            for (int j = 0; j < 4; j++) {
                int col = cc*128 + wn + j*8 + 2*c4;
                *reinterpret_cast<float2*>(&L[row][col])   = make_float2(acc[i][j].x, acc[i][j].y);
                *reinterpret_cast<float2*>(&L[row+8][col]) = make_float2(acc[i][j].z, acc[i][j].w);
            }
        }
    }
    __syncthreads();

    for (int r = wid; r < 64; r += 8) {
        float v[8]; float mx = -FLT_MAX;
#pragma unroll
        for (int t = 0; t < 8; t++) { v[t] = L[r][lane + 32*t]; mx = fmaxf(mx, v[t]); }
#pragma unroll
        for (int o = 16; o > 0; o >>= 1) mx = fmaxf(mx, __shfl_xor_sync(0xffffffffu, mx, o));
        float s = 0.f;
#pragma unroll
        for (int t = 0; t < 8; t++) { v[t] = __expf(v[t] - mx); s += v[t]; }
#pragma unroll
        for (int o = 16; o > 0; o >>= 1) s += __shfl_xor_sync(0xffffffffu, s, o);
        float inv = 1.0f / s;
#pragma unroll
        for (int t = 0; t < 8; t++) L[r][lane + 32*t] = v[t] * inv;
    }

    int wn3 = (wid >> 1) * 16;
    float4 acc3[2][2];
#pragma unroll
    for (int i = 0; i < 2; i++)
#pragma unroll
        for (int j = 0; j < 2; j++) acc3[i][j] = make_float4(0.f,0.f,0.f,0.f);
    for (int kc = 0; kc < 4; kc++) {
        __syncthreads();
#pragma unroll
        for (int i = 0; i < 4; i++) {
            int idx = tid + i*256;
            int row = idx >> 4;
            int cq  = (idx & 15) * 4;
            float4 v = *reinterpret_cast<const float4*>(Yb + (size_t)(kc*64+row)*DD + cq);
            Ys[row][cq+0] = split_tf32(v.x);
            Ys[row][cq+1] = split_tf32(v.y);
            Ys[row][cq+2] = split_tf32(v.z);
            Ys[row][cq+3] = split_tf32(v.w);
        }
        __syncthreads();
#pragma unroll
        for (int ks = 0; ks < 8; ks++) {
            int k0 = ks*8;
            int kb = kc*64 + k0;
            uint2 a2[2][4], b2[2][2];
#pragma unroll
            for (int i = 0; i < 2; i++) {
                int mb = wm + i*16;
                a2[i][0] = split_tf32(L[mb+r4  ][kb+c4  ]);
                a2[i][1] = split_tf32(L[mb+8+r4][kb+c4  ]);
                a2[i][2] = split_tf32(L[mb+r4  ][kb+4+c4]);
                a2[i][3] = split_tf32(L[mb+8+r4][kb+4+c4]);
            }
#pragma unroll
            for (int j = 0; j < 2; j++) {
                int nb = wn3 + j*8;
                b2[j][0] = Ys[k0+c4  ][nb+r4];
                b2[j][1] = Ys[k0+4+c4][nb+r4];
            }
#pragma unroll
            for (int i = 0; i < 2; i++)
#pragma unroll
                for (int j = 0; j < 2; j++) mma_tf32x3(acc3[i][j], a2[i], b2[j]);
        }
    }
#pragma unroll
    for (int i = 0; i < 2; i++) {
        int row0 = q0 + wm + i*16 + r4;
#pragma unroll
        for (int j = 0; j < 2; j++) {
            int col = wn3 + j*8 + 2*c4;
            *reinterpret_cast<float2*>(X + ((size_t)bh*NN + row0)*DD + col) =
                make_float2(acc3[i][j].x, acc3[i][j].y);
            *reinterpret_cast<float2*>(X + ((size_t)bh*NN + row0+8)*DD + col) =
                make_float2(acc3[i][j].z, acc3[i][j].w);
        }
    }
}

// ---------------- host launch ----------------
extern "C" void kernel_launch(void* const* d_in, const int* in_sizes, int n_in,
                              void* d_out, int out_size)
{
    (void)in_sizes; (void)n_in; (void)out_size;
    const float* Q = (const float*)d_in[0];
    const float* K = (const float*)d_in[1];
    const float* V = (const float*)d_in[2];
    float* X = (float*)d_out;

    static cudaStream_t s2 = nullptr;
    static cudaEvent_t evFork = nullptr, evJoin = nullptr, evY = nullptr, evTail = nullptr;
    static bool attrs_done = false;
    if (!s2) {
        cudaStreamCreateWithFlags(&s2, cudaStreamNonBlocking);
        cudaEventCreateWithFlags(&evFork, cudaEventDisableTiming);
        cudaEventCreateWithFlags(&evJoin, cudaEventDisableTiming);
        cudaEventCreateWithFlags(&evY,    cudaEventDisableTiming);
        cudaEventCreateWithFlags(&evTail, cudaEventDisableTiming);
    }
    const int NT_SMEM  = 2*64*132*sizeof(float);                 // 67.5 KB
    const int NS1_SMEM = 64*136*4 + 64*72*4;                     // 53.2 KB
    const int NS3_SMEM = 64*132*8 + 64*72*8;                     // 104.4 KB
    const int FL_SMEM  = (128*68 + 64*68 + 64*68 + 128*68)*4;    // 104.4 KB
    const int FX_SMEM  = (2*64*132 + 128*FX_LPAD)*sizeof(float); // 200.7 KB
    const int FX3_SMEM = FX_QH_BYTES + FX_BH_BYTES + FX_L_BYTES; // 168.9 KB
    if (!attrs_done) {
        cudaFuncSetAttribute(gemm_nt128_kernel, cudaFuncAttributeMaxDynamicSharedMemorySize, NT_SMEM);
        cudaFuncSetAttribute(ns_fused1_kernel,  cudaFuncAttributeMaxDynamicSharedMemorySize, NS1_SMEM);
        cudaFuncSetAttribute(ns_fused3_kernel,  cudaFuncAttributeMaxDynamicSharedMemorySize, NS3_SMEM);
        cudaFuncSetAttribute(rv_flash_kernel,   cudaFuncAttributeMaxDynamicSharedMemorySize, FL_SMEM);
        cudaFuncSetAttribute(fusedx_kernel,     cudaFuncAttributeMaxDynamicSharedMemorySize, FX_SMEM);
        cudaFuncSetAttribute(fusedx3_kernel,    cudaFuncAttributeMaxDynamicSharedMemorySize, FX3_SMEM);
        attrs_done = true;
    }

    float *nc, *nr, *u, *v0, *v1, *kv, *t1, *t2, *rvp, *ml, *rv, *y;
    int *ik, *iq;
    cudaGetSymbolAddress((void**)&nc, g_nc);
    cudaGetSymbolAddress((void**)&nr, g_nr);
    cudaGetSymbolAddress((void**)&ik, g_idxk);
    cudaGetSymbolAddress((void**)&iq, g_idxq);
    cudaGetSymbolAddress((void**)&u,  g_u);
    cudaGetSymbolAddress((void**)&v0, g_v0);
    cudaGetSymbolAddress((void**)&v1, g_v1);
    cudaGetSymbolAddress((void**)&kv, g_kv);
    cudaGetSymbolAddress((void**)&t1, g_t1);
    cudaGetSymbolAddress((void**)&t2, g_t2);
    cudaGetSymbolAddress((void**)&rvp, g_rvp);
    cudaGetSymbolAddress((void**)&ml, g_ml);
    cudaGetSymbolAddress((void**)&rv, g_rv);
    cudaGetSymbolAddress((void**)&y,  g_y);

    // 1) selection + gather
    topk_kernel<<<32, 1024>>>(Q, K, ik, iq);
    gather_kernel<<<16, dim3(64,4)>>>(Q, K, ik, iq, nc, nr);

    // fork: flash RV pipeline (fp32, FMA pipe) overlaps main-stream tensor work
    cudaEventRecord(evFork, 0);
    cudaStreamWaitEvent(s2, evFork, 0);

    rv_flash_kernel<<<dim3(8, 2, 16), 256, FL_SMEM, s2>>>(nr, K, V, rvp, ml);
    rv_combine_kernel<<<BH*MM*DD/(256*4), 256, 0, s2>>>(rvp, ml, rv);
    cudaEventRecord(evJoin, s2);

    // main: u = softmax(nr @ nc^T); Newton-Schulz inverse (R12 config)
    gemm_nt128_kernel<<<dim3(2, 2, 16), 256, NT_SMEM>>>(nr, nc, u, MM, MM);
    softmax_rows_kernel<<<BH*MM, 256, MM*sizeof(float)>>>(u, MM);
    v0init_kernel<<<16, 256>>>(u, v0);

    const dim3 NSG(4, 2, 16);   // 128 blocks -- dependent chain needs a full wave
    float* vin = v0; float* vout = v1;
    for (int it = 0; it < 4; it++) {
        if (it < 3) {
            ns_fused1_kernel<<<NSG, 256, NS1_SMEM>>>(u,   vin, nullptr, kv,   1.0f,  0.0f);
            ns_fused1_kernel<<<NSG, 256, NS1_SMEM>>>(kv,  kv,  kv,      t1,  -1.0f,  7.0f);
            ns_fused1_kernel<<<NSG, 256, NS1_SMEM>>>(kv,  t1,  kv,      t2,  -1.0f, 15.0f);
            ns_fused1_kernel<<<NSG, 256, NS1_SMEM>>>(vin, t2,  vin,     vout, -0.25f, 3.25f);
        } else {
            ns_fused3_kernel<<<NSG, 256, NS3_SMEM>>>(u,   vin, nullptr, kv,   1.0f,  0.0f);
            ns_fused3_kernel<<<NSG, 256, NS3_SMEM>>>(kv,  kv,  kv,      t1,  -1.0f,  7.0f);
            ns_fused3_kernel<<<NSG, 256, NS3_SMEM>>>(kv,  t1,  kv,      t2,  -1.0f, 15.0f);
            ns_fused3_kernel<<<NSG, 256, NS3_SMEM>>>(vin, t2,  vin,     vout, -0.25f, 3.25f);
        }
        float* tmp = vin; vin = vout; vout = tmp;
    }

    // join: need rv before Y
    cudaStreamWaitEvent(0, evJoin, 0);

    // 7) Y = V_inv @ RV
    gemm_nn_kernel<<<dim3(1,4,16), 256>>>(vin, rv, y, MM, DD, MM);

    // 8) final tail split across both pipes:
    //    q < 2048  -> fp32 fusedx (FMA pipe, main stream)
    //    q >= 2048 -> 3xTF32 fusedx3 (tensor pipe, s2), concurrent
    cudaEventRecord(evY, 0);
    cudaStreamWaitEvent(s2, evY, 0);
    fusedx3_kernel<<<dim3(32, BH), 256, FX3_SMEM, s2>>>(Q, nc, y, X, 2048);
    cudaEventRecord(evTail, s2);
    fusedx_kernel<<<dim3(16, BH), 256, FX_SMEM>>>(Q, nc, y, X, 0);
    cudaStreamWaitEvent(0, evTail, 0);
}

// round 15
// speedup vs baseline: 1.1781x; 1.0398x over previous
#include <cuda_runtime.h>
#include <float.h>
#include <stdint.h>

#define BH 16
#define HH 8
#define NN 4096
#define DD 64
#define MM 256

// ---------------- scratch (__device__ globals; no allocation) ----------------
__device__ float g_nc [BH*MM*DD];
__device__ float g_nr [BH*MM*DD];
__device__ int   g_idxk[BH*MM];
__device__ int   g_idxq[BH*MM];
__device__ float g_u  [BH*MM*MM];
__device__ float g_v0 [BH*MM*MM];
__device__ float g_v1 [BH*MM*MM];
__device__ float g_kv [BH*MM*MM];
__device__ float g_t1 [BH*MM*MM];
__device__ float g_t2 [BH*MM*MM];
__device__ float g_rvp[8*BH*MM*DD];          // flash split partials
__device__ float g_ml [8*BH*MM*2];           // flash split (max, sumexp)
__device__ float g_rv [BH*MM*DD];
__device__ float g_y  [BH*MM*DD];

// ---------------- tf32 mma helpers ----------------
__device__ __forceinline__ uint32_t f2tf(float v) {
    uint32_t r; asm("cvt.rna.tf32.f32 %0, %1;" : "=r"(r) : "f"(v)); return r;
}
__device__ __forceinline__ void mma_tf32(float4& d, const uint32_t* a, const uint32_t* b) {
    asm volatile("mma.sync.aligned.m16n8k8.row.col.f32.tf32.tf32.f32 "
        "{%0,%1,%2,%3}, {%4,%5,%6,%7}, {%8,%9}, {%0,%1,%2,%3};"
        : "+f"(d.x), "+f"(d.y), "+f"(d.z), "+f"(d.w)
        : "r"(a[0]), "r"(a[1]), "r"(a[2]), "r"(a[3]), "r"(b[0]), "r"(b[1]));
}
__device__ __forceinline__ uint2 split_tf32(float x) {
    uint32_t hi = f2tf(x);
    float lo = x - __uint_as_float(hi);
    return make_uint2(hi, f2tf(lo));
}
// 3xTF32: d += a_hi*b_hi + a_lo*b_hi + a_hi*b_lo (fp32-grade)
__device__ __forceinline__ void mma_tf32x3(float4& d, const uint2* a, const uint2* b) {
    uint32_t ah[4] = {a[0].x, a[1].x, a[2].x, a[3].x};
    uint32_t al[4] = {a[0].y, a[1].y, a[2].y, a[3].y};
    uint32_t bh_[2] = {b[0].x, b[1].x};
    uint32_t bl_[2] = {b[0].y, b[1].y};
    mma_tf32(d, ah, bh_);
    mma_tf32(d, al, bh_);
    mma_tf32(d, ah, bl_);
}

// ---------------- top-k: exact bitonic sort of (sum,row) keys ----------------
__global__ void __launch_bounds__(1024) topk_kernel(
    const float* __restrict__ Q, const float* __restrict__ K,
    int* __restrict__ idxk, int* __restrict__ idxq)
{
    __shared__ unsigned long long keys[NN];
    int bh  = blockIdx.x >> 1;
    int isQ = blockIdx.x & 1;
    const float* src = isQ ? Q : K;
    int tid = threadIdx.x;

    for (int r = tid; r < NN; r += 1024) {
        const float4* p = reinterpret_cast<const float4*>(src + ((size_t)bh*NN + r)*DD);
        float s = 0.f;
#pragma unroll
        for (int t = 0; t < DD/4; t++) { float4 v = p[t]; s += v.x + v.y + v.z + v.w; }
        unsigned int u = __float_as_uint(s);
        unsigned int m = (u & 0x80000000u) ? ~u : (u | 0x80000000u);
        keys[r] = ((unsigned long long)(~m) << 32) | (unsigned int)r;
    }
    __syncthreads();

    for (int k = 2; k <= NN; k <<= 1) {
        for (int j = k >> 1; j > 0; j >>= 1) {
            for (int i = tid; i < NN; i += 1024) {
                int ixj = i ^ j;
                if (ixj > i) {
                    bool up = ((i & k) == 0);
                    unsigned long long a = keys[i], c = keys[ixj];
                    if ((a > c) == up) { keys[i] = c; keys[ixj] = a; }
                }
            }
            __syncthreads();
        }
    }
    int* dst = isQ ? idxq : idxk;
    if (tid < MM) dst[bh*MM + tid] = (int)(keys[tid] & 0xFFFFFFFFu);
}

// ---------------- gather nc = K[idx_k], nr = Q[idx_q]/8 ----------------
__global__ void gather_kernel(const float* __restrict__ Q, const float* __restrict__ K,
                              const int* __restrict__ idxk, const int* __restrict__ idxq,
                              float* __restrict__ nc, float* __restrict__ nr)
{
    int bh = blockIdx.x;
    int tx = threadIdx.x;
    int ty = threadIdx.y;
    for (int i = ty; i < MM; i += 4) {
        int ik = idxk[bh*MM + i];
        int iq = idxq[bh*MM + i];
        nc[((size_t)bh*MM + i)*DD + tx] = K[((size_t)bh*NN + ik)*DD + tx];
        nr[((size_t)bh*MM + i)*DD + tx] = Q[((size_t)bh*NN + iq)*DD + tx] * 0.125f;
    }
}

// ---------------- NT GEMM (K=64): 128x128 tile, 8x8 micro (fp32) -------------
__global__ void __launch_bounds__(256) gemm_nt128_kernel(
    const float* __restrict__ A, const float* __restrict__ B, float* __restrict__ C,
    int Ma, int Nb)
{
    extern __shared__ float sm[];
    float (*As)[132] = reinterpret_cast<float(*)[132]>(sm);
    float (*Bs)[132] = reinterpret_cast<float(*)[132]>(sm + 64*132);
    int bh = blockIdx.z;
    int m0 = blockIdx.y * 128;
    int n0 = blockIdx.x * 128;
    const float* Ab = A + (size_t)bh*Ma*64;
    const float* Bb = B + (size_t)bh*Nb*64;
    float*       Cb = C + (size_t)bh*Ma*Nb;
    int tid = threadIdx.x;
#pragma unroll
    for (int i = 0; i < 8; i++) {
        int idx = tid + i*256;
        int row = idx & 127;
        int c4  = (idx >> 7) * 4;
        float4 v = *reinterpret_cast<const float4*>(Ab + (size_t)(m0+row)*64 + c4);
        As[c4+0][row]=v.x; As[c4+1][row]=v.y; As[c4+2][row]=v.z; As[c4+3][row]=v.w;
        float4 w = *reinterpret_cast<const float4*>(Bb + (size_t)(n0+row)*64 + c4);
        Bs[c4+0][row]=w.x; Bs[c4+1][row]=w.y; Bs[c4+2][row]=w.z; Bs[c4+3][row]=w.w;
    }
    __syncthreads();
    int tx8 = (tid & 15) * 8, ty8 = (tid >> 4) * 8;
    float acc[8][8] = {};
#pragma unroll 8
    for (int kk = 0; kk < 64; kk++) {
        float a[8], b[8];
        *reinterpret_cast<float4*>(&a[0]) = *reinterpret_cast<float4*>(&As[kk][ty8]);
        *reinterpret_cast<float4*>(&a[4]) = *reinterpret_cast<float4*>(&As[kk][ty8+4]);
        *reinterpret_cast<float4*>(&b[0]) = *reinterpret_cast<float4*>(&Bs[kk][tx8]);
        *reinterpret_cast<float4*>(&b[4]) = *reinterpret_cast<float4*>(&Bs[kk][tx8+4]);
#pragma unroll
        for (int i = 0; i < 8; i++)
#pragma unroll
            for (int j = 0; j < 8; j++) acc[i][j] += a[i]*b[j];
    }
#pragma unroll
    for (int i = 0; i < 8; i++) {
        *reinterpret_cast<float4*>(Cb + (size_t)(m0+ty8+i)*Nb + n0+tx8) =
            make_float4(acc[i][0],acc[i][1],acc[i][2],acc[i][3]);
        *reinterpret_cast<float4*>(Cb + (size_t)(m0+ty8+i)*Nb + n0+tx8+4) =
            make_float4(acc[i][4],acc[i][5],acc[i][6],acc[i][7]);
    }
}

// ---------------- NS fused GEMM (single tf32, full K, fused epilogue) --------
// Out = alpha*(A@B) + beta*Cadd. Proven R8/R10/R11/R12. grid (4, 2, 16).
// PDL-aware: waits for the upstream grid before the first dependent read.
__global__ void __launch_bounds__(256) ns_fused1_kernel(
    const float* __restrict__ A, const float* __restrict__ B,
    const float* __restrict__ Cadd, float* __restrict__ Out,
    float alpha, float beta)
{
    extern __shared__ char smc[];
    uint32_t (*As)[136] = reinterpret_cast<uint32_t(*)[136]>(smc);
    uint32_t (*Bs)[72]  = reinterpret_cast<uint32_t(*)[72]> (smc + 64*136*4);
    int bh = blockIdx.z;
    int n0 = blockIdx.x * 64;
    int m0 = blockIdx.y * 128;
    const float* Ab = A + (size_t)bh*MM*MM;
    const float* Bb = B + (size_t)bh*MM*MM;
    float*       Ob = Out + (size_t)bh*MM*MM;
    int tid = threadIdx.x, lane = tid & 31, wid = tid >> 5;
    int r4 = lane >> 2, c4 = lane & 3;
    int wm = (wid & 1) * 64;
    int wn = ((wid >> 1) & 1) * 32;
    int kg = wid >> 2;
    int kb = kg * 32;

    float4 acc[4][4];
#pragma unroll
    for (int i = 0; i < 4; i++)
#pragma unroll
        for (int j = 0; j < 4; j++) acc[i][j] = make_float4(0.f,0.f,0.f,0.f);

    cudaGridDependencySynchronize();   // PDL: upstream writes visible past here

    for (int sc = 0; sc < 4; sc++) {
        int k0g = sc * 64;
        if (sc) __syncthreads();
#pragma unroll
        for (int i = 0; i < 8; i++) {
            int idx = tid + i*256;
            int row = idx & 127;
            int kq  = (idx >> 7) * 4;
            float4 v = *reinterpret_cast<const float4*>(Ab + (size_t)(m0+row)*MM + k0g + kq);
            As[kq+0][row]=f2tf(v.x); As[kq+1][row]=f2tf(v.y);
            As[kq+2][row]=f2tf(v.z); As[kq+3][row]=f2tf(v.w);
        }
#pragma unroll
        for (int i = 0; i < 4; i++) {
            int idx = tid + i*256;
            int row = idx >> 4;
            int cq  = (idx & 15) * 4;
            float4 v = *reinterpret_cast<const float4*>(Bb + (size_t)(k0g+row)*MM + n0 + cq);
            Bs[row][cq+0]=f2tf(v.x); Bs[row][cq+1]=f2tf(v.y);
            Bs[row][cq+2]=f2tf(v.z); Bs[row][cq+3]=f2tf(v.w);
        }
        __syncthreads();
#pragma unroll
        for (int ks = 0; ks < 4; ks++) {
            int k0 = kb + ks*8;
            uint32_t af[4][4], bf[4][2];
#pragma unroll
            for (int i = 0; i < 4; i++) {
                int mb = wm + i*16;
                af[i][0] = As[k0+c4  ][mb+r4];
                af[i][1] = As[k0+c4  ][mb+8+r4];
                af[i][2] = As[k0+4+c4][mb+r4];
                af[i][3] = As[k0+4+c4][mb+8+r4];
            }
#pragma unroll
            for (int j = 0; j < 4; j++) {
                int nb = wn + j*8;
                bf[j][0] = Bs[k0+c4  ][nb+r4];
                bf[j][1] = Bs[k0+4+c4][nb+r4];
            }
#pragma unroll
            for (int i = 0; i < 4; i++)
#pragma unroll
                for (int j = 0; j < 4; j++) mma_tf32(acc[i][j], af[i], bf[j]);
        }
    }

    __syncthreads();
    float4* red = reinterpret_cast<float4*>(smc);
    if (kg == 1) {
        int slot = wid - 4;
#pragma unroll
        for (int f = 0; f < 16; f++)
            red[((size_t)f*4 + slot)*32 + lane] = acc[f>>2][f&3];
    }
    __syncthreads();
    if (kg == 0) {
        const float* Cb = Cadd ? (Cadd + (size_t)bh*MM*MM) : nullptr;
#pragma unroll
        for (int f = 0; f < 16; f++) {
            float4 o = red[((size_t)f*4 + wid)*32 + lane];
            acc[f>>2][f&3].x += o.x; acc[f>>2][f&3].y += o.y;
            acc[f>>2][f&3].z += o.z; acc[f>>2][f&3].w += o.w;
        }
#pragma unroll
        for (int i = 0; i < 4; i++) {
            int row0 = m0 + wm + i*16 + r4;
#pragma unroll
            for (int j = 0; j < 4; j++) {
                int col = n0 + wn + j*8 + 2*c4;
                float2 v0 = make_float2(alpha*acc[i][j].x, alpha*acc[i][j].y);
                float2 v1 = make_float2(alpha*acc[i][j].z, alpha*acc[i][j].w);
                if (Cb) {
                    float2 c0 = *reinterpret_cast<const float2*>(Cb + (size_t)row0*MM + col);
                    float2 c1 = *reinterpret_cast<const float2*>(Cb + (size_t)(row0+8)*MM + col);
                    v0.x += beta*c0.x; v0.y += beta*c0.y;
                    v1.x += beta*c1.x; v1.y += beta*c1.y;
                }
                *reinterpret_cast<float2*>(Ob + (size_t)row0*MM + col) = v0;
                *reinterpret_cast<float2*>(Ob + (size_t)(row0+8)*MM + col) = v1;
            }
        }
    }
}

// ---------------- NS fused GEMM (3xTF32, fp32-grade; iteration 4) ------------
// Proven R12. grid (4, 2, 16). PDL-aware.
__global__ void __launch_bounds__(256) ns_fused3_kernel(
    const float* __restrict__ A, const float* __restrict__ B,
    const float* __restrict__ Cadd, float* __restrict__ Out,
    float alpha, float beta)
{
    extern __shared__ char smc[];
    uint2 (*As2)[132] = reinterpret_cast<uint2(*)[132]>(smc);
    uint2 (*Bs2)[72]  = reinterpret_cast<uint2(*)[72]> (smc + 64*132*8);
    int bh = blockIdx.z;
    int n0 = blockIdx.x * 64;
    int m0 = blockIdx.y * 128;
    const float* Ab = A + (size_t)bh*MM*MM;
    const float* Bb = B + (size_t)bh*MM*MM;
    float*       Ob = Out + (size_t)bh*MM*MM;
    int tid = threadIdx.x, lane = tid & 31, wid = tid >> 5;
    int r4 = lane >> 2, c4 = lane & 3;
    int wm = (wid & 1) * 64;
    int wn = ((wid >> 1) & 1) * 32;
    int kg = wid >> 2;
    int kb = kg * 32;

    float4 acc[4][4];
#pragma unroll
    for (int i = 0; i < 4; i++)
#pragma unroll
        for (int j = 0; j < 4; j++) acc[i][j] = make_float4(0.f,0.f,0.f,0.f);

    cudaGridDependencySynchronize();   // PDL: upstream writes visible past here

    for (int sc = 0; sc < 4; sc++) {
        int k0g = sc * 64;
        if (sc) __syncthreads();
#pragma unroll
        for (int i = 0; i < 8; i++) {
            int idx = tid + i*256;
            int row = idx & 127;
            int kq  = (idx >> 7) * 4;
            float4 v = *reinterpret_cast<const float4*>(Ab + (size_t)(m0+row)*MM + k0g + kq);
            As2[kq+0][row]=split_tf32(v.x); As2[kq+1][row]=split_tf32(v.y);
            As2[kq+2][row]=split_tf32(v.z); As2[kq+3][row]=split_tf32(v.w);
        }
#pragma unroll
        for (int i = 0; i < 4; i++) {
            int idx = tid + i*256;
            int row = idx >> 4;
            int cq  = (idx & 15) * 4;
            float4 v = *reinterpret_cast<const float4*>(Bb + (size_t)(k0g+row)*MM + n0 + cq);
            Bs2[row][cq+0]=split_tf32(v.x); Bs2[row][cq+1]=split_tf32(v.y);
            Bs2[row][cq+2]=split_tf32(v.z); Bs2[row][cq+3]=split_tf32(v.w);
        }
        __syncthreads();
#pragma unroll
        for (int ks = 0; ks < 4; ks++) {
            int k0 = kb + ks*8;
            uint2 a2[4][4], b2[4][2];
#pragma unroll
            for (int i = 0; i < 4; i++) {
                int mb = wm + i*16;
                a2[i][0] = As2[k0+c4  ][mb+r4];
                a2[i][1] = As2[k0+c4  ][mb+8+r4];
                a2[i][2] = As2[k0+4+c4][mb+r4];
                a2[i][3] = As2[k0+4+c4][mb+8+r4];
            }
#pragma unroll
            for (int j = 0; j < 4; j++) {
                int nb = wn + j*8;
                b2[j][0] = Bs2[k0+c4  ][nb+r4];
                b2[j][1] = Bs2[k0+4+c4][nb+r4];
            }
#pragma unroll
            for (int i = 0; i < 4; i++)
#pragma unroll
                for (int j = 0; j < 4; j++) mma_tf32x3(acc[i][j], a2[i], b2[j]);
        }
    }

    __syncthreads();
    float4* red = reinterpret_cast<float4*>(smc);
    if (kg == 1) {
        int slot = wid - 4;
#pragma unroll
        for (int f = 0; f < 16; f++)
            red[((size_t)f*4 + slot)*32 + lane] = acc[f>>2][f&3];
    }
    __syncthreads();
    if (kg == 0) {
        const float* Cb = Cadd ? (Cadd + (size_t)bh*MM*MM) : nullptr;
#pragma unroll
        for (int f = 0; f < 16; f++) {
            float4 o = red[((size_t)f*4 + wid)*32 + lane];
            acc[f>>2][f&3].x += o.x; acc[f>>2][f&3].y += o.y;
            acc[f>>2][f&3].z += o.z; acc[f>>2][f&3].w += o.w;
        }
#pragma unroll
        for (int i = 0; i < 4; i++) {
            int row0 = m0 + wm + i*16 + r4;
#pragma unroll
            for (int j = 0; j < 4; j++) {
                int col = n0 + wn + j*8 + 2*c4;
                float2 v0 = make_float2(alpha*acc[i][j].x, alpha*acc[i][j].y);
                float2 v1 = make_float2(alpha*acc[i][j].z, alpha*acc[i][j].w);
                if (Cb) {
                    float2 c0 = *reinterpret_cast<const float2*>(Cb + (size_t)row0*MM + col);
                    float2 c1 = *reinterpret_cast<const float2*>(Cb + (size_t)(row0+8)*MM + col);
                    v0.x += beta*c0.x; v0.y += beta*c0.y;
                    v1.x += beta*c1.x; v1.y += beta*c1.y;
                }
                *reinterpret_cast<float2*>(Ob + (size_t)row0*MM + col) = v0;
                *reinterpret_cast<float2*>(Ob + (size_t)(row0+8)*MM + col) = v1;
            }
        }
    }
}

// ---------------- NN GEMM (small, for Y = inv @ RV) --------------------------
__global__ void __launch_bounds__(256) gemm_nn_kernel(
    const float* __restrict__ A, const float* __restrict__ B,
    float* __restrict__ Out, int Ma, int Nb, int Kd)
{
    __shared__ float As[64][65];
    __shared__ float Bs[64][65];
    int bh = blockIdx.z;
    int n0 = blockIdx.x * 64;
    int m0 = blockIdx.y * 64;
    const float* Ab = A + (size_t)bh*Ma*Kd;
    const float* Bb = B + (size_t)bh*Kd*Nb;
    float*       Ob = Out + (size_t)bh*Ma*Nb;
    int tid = threadIdx.x;
    int tx4 = (tid & 15) * 4, ty4 = (tid >> 4) * 4;
    float acc[4][4] = {};
    for (int k0 = 0; k0 < Kd; k0 += 64) {
        for (int l = tid; l < 64*16; l += 256) {
            int row = l >> 4, c4 = (l & 15) * 4;
            float4 va = *reinterpret_cast<const float4*>(Ab + (size_t)(m0+row)*Kd + k0 + c4);
            As[row][c4+0]=va.x; As[row][c4+1]=va.y; As[row][c4+2]=va.z; As[row][c4+3]=va.w;
            float4 vb = *reinterpret_cast<const float4*>(Bb + (size_t)(k0+row)*Nb + n0 + c4);
            Bs[row][c4+0]=vb.x; Bs[row][c4+1]=vb.y; Bs[row][c4+2]=vb.z; Bs[row][c4+3]=vb.w;
        }
        __syncthreads();
#pragma unroll 16
        for (int kk = 0; kk < 64; kk++) {
            float a0=As[ty4+0][kk], a1=As[ty4+1][kk], a2=As[ty4+2][kk], a3=As[ty4+3][kk];
            float b0=Bs[kk][tx4+0], b1=Bs[kk][tx4+1], b2=Bs[kk][tx4+2], b3=Bs[kk][tx4+3];
            acc[0][0]+=a0*b0; acc[0][1]+=a0*b1; acc[0][2]+=a0*b2; acc[0][3]+=a0*b3;
            acc[1][0]+=a1*b0; acc[1][1]+=a1*b1; acc[1][2]+=a1*b2; acc[1][3]+=a1*b3;
            acc[2][0]+=a2*b0; acc[2][1]+=a2*b1; acc[2][2]+=a2*b2; acc[2][3]+=a2*b3;
            acc[3][0]+=a3*b0; acc[3][1]+=a3*b1; acc[3][2]+=a3*b2; acc[3][3]+=a3*b3;
        }
        __syncthreads();
    }
#pragma unroll
    for (int i = 0; i < 4; i++) {
        size_t off = (size_t)(m0+ty4+i)*Nb + n0 + tx4;
        *reinterpret_cast<float4*>(Ob + off) =
            make_float4(acc[i][0], acc[i][1], acc[i][2], acc[i][3]);
    }
}

// ---------------- row softmax (in place), one block per row ------------------
__global__ void softmax_rows_kernel(float* __restrict__ data, int cols)
{
    extern __shared__ float buf[];
    __shared__ float red[256];
    size_t row = blockIdx.x;
    float* d = data + row * (size_t)cols;
    int tid = threadIdx.x;
    float mx = -FLT_MAX;
    for (int c = tid; c < cols; c += 256) { float v = d[c]; buf[c] = v; mx = fmaxf(mx, v); }
    red[tid] = mx; __syncthreads();
    for (int st = 128; st > 0; st >>= 1) { if (tid < st) red[tid] = fmaxf(red[tid], red[tid+st]); __syncthreads(); }
    mx = red[0];
    __syncthreads();
    float s = 0.f;
    for (int c = tid; c < cols; c += 256) { float e = __expf(buf[c] - mx); buf[c] = e; s += e; }
    red[tid] = s; __syncthreads();
    for (int st = 128; st > 0; st >>= 1) { if (tid < st) red[tid] += red[tid+st]; __syncthreads(); }
    float inv = 1.0f / red[0];
    for (int c = tid; c < cols; c += 256) d[c] = buf[c] * inv;
}

// ---------------- V0 = u^T / max_j(colsum_j(u)) ------------------------------
__global__ void __launch_bounds__(256) v0init_kernel(const float* __restrict__ U, float* __restrict__ V0)
{
    __shared__ float red[256];
    int bh = blockIdx.x;
    const float* u = U  + (size_t)bh*MM*MM;
    float*       v = V0 + (size_t)bh*MM*MM;
    int j = threadIdx.x;
    float s = 0.f;
    for (int i = 0; i < MM; i++) s += u[(size_t)i*MM + j];
    red[j] = s; __syncthreads();
    for (int st = 128; st > 0; st >>= 1) { if (j < st) red[j] = fmaxf(red[j], red[j+st]); __syncthreads(); }
    float scale = 1.0f / red[0];
    for (int q = 0; q < MM; q++) v[(size_t)j*MM + q] = scale * u[(size_t)q*MM + j];
}

// ---------------- flash RV: partial softmax(nr @ K^T) @ V over KV splits -----
__global__ void __launch_bounds__(256) rv_flash_kernel(
    const float* __restrict__ NR, const float* __restrict__ K,
    const float* __restrict__ V, float* __restrict__ P, float* __restrict__ ML)
{
    extern __shared__ float sm[];
    float (*Nrs)[68] = reinterpret_cast<float(*)[68]>(sm);
    float (*Ksk)[68] = reinterpret_cast<float(*)[68]>(sm + 128*68);
    float (*Vs)[68]  = reinterpret_cast<float(*)[68]>(sm + 128*68 + 64*68);
    float (*Ps)[68]  = reinterpret_cast<float(*)[68]>(sm + 128*68 + 2*64*68);
    int s  = blockIdx.x;
    int m0 = blockIdx.y * 128;
    int bh = blockIdx.z;
    const float* Nb = NR + (size_t)bh*MM*DD;
    const float* Kb = K  + (size_t)bh*NN*DD;
    const float* Vb = V  + (size_t)bh*NN*DD;
    int tid = threadIdx.x;
    int ry = (tid >> 4) * 8;
    int cx = (tid & 15) * 4;

#pragma unroll
    for (int i = 0; i < 8; i++) {
        int idx = tid + i*256;
        int row = idx >> 4, q4 = (idx & 15) * 4;
        *reinterpret_cast<float4*>(&Nrs[row][q4]) =
            *reinterpret_cast<const float4*>(Nb + (size_t)(m0+row)*DD + q4);
    }

    float m_i[8], l_i[8];
    float O[8][4] = {};
#pragma unroll
    for (int i = 0; i < 8; i++) { m_i[i] = -FLT_MAX; l_i[i] = 0.f; }

    for (int kc = 0; kc < 8; kc++) {
        int k0 = s*512 + kc*64;
        __syncthreads();
#pragma unroll
        for (int i = 0; i < 4; i++) {
            int idx = tid + i*256;
            int c  = idx & 63;
            int kq = (idx >> 6) * 4;
            float4 v = *reinterpret_cast<const float4*>(Kb + (size_t)(k0+c)*DD + kq);
            Ksk[kq+0][c]=v.x; Ksk[kq+1][c]=v.y; Ksk[kq+2][c]=v.z; Ksk[kq+3][c]=v.w;
        }
#pragma unroll
        for (int i = 0; i < 4; i++) {
            int idx = tid + i*256;
            int row = idx >> 4, q4 = (idx & 15) * 4;
            *reinterpret_cast<float4*>(&Vs[row][q4]) =
                *reinterpret_cast<const float4*>(Vb + (size_t)(k0+row)*DD + q4);
        }
        __syncthreads();

        float sv[8][4] = {};
#pragma unroll 8
        for (int kk = 0; kk < 64; kk++) {
            float b[4];
            *reinterpret_cast<float4*>(&b[0]) = *reinterpret_cast<float4*>(&Ksk[kk][cx]);
            float a[8];
#pragma unroll
            for (int i = 0; i < 8; i++) a[i] = Nrs[ry+i][kk];
#pragma unroll
            for (int i = 0; i < 8; i++)
#pragma unroll
                for (int j = 0; j < 4; j++) sv[i][j] += a[i]*b[j];
        }

#pragma unroll
        for (int i = 0; i < 8; i++) {
            float mc = fmaxf(fmaxf(sv[i][0], sv[i][1]), fmaxf(sv[i][2], sv[i][3]));
#pragma unroll
            for (int o = 8; o > 0; o >>= 1) mc = fmaxf(mc, __shfl_xor_sync(0xffffffffu, mc, o));
            float mn = fmaxf(m_i[i], mc);
            float corr = __expf(m_i[i] - mn);
            l_i[i] *= corr;
#pragma unroll
            for (int j = 0; j < 4; j++) O[i][j] *= corr;
            float ls = 0.f;
#pragma unroll
            for (int j = 0; j < 4; j++) {
                float p = __expf(sv[i][j] - mn);
                Ps[ry+i][cx+j] = p;
                ls += p;
            }
#pragma unroll
            for (int o = 8; o > 0; o >>= 1) ls += __shfl_xor_sync(0xffffffffu, ls, o);
            l_i[i] += ls;
            m_i[i] = mn;
        }
        __syncthreads();

#pragma unroll 8
        for (int kk = 0; kk < 64; kk++) {
            float b[4];
            *reinterpret_cast<float4*>(&b[0]) = *reinterpret_cast<float4*>(&Vs[kk][cx]);
            float a[8];
#pragma unroll
            for (int i = 0; i < 8; i++) a[i] = Ps[ry+i][kk];
#pragma unroll
            for (int i = 0; i < 8; i++)
#pragma unroll
                for (int j = 0; j < 4; j++) O[i][j] += a[i]*b[j];
        }
    }

    float* Pb = P + ((size_t)s*BH + bh)*MM*DD;
#pragma unroll
    for (int i = 0; i < 8; i++)
        *reinterpret_cast<float4*>(Pb + (size_t)(m0+ry+i)*DD + cx) =
            make_float4(O[i][0], O[i][1], O[i][2], O[i][3]);
    if ((tid & 15) == 0) {
        float* mlb = ML + (((size_t)s*BH + bh)*MM + m0)*2;
#pragma unroll
        for (int i = 0; i < 8; i++) {
            mlb[(ry+i)*2 + 0] = m_i[i];
            mlb[(ry+i)*2 + 1] = l_i[i];
        }
    }
}

__global__ void rv_combine_kernel(const float* __restrict__ P, const float* __restrict__ ML,
                                  float* __restrict__ RV)
{
    int gt = blockIdx.x * 256 + threadIdx.x;
    int row = gt >> 4;
    int c4  = (gt & 15) * 4;
    float m_s[8], l_s[8];
    float gm = -FLT_MAX;
#pragma unroll
    for (int s = 0; s < 8; s++) {
        m_s[s] = ML[(((size_t)s*BH*MM) + row)*2 + 0];
        l_s[s] = ML[(((size_t)s*BH*MM) + row)*2 + 1];
        gm = fmaxf(gm, m_s[s]);
    }
    float L = 0.f;
    float4 acc = make_float4(0.f,0.f,0.f,0.f);
#pragma unroll
    for (int s = 0; s < 8; s++) {
        float w = __expf(m_s[s] - gm);
        L += w * l_s[s];
        float4 o = *reinterpret_cast<const float4*>(P + ((size_t)s*BH*MM + row)*DD + c4);
        acc.x += w*o.x; acc.y += w*o.y; acc.z += w*o.z; acc.w += w*o.w;
    }
    float inv = 1.0f / L;
    *reinterpret_cast<float4*>(RV + (size_t)row*DD + c4) =
        make_float4(acc.x*inv, acc.y*inv, acc.z*inv, acc.w*inv);
}

// ---------------- fused final: X_chunk = softmax(Qs_chunk @ nc^T) @ Y --------
#define FX_LPAD 260
__global__ void __launch_bounds__(256) fusedx_kernel(
    const float* __restrict__ Q, const float* __restrict__ nc,
    const float* __restrict__ Y, float* __restrict__ X)
{
    extern __shared__ float sm[];
    float (*As)[132] = reinterpret_cast<float(*)[132]>(sm);
    float (*Bs)[132] = reinterpret_cast<float(*)[132]>(sm + 64*132);
    float (*Ys)[68]  = reinterpret_cast<float(*)[68]> (sm + 64*132);
    float (*L)[FX_LPAD] = reinterpret_cast<float(*)[FX_LPAD]>(sm + 2*64*132);
    int bh = blockIdx.y;
    int q0 = blockIdx.x * 128;
    int tid = threadIdx.x;
    const float* Qb  = Q  + (size_t)bh*NN*DD;
    const float* ncb = nc + (size_t)bh*MM*DD;
    const float* Yb  = Y  + (size_t)bh*MM*DD;

#pragma unroll
    for (int i = 0; i < 8; i++) {
        int idx = tid + i*256;
        int row = idx & 127;
        int c4  = (idx >> 7) * 4;
        float4 v = *reinterpret_cast<const float4*>(Qb + (size_t)(q0+row)*DD + c4);
        As[c4+0][row]=v.x*0.125f; As[c4+1][row]=v.y*0.125f;
        As[c4+2][row]=v.z*0.125f; As[c4+3][row]=v.w*0.125f;
    }

    int tx8 = (tid & 15) * 8, ty8 = (tid >> 4) * 8;
    for (int cc = 0; cc < 2; cc++) {
        __syncthreads();
#pragma unroll
        for (int i = 0; i < 8; i++) {
            int idx = tid + i*256;
            int row = idx & 127;
            int c4  = (idx >> 7) * 4;
            float4 v = *reinterpret_cast<const float4*>(ncb + (size_t)(cc*128+row)*DD + c4);
            Bs[c4+0][row]=v.x; Bs[c4+1][row]=v.y; Bs[c4+2][row]=v.z; Bs[c4+3][row]=v.w;
        }
        __syncthreads();
        float acc[8][8] = {};
#pragma unroll 8
        for (int kk = 0; kk < 64; kk++) {
            float a[8], b[8];
            *reinterpret_cast<float4*>(&a[0]) = *reinterpret_cast<float4*>(&As[kk][ty8]);
            *reinterpret_cast<float4*>(&a[4]) = *reinterpret_cast<float4*>(&As[kk][ty8+4]);
            *reinterpret_cast<float4*>(&b[0]) = *reinterpret_cast<float4*>(&Bs[kk][tx8]);
            *reinterpret_cast<float4*>(&b[4]) = *reinterpret_cast<float4*>(&Bs[kk][tx8+4]);
#pragma unroll
            for (int i = 0; i < 8; i++)
#pragma unroll
                for (int j = 0; j < 8; j++) acc[i][j] += a[i]*b[j];
        }
#pragma unroll
        for (int i = 0; i < 8; i++) {
            *reinterpret_cast<float4*>(&L[ty8+i][cc*128+tx8]) =
                make_float4(acc[i][0],acc[i][1],acc[i][2],acc[i][3]);
            *reinterpret_cast<float4*>(&L[ty8+i][cc*128+tx8+4]) =
                make_float4(acc[i][4],acc[i][5],acc[i][6],acc[i][7]);
        }
    }
    __syncthreads();

    int wid = tid >> 5, lane = tid & 31;
    for (int r = wid; r < 128; r += 8) {
        float v[8]; float mx = -FLT_MAX;
#pragma unroll
        for (int t = 0; t < 8; t++) { v[t] = L[r][lane + 32*t]; mx = fmaxf(mx, v[t]); }
#pragma unroll
        for (int o = 16; o > 0; o >>= 1) mx = fmaxf(mx, __shfl_xor_sync(0xffffffffu, mx, o));
        float s = 0.f;
#pragma unroll
        for (int t = 0; t < 8; t++) { v[t] = __expf(v[t] - mx); s += v[t]; }
#pragma unroll
        for (int o = 16; o > 0; o >>= 1) s += __shfl_xor_sync(0xffffffffu, s, o);
        float inv = 1.0f / s;
#pragma unroll
        for (int t = 0; t < 8; t++) L[r][lane + 32*t] = v[t] * inv;
    }

    int ry = (tid >> 4) * 8;
    int cx = (tid & 15) * 4;
    float acc3[8][4] = {};
    for (int kc = 0; kc < 4; kc++) {
        __syncthreads();
#pragma unroll
        for (int i = 0; i < 4; i++) {
            int idx = tid + i*256;
            int row = idx >> 4, c4 = (idx & 15) * 4;
            *reinterpret_cast<float4*>(&Ys[row][c4]) =
                *reinterpret_cast<const float4*>(Yb + (size_t)(kc*64+row)*DD + c4);
        }
        __syncthreads();
#pragma unroll 8
        for (int kk = 0; kk < 64; kk++) {
            float b[4];
            *reinterpret_cast<float4*>(&b[0]) = *reinterpret_cast<float4*>(&Ys[kk][cx]);
            float a[8];
#pragma unroll
            for (int i = 0; i < 8; i++) a[i] = L[ry+i][kc*64+kk];
#pragma unroll
            for (int i = 0; i < 8; i++)
#pragma unroll
                for (int j = 0; j < 4; j++) acc3[i][j] += a[i]*b[j];
        }
    }
#pragma unroll
    for (int i = 0; i < 8; i++)
        *reinterpret_cast<float4*>(X + ((size_t)bh*NN + q0 + ry + i)*DD + cx) =
            make_float4(acc3[i][0], acc3[i][1], acc3[i][2], acc3[i][3]);
}

// ---------------- host launch ----------------
extern "C" void kernel_launch(void* const* d_in, const int* in_sizes, int n_in,
                              void* d_out, int out_size)
{
    (void)in_sizes; (void)n_in; (void)out_size;
    const float* Q = (const float*)d_in[0];
    const float* K = (const float*)d_in[1];
    const float* V = (const float*)d_in[2];
    float* X = (float*)d_out;

    static cudaStream_t s2 = nullptr;
    static cudaEvent_t evFork = nullptr, evJoin = nullptr;
    static bool attrs_done = false;
    if (!s2) {
        cudaStreamCreateWithFlags(&s2, cudaStreamNonBlocking);
        cudaEventCreateWithFlags(&evFork, cudaEventDisableTiming);
        cudaEventCreateWithFlags(&evJoin, cudaEventDisableTiming);
    }
    const int NT_SMEM  = 2*64*132*sizeof(float);                 // 67.5 KB
    const int NS1_SMEM = 64*136*4 + 64*72*4;                     // 53.2 KB
    const int NS3_SMEM = 64*132*8 + 64*72*8;                     // 104.4 KB
    const int FL_SMEM  = (128*68 + 64*68 + 64*68 + 128*68)*4;    // 104.4 KB
    const int FX_SMEM  = (2*64*132 + 128*FX_LPAD)*sizeof(float); // 200.7 KB
    if (!attrs_done) {
        cudaFuncSetAttribute(gemm_nt128_kernel, cudaFuncAttributeMaxDynamicSharedMemorySize, NT_SMEM);
        cudaFuncSetAttribute(ns_fused1_kernel,  cudaFuncAttributeMaxDynamicSharedMemorySize, NS1_SMEM);
        cudaFuncSetAttribute(ns_fused3_kernel,  cudaFuncAttributeMaxDynamicSharedMemorySize, NS3_SMEM);
        cudaFuncSetAttribute(rv_flash_kernel,   cudaFuncAttributeMaxDynamicSharedMemorySize, FL_SMEM);
        cudaFuncSetAttribute(fusedx_kernel,     cudaFuncAttributeMaxDynamicSharedMemorySize, FX_SMEM);
        attrs_done = true;
    }

    float *nc, *nr, *u, *v0, *v1, *kv, *t1, *t2, *rvp, *ml, *rv, *y;
    int *ik, *iq;
    cudaGetSymbolAddress((void**)&nc, g_nc);
    cudaGetSymbolAddress((void**)&nr, g_nr);
    cudaGetSymbolAddress((void**)&ik, g_idxk);
    cudaGetSymbolAddress((void**)&iq, g_idxq);
    cudaGetSymbolAddress((void**)&u,  g_u);
    cudaGetSymbolAddress((void**)&v0, g_v0);
    cudaGetSymbolAddress((void**)&v1, g_v1);
    cudaGetSymbolAddress((void**)&kv, g_kv);
    cudaGetSymbolAddress((void**)&t1, g_t1);
    cudaGetSymbolAddress((void**)&t2, g_t2);
    cudaGetSymbolAddress((void**)&rvp, g_rvp);
    cudaGetSymbolAddress((void**)&ml, g_ml);
    cudaGetSymbolAddress((void**)&rv, g_rv);
    cudaGetSymbolAddress((void**)&y,  g_y);

    // 1) selection + gather
    topk_kernel<<<32, 1024>>>(Q, K, ik, iq);
    gather_kernel<<<16, dim3(64,4)>>>(Q, K, ik, iq, nc, nr);

    // fork: flash RV pipeline (fp32, FMA pipe) overlaps main-stream tensor work
    cudaEventRecord(evFork, 0);
    cudaStreamWaitEvent(s2, evFork, 0);

    rv_flash_kernel<<<dim3(8, 2, 16), 256, FL_SMEM, s2>>>(nr, K, V, rvp, ml);
    rv_combine_kernel<<<BH*MM*DD/(256*4), 256, 0, s2>>>(rvp, ml, rv);
    cudaEventRecord(evJoin, s2);

    // main: u = softmax(nr @ nc^T); Newton-Schulz inverse
    gemm_nt128_kernel<<<dim3(2, 2, 16), 256, NT_SMEM>>>(nr, nc, u, MM, MM);
    softmax_rows_kernel<<<BH*MM, 256, MM*sizeof(float)>>>(u, MM);
    v0init_kernel<<<16, 256>>>(u, v0);

    // NS chain with Programmatic Dependent Launch: each dependent kernel's
    // blocks may launch while the previous drains; the kernel-side
    // cudaGridDependencySynchronize() guarantees upstream writes are visible
    // before any dependent read. Numerically identical to the R12 chain.
    cudaLaunchAttribute pdlAttr[1];
    pdlAttr[0].id = cudaLaunchAttributeProgrammaticStreamSerialization;
    pdlAttr[0].val.programmaticStreamSerializationAllowed = 1;

    cudaLaunchConfig_t cfg1 = {};
    cfg1.gridDim = dim3(4, 2, 16);
    cfg1.blockDim = dim3(256, 1, 1);
    cfg1.dynamicSmemBytes = NS1_SMEM;
    cfg1.stream = 0;
    cfg1.attrs = pdlAttr;
    cfg1.numAttrs = 1;
    cudaLaunchConfig_t cfg3 = cfg1;
    cfg3.dynamicSmemBytes = NS3_SMEM;

    float* vin = v0; float* vout = v1;
    for (int it = 0; it < 4; it++) {
        if (it < 3) {
            // single tf32, fused epilogue: Newton-Schulz self-corrects the noise
            cudaLaunchKernelEx(&cfg1, ns_fused1_kernel, (const float*)u,   (const float*)vin, (const float*)nullptr, kv,   1.0f,  0.0f);
            cudaLaunchKernelEx(&cfg1, ns_fused1_kernel, (const float*)kv,  (const float*)kv,  (const float*)kv,      t1,  -1.0f,  7.0f);
            cudaLaunchKernelEx(&cfg1, ns_fused1_kernel, (const float*)kv,  (const float*)t1,  (const float*)kv,      t2,  -1.0f, 15.0f);
            cudaLaunchKernelEx(&cfg1, ns_fused1_kernel, (const float*)vin, (const float*)t2,  (const float*)vin,     vout, -0.25f, 3.25f);
        } else {
            // final iteration fp32-grade (3xTF32, fused epilogue)
            cudaLaunchKernelEx(&cfg3, ns_fused3_kernel, (const float*)u,   (const float*)vin, (const float*)nullptr, kv,   1.0f,  0.0f);
            cudaLaunchKernelEx(&cfg3, ns_fused3_kernel, (const float*)kv,  (const float*)kv,  (const float*)kv,      t1,  -1.0f,  7.0f);
            cudaLaunchKernelEx(&cfg3, ns_fused3_kernel, (const float*)kv,  (const float*)t1,  (const float*)kv,      t2,  -1.0f, 15.0f);
            cudaLaunchKernelEx(&cfg3, ns_fused3_kernel, (const float*)vin, (const float*)t2,  (const float*)vin,     vout, -0.25f, 3.25f);
        }
        float* tmp = vin; vin = vout; vout = tmp;
    }

    // join: need rv before Y
    cudaStreamWaitEvent(0, evJoin, 0);

    // 7) Y = V_inv @ RV
    gemm_nn_kernel<<<dim3(1,4,16), 256>>>(vin, rv, y, MM, DD, MM);
    // 8) X = softmax(Qs @ nc^T) @ Y, fused per 128-row chunk
    fusedx_kernel<<<dim3(NN/128, BH), 256, FX_SMEM>>>(Q, nc, y, X);
}

// round 16
// speedup vs baseline: 1.2207x; 1.0362x over previous
#include <cuda_runtime.h>
#include <float.h>
#include <stdint.h>

#define BH 16
#define HH 8
#define NN 4096
#define DD 64
#define MM 256

// ---------------- scratch (__device__ globals; no allocation) ----------------
__device__ float g_nc [BH*MM*DD];
__device__ float g_nr [BH*MM*DD];
__device__ int   g_idxk[BH*MM];
__device__ int   g_idxq[BH*MM];
__device__ float g_u  [BH*MM*MM];
__device__ float g_v0 [BH*MM*MM];
__device__ float g_v1 [BH*MM*MM];
__device__ float g_kv [BH*MM*MM];
__device__ float g_t1 [BH*MM*MM];
__device__ float g_t2 [BH*MM*MM];
__device__ float g_rvp[8*BH*MM*DD];          // flash split partials
__device__ float g_ml [8*BH*MM*2];           // flash split (max, sumexp)
__device__ float g_rv [BH*MM*DD];
__device__ float g_y  [BH*MM*DD];

// ---------------- tf32 mma helpers ----------------
__device__ __forceinline__ uint32_t f2tf(float v) {
    uint32_t r; asm("cvt.rna.tf32.f32 %0, %1;" : "=r"(r) : "f"(v)); return r;
}
__device__ __forceinline__ void mma_tf32(float4& d, const uint32_t* a, const uint32_t* b) {
    asm volatile("mma.sync.aligned.m16n8k8.row.col.f32.tf32.tf32.f32 "
        "{%0,%1,%2,%3}, {%4,%5,%6,%7}, {%8,%9}, {%0,%1,%2,%3};"
        : "+f"(d.x), "+f"(d.y), "+f"(d.z), "+f"(d.w)
        : "r"(a[0]), "r"(a[1]), "r"(a[2]), "r"(a[3]), "r"(b[0]), "r"(b[1]));
}
__device__ __forceinline__ uint2 split_tf32(float x) {
    uint32_t hi = f2tf(x);
    float lo = x - __uint_as_float(hi);
    return make_uint2(hi, f2tf(lo));
}
// 3xTF32: d += a_hi*b_hi + a_lo*b_hi + a_hi*b_lo (fp32-grade)
__device__ __forceinline__ void mma_tf32x3(float4& d, const uint2* a, const uint2* b) {
    uint32_t ah[4] = {a[0].x, a[1].x, a[2].x, a[3].x};
    uint32_t al[4] = {a[0].y, a[1].y, a[2].y, a[3].y};
    uint32_t bh_[2] = {b[0].x, b[1].x};
    uint32_t bl_[2] = {b[0].y, b[1].y};
    mma_tf32(d, ah, bh_);
    mma_tf32(d, al, bh_);
    mma_tf32(d, ah, bl_);
}

// ---------------- top-k: exact bitonic sort of (sum,row) keys ----------------
__global__ void __launch_bounds__(1024) topk_kernel(
    const float* __restrict__ Q, const float* __restrict__ K,
    int* __restrict__ idxk, int* __restrict__ idxq)
{
    __shared__ unsigned long long keys[NN];
    int bh  = blockIdx.x >> 1;
    int isQ = blockIdx.x & 1;
    const float* src = isQ ? Q : K;
    int tid = threadIdx.x;

    for (int r = tid; r < NN; r += 1024) {
        const float4* p = reinterpret_cast<const float4*>(src + ((size_t)bh*NN + r)*DD);
        float s = 0.f;
#pragma unroll
        for (int t = 0; t < DD/4; t++) { float4 v = p[t]; s += v.x + v.y + v.z + v.w; }
        unsigned int u = __float_as_uint(s);
        unsigned int m = (u & 0x80000000u) ? ~u : (u | 0x80000000u);
        keys[r] = ((unsigned long long)(~m) << 32) | (unsigned int)r;
    }
    __syncthreads();

    for (int k = 2; k <= NN; k <<= 1) {
        for (int j = k >> 1; j > 0; j >>= 1) {
            for (int i = tid; i < NN; i += 1024) {
                int ixj = i ^ j;
                if (ixj > i) {
                    bool up = ((i & k) == 0);
                    unsigned long long a = keys[i], c = keys[ixj];
                    if ((a > c) == up) { keys[i] = c; keys[ixj] = a; }
                }
            }
            __syncthreads();
        }
    }
    int* dst = isQ ? idxq : idxk;
    if (tid < MM) dst[bh*MM + tid] = (int)(keys[tid] & 0xFFFFFFFFu);
}

// ---------------- gather nc = K[idx_k], nr = Q[idx_q]/8 (PDL-aware) ----------
__global__ void gather_kernel(const float* __restrict__ Q, const float* __restrict__ K,
                              const int* __restrict__ idxk, const int* __restrict__ idxq,
                              float* __restrict__ nc, float* __restrict__ nr)
{
    cudaGridDependencySynchronize();   // wait for topk's idx writes
    int bh = blockIdx.x;
    int tx = threadIdx.x;
    int ty = threadIdx.y;
    for (int i = ty; i < MM; i += 4) {
        int ik = idxk[bh*MM + i];
        int iq = idxq[bh*MM + i];
        nc[((size_t)bh*MM + i)*DD + tx] = K[((size_t)bh*NN + ik)*DD + tx];
        nr[((size_t)bh*MM + i)*DD + tx] = Q[((size_t)bh*NN + iq)*DD + tx] * 0.125f;
    }
}

// ---------------- NT GEMM (K=64): 128x128 tile, 8x8 micro (fp32, PDL) --------
__global__ void __launch_bounds__(256) gemm_nt128_kernel(
    const float* __restrict__ A, const float* __restrict__ B, float* __restrict__ C,
    int Ma, int Nb)
{
    extern __shared__ float sm[];
    float (*As)[132] = reinterpret_cast<float(*)[132]>(sm);
    float (*Bs)[132] = reinterpret_cast<float(*)[132]>(sm + 64*132);
    int bh = blockIdx.z;
    int m0 = blockIdx.y * 128;
    int n0 = blockIdx.x * 128;
    const float* Ab = A + (size_t)bh*Ma*64;
    const float* Bb = B + (size_t)bh*Nb*64;
    float*       Cb = C + (size_t)bh*Ma*Nb;
    int tid = threadIdx.x;
    cudaGridDependencySynchronize();   // wait for gather's nc/nr writes
#pragma unroll
    for (int i = 0; i < 8; i++) {
        int idx = tid + i*256;
        int row = idx & 127;
        int c4  = (idx >> 7) * 4;
        float4 v = *reinterpret_cast<const float4*>(Ab + (size_t)(m0+row)*64 + c4);
        As[c4+0][row]=v.x; As[c4+1][row]=v.y; As[c4+2][row]=v.z; As[c4+3][row]=v.w;
        float4 w = *reinterpret_cast<const float4*>(Bb + (size_t)(n0+row)*64 + c4);
        Bs[c4+0][row]=w.x; Bs[c4+1][row]=w.y; Bs[c4+2][row]=w.z; Bs[c4+3][row]=w.w;
    }
    __syncthreads();
    int tx8 = (tid & 15) * 8, ty8 = (tid >> 4) * 8;
    float acc[8][8] = {};
#pragma unroll 8
    for (int kk = 0; kk < 64; kk++) {
        float a[8], b[8];
        *reinterpret_cast<float4*>(&a[0]) = *reinterpret_cast<float4*>(&As[kk][ty8]);
        *reinterpret_cast<float4*>(&a[4]) = *reinterpret_cast<float4*>(&As[kk][ty8+4]);
        *reinterpret_cast<float4*>(&b[0]) = *reinterpret_cast<float4*>(&Bs[kk][tx8]);
        *reinterpret_cast<float4*>(&b[4]) = *reinterpret_cast<float4*>(&Bs[kk][tx8+4]);
#pragma unroll
        for (int i = 0; i < 8; i++)
#pragma unroll
            for (int j = 0; j < 8; j++) acc[i][j] += a[i]*b[j];
    }
#pragma unroll
    for (int i = 0; i < 8; i++) {
        *reinterpret_cast<float4*>(Cb + (size_t)(m0+ty8+i)*Nb + n0+tx8) =
            make_float4(acc[i][0],acc[i][1],acc[i][2],acc[i][3]);
        *reinterpret_cast<float4*>(Cb + (size_t)(m0+ty8+i)*Nb + n0+tx8+4) =
            make_float4(acc[i][4],acc[i][5],acc[i][6],acc[i][7]);
    }
}

// ---------------- NS fused GEMM (single tf32, full K, fused epilogue, PDL) ---
__global__ void __launch_bounds__(256) ns_fused1_kernel(
    const float* __restrict__ A, const float* __restrict__ B,
    const float* __restrict__ Cadd, float* __restrict__ Out,
    float alpha, float beta)
{
    extern __shared__ char smc[];
    uint32_t (*As)[136] = reinterpret_cast<uint32_t(*)[136]>(smc);
    uint32_t (*Bs)[72]  = reinterpret_cast<uint32_t(*)[72]> (smc + 64*136*4);
    int bh = blockIdx.z;
    int n0 = blockIdx.x * 64;
    int m0 = blockIdx.y * 128;
    const float* Ab = A + (size_t)bh*MM*MM;
    const float* Bb = B + (size_t)bh*MM*MM;
    float*       Ob = Out + (size_t)bh*MM*MM;
    int tid = threadIdx.x, lane = tid & 31, wid = tid >> 5;
    int r4 = lane >> 2, c4 = lane & 3;
    int wm = (wid & 1) * 64;
    int wn = ((wid >> 1) & 1) * 32;
    int kg = wid >> 2;
    int kb = kg * 32;

    float4 acc[4][4];
#pragma unroll
    for (int i = 0; i < 4; i++)
#pragma unroll
        for (int j = 0; j < 4; j++) acc[i][j] = make_float4(0.f,0.f,0.f,0.f);

    cudaGridDependencySynchronize();   // PDL: upstream writes visible past here

    for (int sc = 0; sc < 4; sc++) {
        int k0g = sc * 64;
        if (sc) __syncthreads();
#pragma unroll
        for (int i = 0; i < 8; i++) {
            int idx = tid + i*256;
            int row = idx & 127;
            int kq  = (idx >> 7) * 4;
            float4 v = *reinterpret_cast<const float4*>(Ab + (size_t)(m0+row)*MM + k0g + kq);
            As[kq+0][row]=f2tf(v.x); As[kq+1][row]=f2tf(v.y);
            As[kq+2][row]=f2tf(v.z); As[kq+3][row]=f2tf(v.w);
        }
#pragma unroll
        for (int i = 0; i < 4; i++) {
            int idx = tid + i*256;
            int row = idx >> 4;
            int cq  = (idx & 15) * 4;
            float4 v = *reinterpret_cast<const float4*>(Bb + (size_t)(k0g+row)*MM + n0 + cq);
            Bs[row][cq+0]=f2tf(v.x); Bs[row][cq+1]=f2tf(v.y);
            Bs[row][cq+2]=f2tf(v.z); Bs[row][cq+3]=f2tf(v.w);
        }
        __syncthreads();
#pragma unroll
        for (int ks = 0; ks < 4; ks++) {
            int k0 = kb + ks*8;
            uint32_t af[4][4], bf[4][2];
#pragma unroll
            for (int i = 0; i < 4; i++) {
                int mb = wm + i*16;
                af[i][0] = As[k0+c4  ][mb+r4];
                af[i][1] = As[k0+c4  ][mb+8+r4];
                af[i][2] = As[k0+4+c4][mb+r4];
                af[i][3] = As[k0+4+c4][mb+8+r4];
            }
#pragma unroll
            for (int j = 0; j < 4; j++) {
                int nb = wn + j*8;
                bf[j][0] = Bs[k0+c4  ][nb+r4];
                bf[j][1] = Bs[k0+4+c4][nb+r4];
            }
#pragma unroll
            for (int i = 0; i < 4; i++)
#pragma unroll
                for (int j = 0; j < 4; j++) mma_tf32(acc[i][j], af[i], bf[j]);
        }
    }

    __syncthreads();
    float4* red = reinterpret_cast<float4*>(smc);
    if (kg == 1) {
        int slot = wid - 4;
#pragma unroll
        for (int f = 0; f < 16; f++)
            red[((size_t)f*4 + slot)*32 + lane] = acc[f>>2][f&3];
    }
    __syncthreads();
    if (kg == 0) {
        const float* Cb = Cadd ? (Cadd + (size_t)bh*MM*MM) : nullptr;
#pragma unroll
        for (int f = 0; f < 16; f++) {
            float4 o = red[((size_t)f*4 + wid)*32 + lane];
            acc[f>>2][f&3].x += o.x; acc[f>>2][f&3].y += o.y;
            acc[f>>2][f&3].z += o.z; acc[f>>2][f&3].w += o.w;
        }
#pragma unroll
        for (int i = 0; i < 4; i++) {
            int row0 = m0 + wm + i*16 + r4;
#pragma unroll
            for (int j = 0; j < 4; j++) {
                int col = n0 + wn + j*8 + 2*c4;
                float2 v0 = make_float2(alpha*acc[i][j].x, alpha*acc[i][j].y);
                float2 v1 = make_float2(alpha*acc[i][j].z, alpha*acc[i][j].w);
                if (Cb) {
                    float2 c0 = *reinterpret_cast<const float2*>(Cb + (size_t)row0*MM + col);
                    float2 c1 = *reinterpret_cast<const float2*>(Cb + (size_t)(row0+8)*MM + col);
                    v0.x += beta*c0.x; v0.y += beta*c0.y;
                    v1.x += beta*c1.x; v1.y += beta*c1.y;
                }
                *reinterpret_cast<float2*>(Ob + (size_t)row0*MM + col) = v0;
                *reinterpret_cast<float2*>(Ob + (size_t)(row0+8)*MM + col) = v1;
            }
        }
    }
}

// ---------------- NS fused GEMM (3xTF32, fp32-grade; iteration 4, PDL) -------
__global__ void __launch_bounds__(256) ns_fused3_kernel(
    const float* __restrict__ A, const float* __restrict__ B,
    const float* __restrict__ Cadd, float* __restrict__ Out,
    float alpha, float beta)
{
    extern __shared__ char smc[];
    uint2 (*As2)[132] = reinterpret_cast<uint2(*)[132]>(smc);
    uint2 (*Bs2)[72]  = reinterpret_cast<uint2(*)[72]> (smc + 64*132*8);
    int bh = blockIdx.z;
    int n0 = blockIdx.x * 64;
    int m0 = blockIdx.y * 128;
    const float* Ab = A + (size_t)bh*MM*MM;
    const float* Bb = B + (size_t)bh*MM*MM;
    float*       Ob = Out + (size_t)bh*MM*MM;
    int tid = threadIdx.x, lane = tid & 31, wid = tid >> 5;
    int r4 = lane >> 2, c4 = lane & 3;
    int wm = (wid & 1) * 64;
    int wn = ((wid >> 1) & 1) * 32;
    int kg = wid >> 2;
    int kb = kg * 32;

    float4 acc[4][4];
#pragma unroll
    for (int i = 0; i < 4; i++)
#pragma unroll
        for (int j = 0; j < 4; j++) acc[i][j] = make_float4(0.f,0.f,0.f,0.f);

    cudaGridDependencySynchronize();   // PDL: upstream writes visible past here

    for (int sc = 0; sc < 4; sc++) {
        int k0g = sc * 64;
        if (sc) __syncthreads();
#pragma unroll
        for (int i = 0; i < 8; i++) {
            int idx = tid + i*256;
            int row = idx & 127;
            int kq  = (idx >> 7) * 4;
            float4 v = *reinterpret_cast<const float4*>(Ab + (size_t)(m0+row)*MM + k0g + kq);
            As2[kq+0][row]=split_tf32(v.x); As2[kq+1][row]=split_tf32(v.y);
            As2[kq+2][row]=split_tf32(v.z); As2[kq+3][row]=split_tf32(v.w);
        }
#pragma unroll
        for (int i = 0; i < 4; i++) {
            int idx = tid + i*256;
            int row = idx >> 4;
            int cq  = (idx & 15) * 4;
            float4 v = *reinterpret_cast<const float4*>(Bb + (size_t)(k0g+row)*MM + n0 + cq);
            Bs2[row][cq+0]=split_tf32(v.x); Bs2[row][cq+1]=split_tf32(v.y);
            Bs2[row][cq+2]=split_tf32(v.z); Bs2[row][cq+3]=split_tf32(v.w);
        }
        __syncthreads();
#pragma unroll
        for (int ks = 0; ks < 4; ks++) {
            int k0 = kb + ks*8;
            uint2 a2[4][4], b2[4][2];
#pragma unroll
            for (int i = 0; i < 4; i++) {
                int mb = wm + i*16;
                a2[i][0] = As2[k0+c4  ][mb+r4];
                a2[i][1] = As2[k0+c4  ][mb+8+r4];
                a2[i][2] = As2[k0+4+c4][mb+r4];
                a2[i][3] = As2[k0+4+c4][mb+8+r4];
            }
#pragma unroll
            for (int j = 0; j < 4; j++) {
                int nb = wn + j*8;
                b2[j][0] = Bs2[k0+c4  ][nb+r4];
                b2[j][1] = Bs2[k0+4+c4][nb+r4];
            }
#pragma unroll
            for (int i = 0; i < 4; i++)
#pragma unroll
                for (int j = 0; j < 4; j++) mma_tf32x3(acc[i][j], a2[i], b2[j]);
        }
    }

    __syncthreads();
    float4* red = reinterpret_cast<float4*>(smc);
    if (kg == 1) {
        int slot = wid - 4;
#pragma unroll
        for (int f = 0; f < 16; f++)
            red[((size_t)f*4 + slot)*32 + lane] = acc[f>>2][f&3];
    }
    __syncthreads();
    if (kg == 0) {
        const float* Cb = Cadd ? (Cadd + (size_t)bh*MM*MM) : nullptr;
#pragma unroll
        for (int f = 0; f < 16; f++) {
            float4 o = red[((size_t)f*4 + wid)*32 + lane];
            acc[f>>2][f&3].x += o.x; acc[f>>2][f&3].y += o.y;
            acc[f>>2][f&3].z += o.z; acc[f>>2][f&3].w += o.w;
        }
#pragma unroll
        for (int i = 0; i < 4; i++) {
            int row0 = m0 + wm + i*16 + r4;
#pragma unroll
            for (int j = 0; j < 4; j++) {
                int col = n0 + wn + j*8 + 2*c4;
                float2 v0 = make_float2(alpha*acc[i][j].x, alpha*acc[i][j].y);
                float2 v1 = make_float2(alpha*acc[i][j].z, alpha*acc[i][j].w);
                if (Cb) {
                    float2 c0 = *reinterpret_cast<const float2*>(Cb + (size_t)row0*MM + col);
                    float2 c1 = *reinterpret_cast<const float2*>(Cb + (size_t)(row0+8)*MM + col);
                    v0.x += beta*c0.x; v0.y += beta*c0.y;
                    v1.x += beta*c1.x; v1.y += beta*c1.y;
                }
                *reinterpret_cast<float2*>(Ob + (size_t)row0*MM + col) = v0;
                *reinterpret_cast<float2*>(Ob + (size_t)(row0+8)*MM + col) = v1;
            }
        }
    }
}

// ---------------- NN GEMM (small, for Y = inv @ RV, PDL) ---------------------
__global__ void __launch_bounds__(256) gemm_nn_kernel(
    const float* __restrict__ A, const float* __restrict__ B,
    float* __restrict__ Out, int Ma, int Nb, int Kd)
{
    __shared__ float As[64][65];
    __shared__ float Bs[64][65];
    int bh = blockIdx.z;
    int n0 = blockIdx.x * 64;
    int m0 = blockIdx.y * 64;
    const float* Ab = A + (size_t)bh*Ma*Kd;
    const float* Bb = B + (size_t)bh*Kd*Nb;
    float*       Ob = Out + (size_t)bh*Ma*Nb;
    int tid = threadIdx.x;
    int tx4 = (tid & 15) * 4, ty4 = (tid >> 4) * 4;
    float acc[4][4] = {};
    cudaGridDependencySynchronize();   // wait for NS-final writes
    for (int k0 = 0; k0 < Kd; k0 += 64) {
        for (int l = tid; l < 64*16; l += 256) {
            int row = l >> 4, c4 = (l & 15) * 4;
            float4 va = *reinterpret_cast<const float4*>(Ab + (size_t)(m0+row)*Kd + k0 + c4);
            As[row][c4+0]=va.x; As[row][c4+1]=va.y; As[row][c4+2]=va.z; As[row][c4+3]=va.w;
            float4 vb = *reinterpret_cast<const float4*>(Bb + (size_t)(k0+row)*Nb + n0 + c4);
            Bs[row][c4+0]=vb.x; Bs[row][c4+1]=vb.y; Bs[row][c4+2]=vb.z; Bs[row][c4+3]=vb.w;
        }
        __syncthreads();
#pragma unroll 16
        for (int kk = 0; kk < 64; kk++) {
            float a0=As[ty4+0][kk], a1=As[ty4+1][kk], a2=As[ty4+2][kk], a3=As[ty4+3][kk];
            float b0=Bs[kk][tx4+0], b1=Bs[kk][tx4+1], b2=Bs[kk][tx4+2], b3=Bs[kk][tx4+3];
            acc[0][0]+=a0*b0; acc[0][1]+=a0*b1; acc[0][2]+=a0*b2; acc[0][3]+=a0*b3;
            acc[1][0]+=a1*b0; acc[1][1]+=a1*b1; acc[1][2]+=a1*b2; acc[1][3]+=a1*b3;
            acc[2][0]+=a2*b0; acc[2][1]+=a2*b1; acc[2][2]+=a2*b2; acc[2][3]+=a2*b3;
            acc[3][0]+=a3*b0; acc[3][1]+=a3*b1; acc[3][2]+=a3*b2; acc[3][3]+=a3*b3;
        }
        __syncthreads();
    }
#pragma unroll
    for (int i = 0; i < 4; i++) {
        size_t off = (size_t)(m0+ty4+i)*Nb + n0 + tx4;
        *reinterpret_cast<float4*>(Ob + off) =
            make_float4(acc[i][0], acc[i][1], acc[i][2], acc[i][3]);
    }
}

// ---------------- row softmax (in place), one block per row (PDL) ------------
__global__ void softmax_rows_kernel(float* __restrict__ data, int cols)
{
    extern __shared__ float buf[];
    __shared__ float red[256];
    size_t row = blockIdx.x;
    float* d = data + row * (size_t)cols;
    int tid = threadIdx.x;
    cudaGridDependencySynchronize();   // wait for upstream GEMM writes
    float mx = -FLT_MAX;
    for (int c = tid; c < cols; c += 256) { float v = d[c]; buf[c] = v; mx = fmaxf(mx, v); }
    red[tid] = mx; __syncthreads();
    for (int st = 128; st > 0; st >>= 1) { if (tid < st) red[tid] = fmaxf(red[tid], red[tid+st]); __syncthreads(); }
    mx = red[0];
    __syncthreads();
    float s = 0.f;
    for (int c = tid; c < cols; c += 256) { float e = __expf(buf[c] - mx); buf[c] = e; s += e; }
    red[tid] = s; __syncthreads();
    for (int st = 128; st > 0; st >>= 1) { if (tid < st) red[tid] += red[tid+st]; __syncthreads(); }
    float inv = 1.0f / red[0];
    for (int c = tid; c < cols; c += 256) d[c] = buf[c] * inv;
}

// ---------------- V0 = u^T / max_j(colsum_j(u)) (PDL) ------------------------
__global__ void __launch_bounds__(256) v0init_kernel(const float* __restrict__ U, float* __restrict__ V0)
{
    __shared__ float red[256];
    int bh = blockIdx.x;
    const float* u = U  + (size_t)bh*MM*MM;
    float*       v = V0 + (size_t)bh*MM*MM;
    int j = threadIdx.x;
    cudaGridDependencySynchronize();   // wait for softmax's u writes
    float s = 0.f;
    for (int i = 0; i < MM; i++) s += u[(size_t)i*MM + j];
    red[j] = s; __syncthreads();
    for (int st = 128; st > 0; st >>= 1) { if (j < st) red[j] = fmaxf(red[j], red[j+st]); __syncthreads(); }
    float scale = 1.0f / red[0];
    for (int q = 0; q < MM; q++) v[(size_t)j*MM + q] = scale * u[(size_t)q*MM + j];
}

// ---------------- flash RV: partial softmax(nr @ K^T) @ V over KV splits -----
__global__ void __launch_bounds__(256) rv_flash_kernel(
    const float* __restrict__ NR, const float* __restrict__ K,
    const float* __restrict__ V, float* __restrict__ P, float* __restrict__ ML)
{
    extern __shared__ float sm[];
    float (*Nrs)[68] = reinterpret_cast<float(*)[68]>(sm);
    float (*Ksk)[68] = reinterpret_cast<float(*)[68]>(sm + 128*68);
    float (*Vs)[68]  = reinterpret_cast<float(*)[68]>(sm + 128*68 + 64*68);
    float (*Ps)[68]  = reinterpret_cast<float(*)[68]>(sm + 128*68 + 2*64*68);
    int s  = blockIdx.x;
    int m0 = blockIdx.y * 128;
    int bh = blockIdx.z;
    const float* Nb = NR + (size_t)bh*MM*DD;
    const float* Kb = K  + (size_t)bh*NN*DD;
    const float* Vb = V  + (size_t)bh*NN*DD;
    int tid = threadIdx.x;
    int ry = (tid >> 4) * 8;
    int cx = (tid & 15) * 4;

#pragma unroll
    for (int i = 0; i < 8; i++) {
        int idx = tid + i*256;
        int row = idx >> 4, q4 = (idx & 15) * 4;
        *reinterpret_cast<float4*>(&Nrs[row][q4]) =
            *reinterpret_cast<const float4*>(Nb + (size_t)(m0+row)*DD + q4);
    }

    float m_i[8], l_i[8];
    float O[8][4] = {};
#pragma unroll
    for (int i = 0; i < 8; i++) { m_i[i] = -FLT_MAX; l_i[i] = 0.f; }

    for (int kc = 0; kc < 8; kc++) {
        int k0 = s*512 + kc*64;
        __syncthreads();
#pragma unroll
        for (int i = 0; i < 4; i++) {
            int idx = tid + i*256;
            int c  = idx & 63;
            int kq = (idx >> 6) * 4;
            float4 v = *reinterpret_cast<const float4*>(Kb + (size_t)(k0+c)*DD + kq);
            Ksk[kq+0][c]=v.x; Ksk[kq+1][c]=v.y; Ksk[kq+2][c]=v.z; Ksk[kq+3][c]=v.w;
        }
#pragma unroll
        for (int i = 0; i < 4; i++) {
            int idx = tid + i*256;
            int row = idx >> 4, q4 = (idx & 15) * 4;
            *reinterpret_cast<float4*>(&Vs[row][q4]) =
                *reinterpret_cast<const float4*>(Vb + (size_t)(k0+row)*DD + q4);
        }
        __syncthreads();

        float sv[8][4] = {};
#pragma unroll 8
        for (int kk = 0; kk < 64; kk++) {
            float b[4];
            *reinterpret_cast<float4*>(&b[0]) = *reinterpret_cast<float4*>(&Ksk[kk][cx]);
            float a[8];
#pragma unroll
            for (int i = 0; i < 8; i++) a[i] = Nrs[ry+i][kk];
#pragma unroll
            for (int i = 0; i < 8; i++)
#pragma unroll
                for (int j = 0; j < 4; j++) sv[i][j] += a[i]*b[j];
        }

#pragma unroll
        for (int i = 0; i < 8; i++) {
            float mc = fmaxf(fmaxf(sv[i][0], sv[i][1]), fmaxf(sv[i][2], sv[i][3]));
#pragma unroll
            for (int o = 8; o > 0; o >>= 1) mc = fmaxf(mc, __shfl_xor_sync(0xffffffffu, mc, o));
            float mn = fmaxf(m_i[i], mc);
            float corr = __expf(m_i[i] - mn);
            l_i[i] *= corr;
#pragma unroll
            for (int j = 0; j < 4; j++) O[i][j] *= corr;
            float ls = 0.f;
#pragma unroll
            for (int j = 0; j < 4; j++) {
                float p = __expf(sv[i][j] - mn);
                Ps[ry+i][cx+j] = p;
                ls += p;
            }
#pragma unroll
            for (int o = 8; o > 0; o >>= 1) ls += __shfl_xor_sync(0xffffffffu, ls, o);
            l_i[i] += ls;
            m_i[i] = mn;
        }
        __syncthreads();

#pragma unroll 8
        for (int kk = 0; kk < 64; kk++) {
            float b[4];
            *reinterpret_cast<float4*>(&b[0]) = *reinterpret_cast<float4*>(&Vs[kk][cx]);
            float a[8];
#pragma unroll
            for (int i = 0; i < 8; i++) a[i] = Ps[ry+i][kk];
#pragma unroll
            for (int i = 0; i < 8; i++)
#pragma unroll
                for (int j = 0; j < 4; j++) O[i][j] += a[i]*b[j];
        }
    }

    float* Pb = P + ((size_t)s*BH + bh)*MM*DD;
#pragma unroll
    for (int i = 0; i < 8; i++)
        *reinterpret_cast<float4*>(Pb + (size_t)(m0+ry+i)*DD + cx) =
            make_float4(O[i][0], O[i][1], O[i][2], O[i][3]);
    if ((tid & 15) == 0) {
        float* mlb = ML + (((size_t)s*BH + bh)*MM + m0)*2;
#pragma unroll
        for (int i = 0; i < 8; i++) {
            mlb[(ry+i)*2 + 0] = m_i[i];
            mlb[(ry+i)*2 + 1] = l_i[i];
        }
    }
}

__global__ void rv_combine_kernel(const float* __restrict__ P, const float* __restrict__ ML,
                                  float* __restrict__ RV)
{
    cudaGridDependencySynchronize();   // wait for rv_flash writes
    int gt = blockIdx.x * 256 + threadIdx.x;
    int row = gt >> 4;
    int c4  = (gt & 15) * 4;
    float m_s[8], l_s[8];
    float gm = -FLT_MAX;
#pragma unroll
    for (int s = 0; s < 8; s++) {
        m_s[s] = ML[(((size_t)s*BH*MM) + row)*2 + 0];
        l_s[s] = ML[(((size_t)s*BH*MM) + row)*2 + 1];
        gm = fmaxf(gm, m_s[s]);
    }
    float L = 0.f;
    float4 acc = make_float4(0.f,0.f,0.f,0.f);
#pragma unroll
    for (int s = 0; s < 8; s++) {
        float w = __expf(m_s[s] - gm);
        L += w * l_s[s];
        float4 o = *reinterpret_cast<const float4*>(P + ((size_t)s*BH*MM + row)*DD + c4);
        acc.x += w*o.x; acc.y += w*o.y; acc.z += w*o.z; acc.w += w*o.w;
    }
    float inv = 1.0f / L;
    *reinterpret_cast<float4*>(RV + (size_t)row*DD + c4) =
        make_float4(acc.x*inv, acc.y*inv, acc.z*inv, acc.w*inv);
}

// ---------------- fused final: X_chunk = softmax(Qs_chunk @ nc^T) @ Y --------
// PDL: the grid-dependency sync is DELAYED until just before the first Y read,
// so phases 1-2 (logits + softmax; depend only on Q/nc) overlap with gemm_nn.
#define FX_LPAD 260
__global__ void __launch_bounds__(256) fusedx_kernel(
    const float* __restrict__ Q, const float* __restrict__ nc,
    const float* __restrict__ Y, float* __restrict__ X)
{
    extern __shared__ float sm[];
    float (*As)[132] = reinterpret_cast<float(*)[132]>(sm);
    float (*Bs)[132] = reinterpret_cast<float(*)[132]>(sm + 64*132);
    float (*Ys)[68]  = reinterpret_cast<float(*)[68]> (sm + 64*132);
    float (*L)[FX_LPAD] = reinterpret_cast<float(*)[FX_LPAD]>(sm + 2*64*132);
    int bh = blockIdx.y;
    int q0 = blockIdx.x * 128;
    int tid = threadIdx.x;
    const float* Qb  = Q  + (size_t)bh*NN*DD;
    const float* ncb = nc + (size_t)bh*MM*DD;
    const float* Yb  = Y  + (size_t)bh*MM*DD;

#pragma unroll
    for (int i = 0; i < 8; i++) {
        int idx = tid + i*256;
        int row = idx & 127;
        int c4  = (idx >> 7) * 4;
        float4 v = *reinterpret_cast<const float4*>(Qb + (size_t)(q0+row)*DD + c4);
        As[c4+0][row]=v.x*0.125f; As[c4+1][row]=v.y*0.125f;
        As[c4+2][row]=v.z*0.125f; As[c4+3][row]=v.w*0.125f;
    }

    int tx8 = (tid & 15) * 8, ty8 = (tid >> 4) * 8;
    for (int cc = 0; cc < 2; cc++) {
        __syncthreads();
#pragma unroll
        for (int i = 0; i < 8; i++) {
            int idx = tid + i*256;
            int row = idx & 127;
            int c4  = (idx >> 7) * 4;
            float4 v = *reinterpret_cast<const float4*>(ncb + (size_t)(cc*128+row)*DD + c4);
            Bs[c4+0][row]=v.x; Bs[c4+1][row]=v.y; Bs[c4+2][row]=v.z; Bs[c4+3][row]=v.w;
        }
        __syncthreads();
        float acc[8][8] = {};
#pragma unroll 8
        for (int kk = 0; kk < 64; kk++) {
            float a[8], b[8];
            *reinterpret_cast<float4*>(&a[0]) = *reinterpret_cast<float4*>(&As[kk][ty8]);
            *reinterpret_cast<float4*>(&a[4]) = *reinterpret_cast<float4*>(&As[kk][ty8+4]);
            *reinterpret_cast<float4*>(&b[0]) = *reinterpret_cast<float4*>(&Bs[kk][tx8]);
            *reinterpret_cast<float4*>(&b[4]) = *reinterpret_cast<float4*>(&Bs[kk][tx8+4]);
#pragma unroll
            for (int i = 0; i < 8; i++)
#pragma unroll
                for (int j = 0; j < 8; j++) acc[i][j] += a[i]*b[j];
        }
#pragma unroll
        for (int i = 0; i < 8; i++) {
            *reinterpret_cast<float4*>(&L[ty8+i][cc*128+tx8]) =
                make_float4(acc[i][0],acc[i][1],acc[i][2],acc[i][3]);
            *reinterpret_cast<float4*>(&L[ty8+i][cc*128+tx8+4]) =
                make_float4(acc[i][4],acc[i][5],acc[i][6],acc[i][7]);
        }
    }
    __syncthreads();

    int wid = tid >> 5, lane = tid & 31;
    for (int r = wid; r < 128; r += 8) {
        float v[8]; float mx = -FLT_MAX;
#pragma unroll
        for (int t = 0; t < 8; t++) { v[t] = L[r][lane + 32*t]; mx = fmaxf(mx, v[t]); }
#pragma unroll
        for (int o = 16; o > 0; o >>= 1) mx = fmaxf(mx, __shfl_xor_sync(0xffffffffu, mx, o));
        float s = 0.f;
#pragma unroll
        for (int t = 0; t < 8; t++) { v[t] = __expf(v[t] - mx); s += v[t]; }
#pragma unroll
        for (int o = 16; o > 0; o >>= 1) s += __shfl_xor_sync(0xffffffffu, s, o);
        float inv = 1.0f / s;
#pragma unroll
        for (int t = 0; t < 8; t++) L[r][lane + 32*t] = v[t] * inv;
    }

    cudaGridDependencySynchronize();   // PDL: Y (from gemm_nn) visible past here

    int ry = (tid >> 4) * 8;
    int cx = (tid & 15) * 4;
    float acc3[8][4] = {};
    for (int kc = 0; kc < 4; kc++) {
        __syncthreads();
#pragma unroll
        for (int i = 0; i < 4; i++) {
            int idx = tid + i*256;
            int row = idx >> 4, c4 = (idx & 15) * 4;
            *reinterpret_cast<float4*>(&Ys[row][c4]) =
                *reinterpret_cast<const float4*>(Yb + (size_t)(kc*64+row)*DD + c4);
        }
        __syncthreads();
#pragma unroll 8
        for (int kk = 0; kk < 64; kk++) {
            float b[4];
            *reinterpret_cast<float4*>(&b[0]) = *reinterpret_cast<float4*>(&Ys[kk][cx]);
            float a[8];
#pragma unroll
            for (int i = 0; i < 8; i++) a[i] = L[ry+i][kc*64+kk];
#pragma unroll
            for (int i = 0; i < 8; i++)
#pragma unroll
                for (int j = 0; j < 4; j++) acc3[i][j] += a[i]*b[j];
        }
    }
#pragma unroll
    for (int i = 0; i < 8; i++)
        *reinterpret_cast<float4*>(X + ((size_t)bh*NN + q0 + ry + i)*DD + cx) =
            make_float4(acc3[i][0], acc3[i][1], acc3[i][2], acc3[i][3]);
}

// ---------------- host launch ----------------
extern "C" void kernel_launch(void* const* d_in, const int* in_sizes, int n_in,
                              void* d_out, int out_size)
{
    (void)in_sizes; (void)n_in; (void)out_size;
    const float* Q = (const float*)d_in[0];
    const float* K = (const float*)d_in[1];
    const float* V = (const float*)d_in[2];
    float* X = (float*)d_out;

    static cudaStream_t s2 = nullptr;
    static cudaEvent_t evFork = nullptr, evJoin = nullptr;
    static bool attrs_done = false;
    if (!s2) {
        cudaStreamCreateWithFlags(&s2, cudaStreamNonBlocking);
        cudaEventCreateWithFlags(&evFork, cudaEventDisableTiming);
        cudaEventCreateWithFlags(&evJoin, cudaEventDisableTiming);
    }
    const int NT_SMEM  = 2*64*132*sizeof(float);                 // 67.5 KB
    const int NS1_SMEM = 64*136*4 + 64*72*4;                     // 53.2 KB
    const int NS3_SMEM = 64*132*8 + 64*72*8;                     // 104.4 KB
    const int FL_SMEM  = (128*68 + 64*68 + 64*68 + 128*68)*4;    // 104.4 KB
    const int FX_SMEM  = (2*64*132 + 128*FX_LPAD)*sizeof(float); // 200.7 KB
    if (!attrs_done) {
        cudaFuncSetAttribute(gemm_nt128_kernel, cudaFuncAttributeMaxDynamicSharedMemorySize, NT_SMEM);
        cudaFuncSetAttribute(ns_fused1_kernel,  cudaFuncAttributeMaxDynamicSharedMemorySize, NS1_SMEM);
        cudaFuncSetAttribute(ns_fused3_kernel,  cudaFuncAttributeMaxDynamicSharedMemorySize, NS3_SMEM);
        cudaFuncSetAttribute(rv_flash_kernel,   cudaFuncAttributeMaxDynamicSharedMemorySize, FL_SMEM);
        cudaFuncSetAttribute(fusedx_kernel,     cudaFuncAttributeMaxDynamicSharedMemorySize, FX_SMEM);
        attrs_done = true;
    }

    float *nc, *nr, *u, *v0, *v1, *kv, *t1, *t2, *rvp, *ml, *rv, *y;
    int *ik, *iq;
    cudaGetSymbolAddress((void**)&nc, g_nc);
    cudaGetSymbolAddress((void**)&nr, g_nr);
    cudaGetSymbolAddress((void**)&ik, g_idxk);
    cudaGetSymbolAddress((void**)&iq, g_idxq);
    cudaGetSymbolAddress((void**)&u,  g_u);
    cudaGetSymbolAddress((void**)&v0, g_v0);
    cudaGetSymbolAddress((void**)&v1, g_v1);
    cudaGetSymbolAddress((void**)&kv, g_kv);
    cudaGetSymbolAddress((void**)&t1, g_t1);
    cudaGetSymbolAddress((void**)&t2, g_t2);
    cudaGetSymbolAddress((void**)&rvp, g_rvp);
    cudaGetSymbolAddress((void**)&ml, g_ml);
    cudaGetSymbolAddress((void**)&rv, g_rv);
    cudaGetSymbolAddress((void**)&y,  g_y);

    // PDL attribute shared by all dependent launches
    cudaLaunchAttribute pdlAttr[1];
    pdlAttr[0].id = cudaLaunchAttributeProgrammaticStreamSerialization;
    pdlAttr[0].val.programmaticStreamSerializationAllowed = 1;

    auto mkcfg = [&](dim3 g, dim3 b, int smem, cudaStream_t st) {
        cudaLaunchConfig_t c = {};
        c.gridDim = g; c.blockDim = b; c.dynamicSmemBytes = (size_t)smem;
        c.stream = st; c.attrs = pdlAttr; c.numAttrs = 1;
        return c;
    };

    // 1) selection + gather (gather PDL-overlaps topk's drain)
    topk_kernel<<<32, 1024>>>(Q, K, ik, iq);
    {
        cudaLaunchConfig_t c = mkcfg(dim3(16), dim3(64,4), 0, 0);
        cudaLaunchKernelEx(&c, gather_kernel, Q, K, (const int*)ik, (const int*)iq, nc, nr);
    }

    // fork: flash RV pipeline (fp32, FMA pipe) overlaps main-stream tensor work
    cudaEventRecord(evFork, 0);
    cudaStreamWaitEvent(s2, evFork, 0);

    rv_flash_kernel<<<dim3(8, 2, 16), 256, FL_SMEM, s2>>>(nr, K, V, rvp, ml);
    {
        cudaLaunchConfig_t c = mkcfg(dim3(BH*MM*DD/(256*4)), dim3(256), 0, s2);
        cudaLaunchKernelEx(&c, rv_combine_kernel, (const float*)rvp, (const float*)ml, rv);
    }
    cudaEventRecord(evJoin, s2);

    // main: u = softmax(nr @ nc^T); Newton-Schulz inverse (all PDL-chained)
    {
        cudaLaunchConfig_t c = mkcfg(dim3(2, 2, 16), dim3(256), NT_SMEM, 0);
        cudaLaunchKernelEx(&c, gemm_nt128_kernel, (const float*)nr, (const float*)nc, u, MM, MM);
    }
    {
        cudaLaunchConfig_t c = mkcfg(dim3(BH*MM), dim3(256), (int)(MM*sizeof(float)), 0);
        cudaLaunchKernelEx(&c, softmax_rows_kernel, u, MM);
    }
    {
        cudaLaunchConfig_t c = mkcfg(dim3(16), dim3(256), 0, 0);
        cudaLaunchKernelEx(&c, v0init_kernel, (const float*)u, v0);
    }

    cudaLaunchConfig_t cfg1 = mkcfg(dim3(4, 2, 16), dim3(256), NS1_SMEM, 0);
    cudaLaunchConfig_t cfg3 = mkcfg(dim3(4, 2, 16), dim3(256), NS3_SMEM, 0);

    float* vin = v0; float* vout = v1;
    for (int it = 0; it < 4; it++) {
        if (it < 3) {
            // single tf32, fused epilogue: Newton-Schulz self-corrects the noise
            cudaLaunchKernelEx(&cfg1, ns_fused1_kernel, (const float*)u,   (const float*)vin, (const float*)nullptr, kv,   1.0f,  0.0f);
            cudaLaunchKernelEx(&cfg1, ns_fused1_kernel, (const float*)kv,  (const float*)kv,  (const float*)kv,      t1,  -1.0f,  7.0f);
            cudaLaunchKernelEx(&cfg1, ns_fused1_kernel, (const float*)kv,  (const float*)t1,  (const float*)kv,      t2,  -1.0f, 15.0f);
            cudaLaunchKernelEx(&cfg1, ns_fused1_kernel, (const float*)vin, (const float*)t2,  (const float*)vin,     vout, -0.25f, 3.25f);
        } else {
            // final iteration fp32-grade (3xTF32, fused epilogue)
            cudaLaunchKernelEx(&cfg3, ns_fused3_kernel, (const float*)u,   (const float*)vin, (const float*)nullptr, kv,   1.0f,  0.0f);
            cudaLaunchKernelEx(&cfg3, ns_fused3_kernel, (const float*)kv,  (const float*)kv,  (const float*)kv,      t1,  -1.0f,  7.0f);
            cudaLaunchKernelEx(&cfg3, ns_fused3_kernel, (const float*)kv,  (const float*)t1,  (const float*)kv,      t2,  -1.0f, 15.0f);
            cudaLaunchKernelEx(&cfg3, ns_fused3_kernel, (const float*)vin, (const float*)t2,  (const float*)vin,     vout, -0.25f, 3.25f);
        }
        float* tmp = vin; vin = vout; vout = tmp;
    }

    // join: need rv before Y (cross-stream event; unaffected by PDL)
    cudaStreamWaitEvent(0, evJoin, 0);

    // 7) Y = V_inv @ RV (PDL-overlaps NS drain)
    {
        cudaLaunchConfig_t c = mkcfg(dim3(1, 4, 16), dim3(256), 0, 0);
        cudaLaunchKernelEx(&c, gemm_nn_kernel, (const float*)vin, (const float*)rv, y, MM, DD, MM);
    }
    // 8) X = softmax(Qs @ nc^T) @ Y; phases 1-2 overlap gemm_nn via delayed sync
    {
        cudaLaunchConfig_t c = mkcfg(dim3(NN/128, BH), dim3(256), FX_SMEM, 0);
        cudaLaunchKernelEx(&c, fusedx_kernel, Q, (const float*)nc, (const float*)y, X);
    }
}

// round 17
// speedup vs baseline: 1.2543x; 1.0275x over previous
#include <cuda_runtime.h>
#include <float.h>
#include <stdint.h>

#define BH 16
#define HH 8
#define NN 4096
#define DD 64
#define MM 256

// ---------------- scratch (__device__ globals; no allocation) ----------------
__device__ float g_nc [BH*MM*DD];
__device__ float g_nr [BH*MM*DD];
__device__ int   g_idxk[BH*MM];
__device__ int   g_idxq[BH*MM];
__device__ float g_u  [BH*MM*MM];
__device__ float g_v0 [BH*MM*MM];
__device__ float g_v1 [BH*MM*MM];
__device__ float g_kv [BH*MM*MM];
__device__ float g_t1 [BH*MM*MM];
__device__ float g_t2 [BH*MM*MM];
__device__ float g_rvp[8*BH*MM*DD];          // flash split partials
__device__ float g_ml [8*BH*MM*2];           // flash split (max, sumexp)
__device__ float g_rv [BH*MM*DD];
__device__ float g_y  [BH*MM*DD];
__device__ float g_p  [(size_t)BH*NN*MM];    // 64 MB: kernel_1 = softmax(Qs@nc^T)

// ---------------- tf32 mma helpers ----------------
__device__ __forceinline__ uint32_t f2tf(float v) {
    uint32_t r; asm("cvt.rna.tf32.f32 %0, %1;" : "=r"(r) : "f"(v)); return r;
}
__device__ __forceinline__ void mma_tf32(float4& d, const uint32_t* a, const uint32_t* b) {
    asm volatile("mma.sync.aligned.m16n8k8.row.col.f32.tf32.tf32.f32 "
        "{%0,%1,%2,%3}, {%4,%5,%6,%7}, {%8,%9}, {%0,%1,%2,%3};"
        : "+f"(d.x), "+f"(d.y), "+f"(d.z), "+f"(d.w)
        : "r"(a[0]), "r"(a[1]), "r"(a[2]), "r"(a[3]), "r"(b[0]), "r"(b[1]));
}
__device__ __forceinline__ uint2 split_tf32(float x) {
    uint32_t hi = f2tf(x);
    float lo = x - __uint_as_float(hi);
    return make_uint2(hi, f2tf(lo));
}
// 3xTF32: d += a_hi*b_hi + a_lo*b_hi + a_hi*b_lo (fp32-grade)
__device__ __forceinline__ void mma_tf32x3(float4& d, const uint2* a, const uint2* b) {
    uint32_t ah[4] = {a[0].x, a[1].x, a[2].x, a[3].x};
    uint32_t al[4] = {a[0].y, a[1].y, a[2].y, a[3].y};
    uint32_t bh_[2] = {b[0].x, b[1].x};
    uint32_t bl_[2] = {b[0].y, b[1].y};
    mma_tf32(d, ah, bh_);
    mma_tf32(d, al, bh_);
    mma_tf32(d, ah, bl_);
}

// ---------------- top-k: exact bitonic sort of (sum,row) keys ----------------
__global__ void __launch_bounds__(1024) topk_kernel(
    const float* __restrict__ Q, const float* __restrict__ K,
    int* __restrict__ idxk, int* __restrict__ idxq)
{
    __shared__ unsigned long long keys[NN];
    int bh  = blockIdx.x >> 1;
    int isQ = blockIdx.x & 1;
    const float* src = isQ ? Q : K;
    int tid = threadIdx.x;

    for (int r = tid; r < NN; r += 1024) {
        const float4* p = reinterpret_cast<const float4*>(src + ((size_t)bh*NN + r)*DD);
        float s = 0.f;
#pragma unroll
        for (int t = 0; t < DD/4; t++) { float4 v = p[t]; s += v.x + v.y + v.z + v.w; }
        unsigned int u = __float_as_uint(s);
        unsigned int m = (u & 0x80000000u) ? ~u : (u | 0x80000000u);
        keys[r] = ((unsigned long long)(~m) << 32) | (unsigned int)r;
    }
    __syncthreads();

    for (int k = 2; k <= NN; k <<= 1) {
        for (int j = k >> 1; j > 0; j >>= 1) {
            for (int i = tid; i < NN; i += 1024) {
                int ixj = i ^ j;
                if (ixj > i) {
                    bool up = ((i & k) == 0);
                    unsigned long long a = keys[i], c = keys[ixj];
                    if ((a > c) == up) { keys[i] = c; keys[ixj] = a; }
                }
            }
            __syncthreads();
        }
    }
    int* dst = isQ ? idxq : idxk;
    if (tid < MM) dst[bh*MM + tid] = (int)(keys[tid] & 0xFFFFFFFFu);
}

// ---------------- gather nc = K[idx_k], nr = Q[idx_q]/8 (PDL-aware) ----------
__global__ void gather_kernel(const float* __restrict__ Q, const float* __restrict__ K,
                              const int* __restrict__ idxk, const int* __restrict__ idxq,
                              float* __restrict__ nc, float* __restrict__ nr)
{
    cudaGridDependencySynchronize();   // wait for topk's idx writes
    int bh = blockIdx.x;
    int tx = threadIdx.x;
    int ty = threadIdx.y;
    for (int i = ty; i < MM; i += 4) {
        int ik = idxk[bh*MM + i];
        int iq = idxq[bh*MM + i];
        nc[((size_t)bh*MM + i)*DD + tx] = K[((size_t)bh*NN + ik)*DD + tx];
        nr[((size_t)bh*MM + i)*DD + tx] = Q[((size_t)bh*NN + iq)*DD + tx] * 0.125f;
    }
}

// ---------------- NT GEMM (K=64): 128x128 tile, 8x8 micro (fp32, PDL) --------
__global__ void __launch_bounds__(256) gemm_nt128_kernel(
    const float* __restrict__ A, const float* __restrict__ B, float* __restrict__ C,
    int Ma, int Nb)
{
    extern __shared__ float sm[];
    float (*As)[132] = reinterpret_cast<float(*)[132]>(sm);
    float (*Bs)[132] = reinterpret_cast<float(*)[132]>(sm + 64*132);
    int bh = blockIdx.z;
    int m0 = blockIdx.y * 128;
    int n0 = blockIdx.x * 128;
    const float* Ab = A + (size_t)bh*Ma*64;
    const float* Bb = B + (size_t)bh*Nb*64;
    float*       Cb = C + (size_t)bh*Ma*Nb;
    int tid = threadIdx.x;
    cudaGridDependencySynchronize();   // wait for gather's nc/nr writes
#pragma unroll
    for (int i = 0; i < 8; i++) {
        int idx = tid + i*256;
        int row = idx & 127;
        int c4  = (idx >> 7) * 4;
        float4 v = *reinterpret_cast<const float4*>(Ab + (size_t)(m0+row)*64 + c4);
        As[c4+0][row]=v.x; As[c4+1][row]=v.y; As[c4+2][row]=v.z; As[c4+3][row]=v.w;
        float4 w = *reinterpret_cast<const float4*>(Bb + (size_t)(n0+row)*64 + c4);
        Bs[c4+0][row]=w.x; Bs[c4+1][row]=w.y; Bs[c4+2][row]=w.z; Bs[c4+3][row]=w.w;
    }
    __syncthreads();
    int tx8 = (tid & 15) * 8, ty8 = (tid >> 4) * 8;
    float acc[8][8] = {};
#pragma unroll 8
    for (int kk = 0; kk < 64; kk++) {
        float a[8], b[8];
        *reinterpret_cast<float4*>(&a[0]) = *reinterpret_cast<float4*>(&As[kk][ty8]);
        *reinterpret_cast<float4*>(&a[4]) = *reinterpret_cast<float4*>(&As[kk][ty8+4]);
        *reinterpret_cast<float4*>(&b[0]) = *reinterpret_cast<float4*>(&Bs[kk][tx8]);
        *reinterpret_cast<float4*>(&b[4]) = *reinterpret_cast<float4*>(&Bs[kk][tx8+4]);
#pragma unroll
        for (int i = 0; i < 8; i++)
#pragma unroll
            for (int j = 0; j < 8; j++) acc[i][j] += a[i]*b[j];
    }
#pragma unroll
    for (int i = 0; i < 8; i++) {
        *reinterpret_cast<float4*>(Cb + (size_t)(m0+ty8+i)*Nb + n0+tx8) =
            make_float4(acc[i][0],acc[i][1],acc[i][2],acc[i][3]);
        *reinterpret_cast<float4*>(Cb + (size_t)(m0+ty8+i)*Nb + n0+tx8+4) =
            make_float4(acc[i][4],acc[i][5],acc[i][6],acc[i][7]);
    }
}

// ---------------- NS fused GEMM (single tf32, full K, fused epilogue, PDL) ---
__global__ void __launch_bounds__(256) ns_fused1_kernel(
    const float* __restrict__ A, const float* __restrict__ B,
    const float* __restrict__ Cadd, float* __restrict__ Out,
    float alpha, float beta)
{
    extern __shared__ char smc[];
    uint32_t (*As)[136] = reinterpret_cast<uint32_t(*)[136]>(smc);
    uint32_t (*Bs)[72]  = reinterpret_cast<uint32_t(*)[72]> (smc + 64*136*4);
    int bh = blockIdx.z;
    int n0 = blockIdx.x * 64;
    int m0 = blockIdx.y * 128;
    const float* Ab = A + (size_t)bh*MM*MM;
    const float* Bb = B + (size_t)bh*MM*MM;
    float*       Ob = Out + (size_t)bh*MM*MM;
    int tid = threadIdx.x, lane = tid & 31, wid = tid >> 5;
    int r4 = lane >> 2, c4 = lane & 3;
    int wm = (wid & 1) * 64;
    int wn = ((wid >> 1) & 1) * 32;
    int kg = wid >> 2;
    int kb = kg * 32;

    float4 acc[4][4];
#pragma unroll
    for (int i = 0; i < 4; i++)
#pragma unroll
        for (int j = 0; j < 4; j++) acc[i][j] = make_float4(0.f,0.f,0.f,0.f);

    cudaGridDependencySynchronize();   // PDL: upstream writes visible past here

    for (int sc = 0; sc < 4; sc++) {
        int k0g = sc * 64;
        if (sc) __syncthreads();
#pragma unroll
        for (int i = 0; i < 8; i++) {
            int idx = tid + i*256;
            int row = idx & 127;
            int kq  = (idx >> 7) * 4;
            float4 v = *reinterpret_cast<const float4*>(Ab + (size_t)(m0+row)*MM + k0g + kq);
            As[kq+0][row]=f2tf(v.x); As[kq+1][row]=f2tf(v.y);
            As[kq+2][row]=f2tf(v.z); As[kq+3][row]=f2tf(v.w);
        }
#pragma unroll
        for (int i = 0; i < 4; i++) {
            int idx = tid + i*256;
            int row = idx >> 4;
            int cq  = (idx & 15) * 4;
            float4 v = *reinterpret_cast<const float4*>(Bb + (size_t)(k0g+row)*MM + n0 + cq);
            Bs[row][cq+0]=f2tf(v.x); Bs[row][cq+1]=f2tf(v.y);
            Bs[row][cq+2]=f2tf(v.z); Bs[row][cq+3]=f2tf(v.w);
        }
        __syncthreads();
#pragma unroll
        for (int ks = 0; ks < 4; ks++) {
            int k0 = kb + ks*8;
            uint32_t af[4][4], bf[4][2];
#pragma unroll
            for (int i = 0; i < 4; i++) {
                int mb = wm + i*16;
                af[i][0] = As[k0+c4  ][mb+r4];
                af[i][1] = As[k0+c4  ][mb+8+r4];
                af[i][2] = As[k0+4+c4][mb+r4];
                af[i][3] = As[k0+4+c4][mb+8+r4];
            }
#pragma unroll
            for (int j = 0; j < 4; j++) {
                int nb = wn + j*8;
                bf[j][0] = Bs[k0+c4  ][nb+r4];
                bf[j][1] = Bs[k0+4+c4][nb+r4];
            }
#pragma unroll
            for (int i = 0; i < 4; i++)
#pragma unroll
                for (int j = 0; j < 4; j++) mma_tf32(acc[i][j], af[i], bf[j]);
        }
    }

    __syncthreads();
    float4* red = reinterpret_cast<float4*>(smc);
    if (kg == 1) {
        int slot = wid - 4;
#pragma unroll
        for (int f = 0; f < 16; f++)
            red[((size_t)f*4 + slot)*32 + lane] = acc[f>>2][f&3];
    }
    __syncthreads();
    if (kg == 0) {
        const float* Cb = Cadd ? (Cadd + (size_t)bh*MM*MM) : nullptr;
#pragma unroll
        for (int f = 0; f < 16; f++) {
            float4 o = red[((size_t)f*4 + wid)*32 + lane];
            acc[f>>2][f&3].x += o.x; acc[f>>2][f&3].y += o.y;
            acc[f>>2][f&3].z += o.z; acc[f>>2][f&3].w += o.w;
        }
#pragma unroll
        for (int i = 0; i < 4; i++) {
            int row0 = m0 + wm + i*16 + r4;
#pragma unroll
            for (int j = 0; j < 4; j++) {
                int col = n0 + wn + j*8 + 2*c4;
                float2 v0 = make_float2(alpha*acc[i][j].x, alpha*acc[i][j].y);
                float2 v1 = make_float2(alpha*acc[i][j].z, alpha*acc[i][j].w);
                if (Cb) {
                    float2 c0 = *reinterpret_cast<const float2*>(Cb + (size_t)row0*MM + col);
                    float2 c1 = *reinterpret_cast<const float2*>(Cb + (size_t)(row0+8)*MM + col);
                    v0.x += beta*c0.x; v0.y += beta*c0.y;
                    v1.x += beta*c1.x; v1.y += beta*c1.y;
                }
                *reinterpret_cast<float2*>(Ob + (size_t)row0*MM + col) = v0;
                *reinterpret_cast<float2*>(Ob + (size_t)(row0+8)*MM + col) = v1;
            }
        }
    }
}

// ---------------- NS fused GEMM (3xTF32, fp32-grade; iteration 4, PDL) -------
__global__ void __launch_bounds__(256) ns_fused3_kernel(
    const float* __restrict__ A, const float* __restrict__ B,
    const float* __restrict__ Cadd, float* __restrict__ Out,
    float alpha, float beta)
{
    extern __shared__ char smc[];
    uint2 (*As2)[132] = reinterpret_cast<uint2(*)[132]>(smc);
    uint2 (*Bs2)[72]  = reinterpret_cast<uint2(*)[72]> (smc + 64*132*8);
    int bh = blockIdx.z;
    int n0 = blockIdx.x * 64;
    int m0 = blockIdx.y * 128;
    const float* Ab = A + (size_t)bh*MM*MM;
    const float* Bb = B + (size_t)bh*MM*MM;
    float*       Ob = Out + (size_t)bh*MM*MM;
    int tid = threadIdx.x, lane = tid & 31, wid = tid >> 5;
    int r4 = lane >> 2, c4 = lane & 3;
    int wm = (wid & 1) * 64;
    int wn = ((wid >> 1) & 1) * 32;
    int kg = wid >> 2;
    int kb = kg * 32;

    float4 acc[4][4];
#pragma unroll
    for (int i = 0; i < 4; i++)
#pragma unroll
        for (int j = 0; j < 4; j++) acc[i][j] = make_float4(0.f,0.f,0.f,0.f);

    cudaGridDependencySynchronize();   // PDL: upstream writes visible past here

    for (int sc = 0; sc < 4; sc++) {
        int k0g = sc * 64;
        if (sc) __syncthreads();
#pragma unroll
        for (int i = 0; i < 8; i++) {
            int idx = tid + i*256;
            int row = idx & 127;
            int kq  = (idx >> 7) * 4;
            float4 v = *reinterpret_cast<const float4*>(Ab + (size_t)(m0+row)*MM + k0g + kq);
            As2[kq+0][row]=split_tf32(v.x); As2[kq+1][row]=split_tf32(v.y);
            As2[kq+2][row]=split_tf32(v.z); As2[kq+3][row]=split_tf32(v.w);
        }
#pragma unroll
        for (int i = 0; i < 4; i++) {
            int idx = tid + i*256;
            int row = idx >> 4;
            int cq  = (idx & 15) * 4;
            float4 v = *reinterpret_cast<const float4*>(Bb + (size_t)(k0g+row)*MM + n0 + cq);
            Bs2[row][cq+0]=split_tf32(v.x); Bs2[row][cq+1]=split_tf32(v.y);
            Bs2[row][cq+2]=split_tf32(v.z); Bs2[row][cq+3]=split_tf32(v.w);
        }
        __syncthreads();
#pragma unroll
        for (int ks = 0; ks < 4; ks++) {
            int k0 = kb + ks*8;
            uint2 a2[4][4], b2[4][2];
#pragma unroll
            for (int i = 0; i < 4; i++) {
                int mb = wm + i*16;
                a2[i][0] = As2[k0+c4  ][mb+r4];
                a2[i][1] = As2[k0+c4  ][mb+8+r4];
                a2[i][2] = As2[k0+4+c4][mb+r4];
                a2[i][3] = As2[k0+4+c4][mb+8+r4];
            }
#pragma unroll
            for (int j = 0; j < 4; j++) {
                int nb = wn + j*8;
                b2[j][0] = Bs2[k0+c4  ][nb+r4];
                b2[j][1] = Bs2[k0+4+c4][nb+r4];
            }
#pragma unroll
            for (int i = 0; i < 4; i++)
#pragma unroll
                for (int j = 0; j < 4; j++) mma_tf32x3(acc[i][j], a2[i], b2[j]);
        }
    }

    __syncthreads();
    float4* red = reinterpret_cast<float4*>(smc);
    if (kg == 1) {
        int slot = wid - 4;
#pragma unroll
        for (int f = 0; f < 16; f++)
            red[((size_t)f*4 + slot)*32 + lane] = acc[f>>2][f&3];
    }
    __syncthreads();
    if (kg == 0) {
        const float* Cb = Cadd ? (Cadd + (size_t)bh*MM*MM) : nullptr;
#pragma unroll
        for (int f = 0; f < 16; f++) {
            float4 o = red[((size_t)f*4 + wid)*32 + lane];
            acc[f>>2][f&3].x += o.x; acc[f>>2][f&3].y += o.y;
            acc[f>>2][f&3].z += o.z; acc[f>>2][f&3].w += o.w;
        }
#pragma unroll
        for (int i = 0; i < 4; i++) {
            int row0 = m0 + wm + i*16 + r4;
#pragma unroll
            for (int j = 0; j < 4; j++) {
                int col = n0 + wn + j*8 + 2*c4;
                float2 v0 = make_float2(alpha*acc[i][j].x, alpha*acc[i][j].y);
                float2 v1 = make_float2(alpha*acc[i][j].z, alpha*acc[i][j].w);
                if (Cb) {
                    float2 c0 = *reinterpret_cast<const float2*>(Cb + (size_t)row0*MM + col);
                    float2 c1 = *reinterpret_cast<const float2*>(Cb + (size_t)(row0+8)*MM + col);
                    v0.x += beta*c0.x; v0.y += beta*c0.y;
                    v1.x += beta*c1.x; v1.y += beta*c1.y;
                }
                *reinterpret_cast<float2*>(Ob + (size_t)row0*MM + col) = v0;
                *reinterpret_cast<float2*>(Ob + (size_t)(row0+8)*MM + col) = v1;
            }
        }
    }
}

// ---------------- NN GEMM (small, for Y = inv @ RV, PDL) ---------------------
__global__ void __launch_bounds__(256) gemm_nn_kernel(
    const float* __restrict__ A, const float* __restrict__ B,
    float* __restrict__ Out, int Ma, int Nb, int Kd)
{
    __shared__ float As[64][65];
    __shared__ float Bs[64][65];
    int bh = blockIdx.z;
    int n0 = blockIdx.x * 64;
    int m0 = blockIdx.y * 64;
    const float* Ab = A + (size_t)bh*Ma*Kd;
    const float* Bb = B + (size_t)bh*Kd*Nb;
    float*       Ob = Out + (size_t)bh*Ma*Nb;
    int tid = threadIdx.x;
    int tx4 = (tid & 15) * 4, ty4 = (tid >> 4) * 4;
    float acc[4][4] = {};
    cudaGridDependencySynchronize();   // wait for NS-final writes
    for (int k0 = 0; k0 < Kd; k0 += 64) {
        for (int l = tid; l < 64*16; l += 256) {
            int row = l >> 4, c4 = (l & 15) * 4;
            float4 va = *reinterpret_cast<const float4*>(Ab + (size_t)(m0+row)*Kd + k0 + c4);
            As[row][c4+0]=va.x; As[row][c4+1]=va.y; As[row][c4+2]=va.z; As[row][c4+3]=va.w;
            float4 vb = *reinterpret_cast<const float4*>(Bb + (size_t)(k0+row)*Nb + n0 + c4);
            Bs[row][c4+0]=vb.x; Bs[row][c4+1]=vb.y; Bs[row][c4+2]=vb.z; Bs[row][c4+3]=vb.w;
        }
        __syncthreads();
#pragma unroll 16
        for (int kk = 0; kk < 64; kk++) {
            float a0=As[ty4+0][kk], a1=As[ty4+1][kk], a2=As[ty4+2][kk], a3=As[ty4+3][kk];
            float b0=Bs[kk][tx4+0], b1=Bs[kk][tx4+1], b2=Bs[kk][tx4+2], b3=Bs[kk][tx4+3];
            acc[0][0]+=a0*b0; acc[0][1]+=a0*b1; acc[0][2]+=a0*b2; acc[0][3]+=a0*b3;
            acc[1][0]+=a1*b0; acc[1][1]+=a1*b1; acc[1][2]+=a1*b2; acc[1][3]+=a1*b3;
            acc[2][0]+=a2*b0; acc[2][1]+=a2*b1; acc[2][2]+=a2*b2; acc[2][3]+=a2*b3;
            acc[3][0]+=a3*b0; acc[3][1]+=a3*b1; acc[3][2]+=a3*b2; acc[3][3]+=a3*b3;
        }
        __syncthreads();
    }
#pragma unroll
    for (int i = 0; i < 4; i++) {
        size_t off = (size_t)(m0+ty4+i)*Nb + n0 + tx4;
        *reinterpret_cast<float4*>(Ob + off) =
            make_float4(acc[i][0], acc[i][1], acc[i][2], acc[i][3]);
    }
}

// ---------------- row softmax (in place), one block per row (PDL) ------------
__global__ void softmax_rows_kernel(float* __restrict__ data, int cols)
{
    extern __shared__ float buf[];
    __shared__ float red[256];
    size_t row = blockIdx.x;
    float* d = data + row * (size_t)cols;
    int tid = threadIdx.x;
    cudaGridDependencySynchronize();   // wait for upstream GEMM writes
    float mx = -FLT_MAX;
    for (int c = tid; c < cols; c += 256) { float v = d[c]; buf[c] = v; mx = fmaxf(mx, v); }
    red[tid] = mx; __syncthreads();
    for (int st = 128; st > 0; st >>= 1) { if (tid < st) red[tid] = fmaxf(red[tid], red[tid+st]); __syncthreads(); }
    mx = red[0];
    __syncthreads();
    float s = 0.f;
    for (int c = tid; c < cols; c += 256) { float e = __expf(buf[c] - mx); buf[c] = e; s += e; }
    red[tid] = s; __syncthreads();
    for (int st = 128; st > 0; st >>= 1) { if (tid < st) red[tid] += red[tid+st]; __syncthreads(); }
    float inv = 1.0f / red[0];
    for (int c = tid; c < cols; c += 256) d[c] = buf[c] * inv;
}

// ---------------- V0 = u^T / max_j(colsum_j(u)) (PDL) ------------------------
__global__ void __launch_bounds__(256) v0init_kernel(const float* __restrict__ U, float* __restrict__ V0)
{
    __shared__ float red[256];
    int bh = blockIdx.x;
    const float* u = U  + (size_t)bh*MM*MM;
    float*       v = V0 + (size_t)bh*MM*MM;
    int j = threadIdx.x;
    cudaGridDependencySynchronize();   // wait for softmax's u writes
    float s = 0.f;
    for (int i = 0; i < MM; i++) s += u[(size_t)i*MM + j];
    red[j] = s; __syncthreads();
    for (int st = 128; st > 0; st >>= 1) { if (j < st) red[j] = fmaxf(red[j], red[j+st]); __syncthreads(); }
    float scale = 1.0f / red[0];
    for (int q = 0; q < MM; q++) v[(size_t)j*MM + q] = scale * u[(size_t)q*MM + j];
}

// ---------------- flash RV: partial softmax(nr @ K^T) @ V over KV splits -----
__global__ void __launch_bounds__(256) rv_flash_kernel(
    const float* __restrict__ NR, const float* __restrict__ K,
    const float* __restrict__ V, float* __restrict__ P, float* __restrict__ ML)
{
    extern __shared__ float sm[];
    float (*Nrs)[68] = reinterpret_cast<float(*)[68]>(sm);
    float (*Ksk)[68] = reinterpret_cast<float(*)[68]>(sm + 128*68);
    float (*Vs)[68]  = reinterpret_cast<float(*)[68]>(sm + 128*68 + 64*68);
    float (*Ps)[68]  = reinterpret_cast<float(*)[68]>(sm + 128*68 + 2*64*68);
    int s  = blockIdx.x;
    int m0 = blockIdx.y * 128;
    int bh = blockIdx.z;
    const float* Nb = NR + (size_t)bh*MM*DD;
    const float* Kb = K  + (size_t)bh*NN*DD;
    const float* Vb = V  + (size_t)bh*NN*DD;
    int tid = threadIdx.x;
    int ry = (tid >> 4) * 8;
    int cx = (tid & 15) * 4;

#pragma unroll
    for (int i = 0; i < 8; i++) {
        int idx = tid + i*256;
        int row = idx >> 4, q4 = (idx & 15) * 4;
        *reinterpret_cast<float4*>(&Nrs[row][q4]) =
            *reinterpret_cast<const float4*>(Nb + (size_t)(m0+row)*DD + q4);
    }

    float m_i[8], l_i[8];
    float O[8][4] = {};
#pragma unroll
    for (int i = 0; i < 8; i++) { m_i[i] = -FLT_MAX; l_i[i] = 0.f; }

    for (int kc = 0; kc < 8; kc++) {
        int k0 = s*512 + kc*64;
        __syncthreads();
#pragma unroll
        for (int i = 0; i < 4; i++) {
            int idx = tid + i*256;
            int c  = idx & 63;
            int kq = (idx >> 6) * 4;
            float4 v = *reinterpret_cast<const float4*>(Kb + (size_t)(k0+c)*DD + kq);
            Ksk[kq+0][c]=v.x; Ksk[kq+1][c]=v.y; Ksk[kq+2][c]=v.z; Ksk[kq+3][c]=v.w;
        }
#pragma unroll
        for (int i = 0; i < 4; i++) {
            int idx = tid + i*256;
            int row = idx >> 4, q4 = (idx & 15) * 4;
            *reinterpret_cast<float4*>(&Vs[row][q4]) =
                *reinterpret_cast<const float4*>(Vb + (size_t)(k0+row)*DD + q4);
        }
        __syncthreads();

        float sv[8][4] = {};
#pragma unroll 8
        for (int kk = 0; kk < 64; kk++) {
            float b[4];
            *reinterpret_cast<float4*>(&b[0]) = *reinterpret_cast<float4*>(&Ksk[kk][cx]);
            float a[8];
#pragma unroll
            for (int i = 0; i < 8; i++) a[i] = Nrs[ry+i][kk];
#pragma unroll
            for (int i = 0; i < 8; i++)
#pragma unroll
                for (int j = 0; j < 4; j++) sv[i][j] += a[i]*b[j];
        }

#pragma unroll
        for (int i = 0; i < 8; i++) {
            float mc = fmaxf(fmaxf(sv[i][0], sv[i][1]), fmaxf(sv[i][2], sv[i][3]));
#pragma unroll
            for (int o = 8; o > 0; o >>= 1) mc = fmaxf(mc, __shfl_xor_sync(0xffffffffu, mc, o));
            float mn = fmaxf(m_i[i], mc);
            float corr = __expf(m_i[i] - mn);
            l_i[i] *= corr;
#pragma unroll
            for (int j = 0; j < 4; j++) O[i][j] *= corr;
            float ls = 0.f;
#pragma unroll
            for (int j = 0; j < 4; j++) {
                float p = __expf(sv[i][j] - mn);
                Ps[ry+i][cx+j] = p;
                ls += p;
            }
#pragma unroll
            for (int o = 8; o > 0; o >>= 1) ls += __shfl_xor_sync(0xffffffffu, ls, o);
            l_i[i] += ls;
            m_i[i] = mn;
        }
        __syncthreads();

#pragma unroll 8
        for (int kk = 0; kk < 64; kk++) {
            float b[4];
            *reinterpret_cast<float4*>(&b[0]) = *reinterpret_cast<float4*>(&Vs[kk][cx]);
            float a[8];
#pragma unroll
            for (int i = 0; i < 8; i++) a[i] = Ps[ry+i][kk];
#pragma unroll
            for (int i = 0; i < 8; i++)
#pragma unroll
                for (int j = 0; j < 4; j++) O[i][j] += a[i]*b[j];
        }
    }

    float* Pb = P + ((size_t)s*BH + bh)*MM*DD;
#pragma unroll
    for (int i = 0; i < 8; i++)
        *reinterpret_cast<float4*>(Pb + (size_t)(m0+ry+i)*DD + cx) =
            make_float4(O[i][0], O[i][1], O[i][2], O[i][3]);
    if ((tid & 15) == 0) {
        float* mlb = ML + (((size_t)s*BH + bh)*MM + m0)*2;
#pragma unroll
        for (int i = 0; i < 8; i++) {
            mlb[(ry+i)*2 + 0] = m_i[i];
            mlb[(ry+i)*2 + 1] = l_i[i];
        }
    }
}

__global__ void rv_combine_kernel(const float* __restrict__ P, const float* __restrict__ ML,
                                  float* __restrict__ RV)
{
    cudaGridDependencySynchronize();   // wait for rv_flash writes
    int gt = blockIdx.x * 256 + threadIdx.x;
    int row = gt >> 4;
    int c4  = (gt & 15) * 4;
    float m_s[8], l_s[8];
    float gm = -FLT_MAX;
#pragma unroll
    for (int s = 0; s < 8; s++) {
        m_s[s] = ML[(((size_t)s*BH*MM) + row)*2 + 0];
        l_s[s] = ML[(((size_t)s*BH*MM) + row)*2 + 1];
        gm = fmaxf(gm, m_s[s]);
    }
    float L = 0.f;
    float4 acc = make_float4(0.f,0.f,0.f,0.f);
#pragma unroll
    for (int s = 0; s < 8; s++) {
        float w = __expf(m_s[s] - gm);
        L += w * l_s[s];
        float4 o = *reinterpret_cast<const float4*>(P + ((size_t)s*BH*MM + row)*DD + c4);
        acc.x += w*o.x; acc.y += w*o.y; acc.z += w*o.z; acc.w += w*o.w;
    }
    float inv = 1.0f / L;
    *reinterpret_cast<float4*>(RV + (size_t)row*DD + c4) =
        make_float4(acc.x*inv, acc.y*inv, acc.z*inv, acc.w*inv);
}

// ---------------- plogits: P = softmax(Qs @ nc^T), full 256-row in-warp ------
// Tile 64 q-rows x 256 cols (full row). Warp w owns rows 8w..8w+7; lane owns
// 8 cols. Row softmax = warp shuffle reduce. fp32 (FMA pipe; runs on s2 under
// the NS tensor window). No grid sync: depends only on gather (event-guarded).
__global__ void __launch_bounds__(256) plogits_kernel(
    const float* __restrict__ Q, const float* __restrict__ nc, float* __restrict__ P)
{
    extern __shared__ float sm[];
    float (*As)[68]  = reinterpret_cast<float(*)[68]> (sm);            // [64k][68m]
    float (*Bs)[260] = reinterpret_cast<float(*)[260]>(sm + 64*68);    // [64k][260n]
    int bh = blockIdx.y;
    int q0 = blockIdx.x * 64;
    int tid = threadIdx.x, lane = tid & 31, wid = tid >> 5;
    const float* Qb  = Q  + (size_t)bh*NN*DD;
    const float* ncb = nc + (size_t)bh*MM*DD;

    // stage Qs^T (scaled by 1/8), k-major: 64m x 64k
#pragma unroll
    for (int i = 0; i < 4; i++) {
        int idx = tid + i*256;
        int m  = idx & 63;
        int kq = (idx >> 6) * 4;
        float4 v = *reinterpret_cast<const float4*>(Qb + (size_t)(q0+m)*DD + kq);
        As[kq+0][m]=v.x*0.125f; As[kq+1][m]=v.y*0.125f;
        As[kq+2][m]=v.z*0.125f; As[kq+3][m]=v.w*0.125f;
    }
    // stage nc^T, k-major: 256n x 64k
#pragma unroll
    for (int i = 0; i < 16; i++) {
        int idx = tid + i*256;
        int n  = idx & 255;
        int kq = (idx >> 8) * 4;
        float4 v = *reinterpret_cast<const float4*>(ncb + (size_t)n*DD + kq);
        Bs[kq+0][n]=v.x; Bs[kq+1][n]=v.y; Bs[kq+2][n]=v.z; Bs[kq+3][n]=v.w;
    }
    __syncthreads();

    int my_m = wid * 8;     // 8 rows per warp
    int my_n = lane * 8;    // 8 cols per lane
    float acc[8][8] = {};
#pragma unroll 8
    for (int kk = 0; kk < 64; kk++) {
        float a[8], b[8];
        *reinterpret_cast<float4*>(&a[0]) = *reinterpret_cast<float4*>(&As[kk][my_m]);
        *reinterpret_cast<float4*>(&a[4]) = *reinterpret_cast<float4*>(&As[kk][my_m+4]);
        *reinterpret_cast<float4*>(&b[0]) = *reinterpret_cast<float4*>(&Bs[kk][my_n]);
        *reinterpret_cast<float4*>(&b[4]) = *reinterpret_cast<float4*>(&Bs[kk][my_n+4]);
#pragma unroll
        for (int i = 0; i < 8; i++)
#pragma unroll
            for (int j = 0; j < 8; j++) acc[i][j] += a[i]*b[j];
    }

    // warp-local row softmax + write
    float* Pb = P + ((size_t)bh*NN + q0)*MM;
#pragma unroll
    for (int i = 0; i < 8; i++) {
        float mx = acc[i][0];
#pragma unroll
        for (int j = 1; j < 8; j++) mx = fmaxf(mx, acc[i][j]);
#pragma unroll
        for (int o = 16; o > 0; o >>= 1) mx = fmaxf(mx, __shfl_xor_sync(0xffffffffu, mx, o));
        float s = 0.f;
#pragma unroll
        for (int j = 0; j < 8; j++) { acc[i][j] = __expf(acc[i][j] - mx); s += acc[i][j]; }
#pragma unroll
        for (int o = 16; o > 0; o >>= 1) s += __shfl_xor_sync(0xffffffffu, s, o);
        float inv = 1.0f / s;
        float* row = Pb + (size_t)(my_m + i)*MM + my_n;
        *reinterpret_cast<float4*>(row)   = make_float4(acc[i][0]*inv, acc[i][1]*inv,
                                                        acc[i][2]*inv, acc[i][3]*inv);
        *reinterpret_cast<float4*>(row+4) = make_float4(acc[i][4]*inv, acc[i][5]*inv,
                                                        acc[i][6]*inv, acc[i][7]*inv);
    }
}

// ---------------- final: X = kernel_1 @ Y  (fp32, 128x64 tile, K=256, PDL) ---
__global__ void __launch_bounds__(256) xgemm_kernel(
    const float* __restrict__ P, const float* __restrict__ Yy, float* __restrict__ X)
{
    extern __shared__ float sm[];
    float (*Ps)[68] = reinterpret_cast<float(*)[68]>(sm);            // [128m][68k]
    float (*Ys)[68] = reinterpret_cast<float(*)[68]>(sm + 128*68);   // [64k][68n]
    int m0 = blockIdx.y * 128;
    int bh = blockIdx.z;
    const float* Pb = P  + (size_t)bh*NN*MM;
    const float* Yb = Yy + (size_t)bh*MM*DD;
    int tid = threadIdx.x;
    int ry = (tid >> 4) * 8;
    int cx = (tid & 15) * 4;
    float acc[8][4] = {};
    cudaGridDependencySynchronize();   // PDL: Y (gemm_nn) visible past here
    for (int kc = 0; kc < 4; kc++) {
        int k0 = kc*64;
        if (kc) __syncthreads();
#pragma unroll
        for (int i = 0; i < 8; i++) {
            int idx = tid + i*256;
            int row = idx >> 4, c4 = (idx & 15) * 4;
            *reinterpret_cast<float4*>(&Ps[row][c4]) =
                *reinterpret_cast<const float4*>(Pb + (size_t)(m0+row)*MM + k0 + c4);
        }
#pragma unroll
        for (int i = 0; i < 4; i++) {
            int idx = tid + i*256;
            int row = idx >> 4, c4 = (idx & 15) * 4;
            *reinterpret_cast<float4*>(&Ys[row][c4]) =
                *reinterpret_cast<const float4*>(Yb + (size_t)(k0+row)*DD + c4);
        }
        __syncthreads();
#pragma unroll 8
        for (int kk = 0; kk < 64; kk++) {
            float b[4];
            *reinterpret_cast<float4*>(&b[0]) = *reinterpret_cast<float4*>(&Ys[kk][cx]);
            float a[8];
#pragma unroll
            for (int i = 0; i < 8; i++) a[i] = Ps[ry+i][kk];
#pragma unroll
            for (int i = 0; i < 8; i++)
#pragma unroll
                for (int j = 0; j < 4; j++) acc[i][j] += a[i]*b[j];
        }
    }
#pragma unroll
    for (int i = 0; i < 8; i++)
        *reinterpret_cast<float4*>(X + ((size_t)bh*NN + m0 + ry + i)*DD + cx) =
            make_float4(acc[i][0], acc[i][1], acc[i][2], acc[i][3]);
}

// ---------------- host launch ----------------
extern "C" void kernel_launch(void* const* d_in, const int* in_sizes, int n_in,
                              void* d_out, int out_size)
{
    (void)in_sizes; (void)n_in; (void)out_size;
    const float* Q = (const float*)d_in[0];
    const float* K = (const float*)d_in[1];
    const float* V = (const float*)d_in[2];
    float* X = (float*)d_out;

    static cudaStream_t s2 = nullptr;
    static cudaEvent_t evFork = nullptr, evJoin = nullptr, evP = nullptr;
    static bool attrs_done = false;
    if (!s2) {
        cudaStreamCreateWithFlags(&s2, cudaStreamNonBlocking);
        cudaEventCreateWithFlags(&evFork, cudaEventDisableTiming);
        cudaEventCreateWithFlags(&evJoin, cudaEventDisableTiming);
        cudaEventCreateWithFlags(&evP,    cudaEventDisableTiming);
    }
    const int NT_SMEM  = 2*64*132*sizeof(float);                 // 67.5 KB
    const int NS1_SMEM = 64*136*4 + 64*72*4;                     // 53.2 KB
    const int NS3_SMEM = 64*132*8 + 64*72*8;                     // 104.4 KB
    const int FL_SMEM  = (128*68 + 64*68 + 64*68 + 128*68)*4;    // 104.4 KB
    const int PL_SMEM  = (64*68 + 64*260)*sizeof(float);         // 82.0 KB
    const int XG_SMEM  = (128*68 + 64*68)*sizeof(float);         // 52.2 KB
    if (!attrs_done) {
        cudaFuncSetAttribute(gemm_nt128_kernel, cudaFuncAttributeMaxDynamicSharedMemorySize, NT_SMEM);
        cudaFuncSetAttribute(ns_fused1_kernel,  cudaFuncAttributeMaxDynamicSharedMemorySize, NS1_SMEM);
        cudaFuncSetAttribute(ns_fused3_kernel,  cudaFuncAttributeMaxDynamicSharedMemorySize, NS3_SMEM);
        cudaFuncSetAttribute(rv_flash_kernel,   cudaFuncAttributeMaxDynamicSharedMemorySize, FL_SMEM);
        cudaFuncSetAttribute(plogits_kernel,    cudaFuncAttributeMaxDynamicSharedMemorySize, PL_SMEM);
        cudaFuncSetAttribute(xgemm_kernel,      cudaFuncAttributeMaxDynamicSharedMemorySize, XG_SMEM);
        attrs_done = true;
    }

    float *nc, *nr, *u, *v0, *v1, *kv, *t1, *t2, *rvp, *ml, *rv, *y, *p;
    int *ik, *iq;
    cudaGetSymbolAddress((void**)&nc, g_nc);
    cudaGetSymbolAddress((void**)&nr, g_nr);
    cudaGetSymbolAddress((void**)&ik, g_idxk);
    cudaGetSymbolAddress((void**)&iq, g_idxq);
    cudaGetSymbolAddress((void**)&u,  g_u);
    cudaGetSymbolAddress((void**)&v0, g_v0);
    cudaGetSymbolAddress((void**)&v1, g_v1);
    cudaGetSymbolAddress((void**)&kv, g_kv);
    cudaGetSymbolAddress((void**)&t1, g_t1);
    cudaGetSymbolAddress((void**)&t2, g_t2);
    cudaGetSymbolAddress((void**)&rvp, g_rvp);
    cudaGetSymbolAddress((void**)&ml, g_ml);
    cudaGetSymbolAddress((void**)&rv, g_rv);
    cudaGetSymbolAddress((void**)&y,  g_y);
    cudaGetSymbolAddress((void**)&p,  g_p);

    // PDL attribute shared by all dependent launches
    cudaLaunchAttribute pdlAttr[1];
    pdlAttr[0].id = cudaLaunchAttributeProgrammaticStreamSerialization;
    pdlAttr[0].val.programmaticStreamSerializationAllowed = 1;

    auto mkcfg = [&](dim3 g, dim3 b, int smem, cudaStream_t st) {
        cudaLaunchConfig_t c = {};
        c.gridDim = g; c.blockDim = b; c.dynamicSmemBytes = (size_t)smem;
        c.stream = st; c.attrs = pdlAttr; c.numAttrs = 1;
        return c;
    };

    // 1) selection + gather (gather PDL-overlaps topk's drain)
    topk_kernel<<<32, 1024>>>(Q, K, ik, iq);
    {
        cudaLaunchConfig_t c = mkcfg(dim3(16), dim3(64,4), 0, 0);
        cudaLaunchKernelEx(&c, gather_kernel, Q, K, (const int*)ik, (const int*)iq, nc, nr);
    }

    // fork: s2 = flash RV + plogits (fp32/FMA; overlaps main-stream tensor NS)
    cudaEventRecord(evFork, 0);
    cudaStreamWaitEvent(s2, evFork, 0);

    rv_flash_kernel<<<dim3(8, 2, 16), 256, FL_SMEM, s2>>>(nr, K, V, rvp, ml);
    {
        cudaLaunchConfig_t c = mkcfg(dim3(BH*MM*DD/(256*4)), dim3(256), 0, s2);
        cudaLaunchKernelEx(&c, rv_combine_kernel, (const float*)rvp, (const float*)ml, rv);
    }
    cudaEventRecord(evJoin, s2);
    {
        // plogits has NO grid sync (depends only on gather, guarded by evFork);
        // PDL lets it start during rv_combine's drain
        cudaLaunchConfig_t c = mkcfg(dim3(NN/64, BH), dim3(256), PL_SMEM, s2);
        cudaLaunchKernelEx(&c, plogits_kernel, Q, (const float*)nc, p);
    }
    cudaEventRecord(evP, s2);

    // main: u = softmax(nr @ nc^T); Newton-Schulz inverse (all PDL-chained)
    {
        cudaLaunchConfig_t c = mkcfg(dim3(2, 2, 16), dim3(256), NT_SMEM, 0);
        cudaLaunchKernelEx(&c, gemm_nt128_kernel, (const float*)nr, (const float*)nc, u, MM, MM);
    }
    {
        cudaLaunchConfig_t c = mkcfg(dim3(BH*MM), dim3(256), (int)(MM*sizeof(float)), 0);
        cudaLaunchKernelEx(&c, softmax_rows_kernel, u, MM);
    }
    {
        cudaLaunchConfig_t c = mkcfg(dim3(16), dim3(256), 0, 0);
        cudaLaunchKernelEx(&c, v0init_kernel, (const float*)u, v0);
    }

    cudaLaunchConfig_t cfg1 = mkcfg(dim3(4, 2, 16), dim3(256), NS1_SMEM, 0);
    cudaLaunchConfig_t cfg3 = mkcfg(dim3(4, 2, 16), dim3(256), NS3_SMEM, 0);

    float* vin = v0; float* vout = v1;
    for (int it = 0; it < 4; it++) {
        if (it < 3) {
            // single tf32, fused epilogue: Newton-Schulz self-corrects the noise
            cudaLaunchKernelEx(&cfg1, ns_fused1_kernel, (const float*)u,   (const float*)vin, (const float*)nullptr, kv,   1.0f,  0.0f);
            cudaLaunchKernelEx(&cfg1, ns_fused1_kernel, (const float*)kv,  (const float*)kv,  (const float*)kv,      t1,  -1.0f,  7.0f);
            cudaLaunchKernelEx(&cfg1, ns_fused1_kernel, (const float*)kv,  (const float*)t1,  (const float*)kv,      t2,  -1.0f, 15.0f);
            cudaLaunchKernelEx(&cfg1, ns_fused1_kernel, (const float*)vin, (const float*)t2,  (const float*)vin,     vout, -0.25f, 3.25f);
        } else {
            // final iteration fp32-grade (3xTF32, fused epilogue)
            cudaLaunchKernelEx(&cfg3, ns_fused3_kernel, (const float*)u,   (const float*)vin, (const float*)nullptr, kv,   1.0f,  0.0f);
            cudaLaunchKernelEx(&cfg3, ns_fused3_kernel, (const float*)kv,  (const float*)kv,  (const float*)kv,      t1,  -1.0f,  7.0f);
            cudaLaunchKernelEx(&cfg3, ns_fused3_kernel, (const float*)kv,  (const float*)t1,  (const float*)kv,      t2,  -1.0f, 15.0f);
            cudaLaunchKernelEx(&cfg3, ns_fused3_kernel, (const float*)vin, (const float*)t2,  (const float*)vin,     vout, -0.25f, 3.25f);
        }
        float* tmp = vin; vin = vout; vout = tmp;
    }

    // join: need rv before Y (cross-stream event; unaffected by PDL)
    cudaStreamWaitEvent(0, evJoin, 0);

    // 7) Y = V_inv @ RV (PDL-overlaps NS drain)
    {
        cudaLaunchConfig_t c = mkcfg(dim3(1, 4, 16), dim3(256), 0, 0);
        cudaLaunchKernelEx(&c, gemm_nn_kernel, (const float*)vin, (const float*)rv, y, MM, DD, MM);
    }

    // join: need kernel_1 (p) before xgemm
    cudaStreamWaitEvent(0, evP, 0);

    // 8) X = kernel_1 @ Y (fp32; PDL sync covers Y from gemm_nn)
    {
        cudaLaunchConfig_t c = mkcfg(dim3(1, NN/128, 16), dim3(256), XG_SMEM, 0);
        cudaLaunchKernelEx(&c, xgemm_kernel, (const float*)p, (const float*)y, X);
    }
}